// round 11
// baseline (speedup 1.0000x reference)
#include <cuda_runtime.h>
#include <cuda_bf16.h>
#include <math.h>
#include <stdint.h>

// ---------------- problem constants ----------------
#define TT   128
#define BB   32
#define TB   (TT*BB)          // 4096
#define HID  128
#define FEAT 512
#define AA   18
#define OUTC (AA+1)           // 19

typedef unsigned long long u64;

// ---------------- packed f32x2 helpers (SASS FFMA2) ----------------
__device__ __forceinline__ u64 pk2(float x, float y) {
    u64 r; asm("mov.b64 %0, {%1, %2};" : "=l"(r) : "f"(x), "f"(y)); return r;
}
__device__ __forceinline__ u64 dup2(float x) { return pk2(x, x); }
__device__ __forceinline__ void ffma2(u64& d, u64 a, u64 b) {
    asm("fma.rn.f32x2 %0, %1, %2, %0;" : "+l"(d) : "l"(a), "l"(b));
}
__device__ __forceinline__ void upk2(u64 v, float& x, float& y) {
    asm("mov.b64 {%0, %1}, %2;" : "=f"(x), "=f"(y) : "l"(v));
}

// ---------------- HMMA helpers (base ISA: mma.sync + ldmatrix) ----------------
__device__ __forceinline__ uint32_t smem_u32(const void* p) {
    uint32_t a;
    asm("{ .reg .u64 t; cvta.to.shared.u64 t, %1; cvt.u32.u64 %0, t; }" : "=r"(a) : "l"(p));
    return a;
}
__device__ __forceinline__ void ldsm_x4(uint32_t* r, uint32_t addr) {
    asm volatile("ldmatrix.sync.aligned.m8n8.x4.shared.b16 {%0,%1,%2,%3}, [%4];"
        : "=r"(r[0]), "=r"(r[1]), "=r"(r[2]), "=r"(r[3]) : "r"(addr));
}
__device__ __forceinline__ void mma_bf16(float* d, const uint32_t* a, const uint32_t* b) {
    asm volatile("mma.sync.aligned.m16n8k16.row.col.f32.bf16.bf16.f32 "
        "{%0,%1,%2,%3}, {%4,%5,%6,%7}, {%8,%9}, {%0,%1,%2,%3};"
        : "+f"(d[0]), "+f"(d[1]), "+f"(d[2]), "+f"(d[3])
        : "r"(a[0]), "r"(a[1]), "r"(a[2]), "r"(a[3]), "r"(b[0]), "r"(b[1]));
}
__device__ __forceinline__ uint32_t bf2(float a, float b) {
    __nv_bfloat162 t = __floats2bfloat162_rn(a, b);
    return *(uint32_t*)&t;
}

// ---------------- scratch (static device allocations) ----------------
__device__ float g_c1[TB * 32 * 20 * 20];
__device__ float g_c2[TB * 64 * 9 * 9];
__device__ float g_c3[TB * 64 * 7 * 7];
__device__ float g_feat[TB * FEAT];
__device__ float g_gx[TB * 4 * HID];
__device__ float g_hid[TB * HID];
__device__ float g_w1r[8192];
// bf16 hi/lo split operands (plain row-major)
__device__ __nv_bfloat16 g_w2h[64 * 512],  g_w2l[64 * 512];       // conv2 weights
__device__ __nv_bfloat16 g_w3h[64 * 576],  g_w3l[64 * 576];       // conv3 weights
__device__ __nv_bfloat16 g_a1h[TB * 3136], g_a1l[TB * 3136];      // c3
__device__ __nv_bfloat16 g_b1h[FEAT * 3136], g_b1l[FEAT * 3136];  // wf
__device__ __nv_bfloat16 g_a2h[TB * FEAT], g_a2l[TB * FEAT];      // feat
__device__ __nv_bfloat16 g_b2h[FEAT * FEAT], g_b2l[FEAT * FEAT];  // w_ih

// ============================================================
// weight reorder (conv1 only): out[r*OC+oc] = in[oc*R+r] * scale
// ============================================================
__global__ void reorder_w_kernel(const float* __restrict__ in,
                                 float* __restrict__ out,
                                 int R, int OC, float scale)
{
    int i = blockIdx.x * 256 + threadIdx.x;
    if (i >= R * OC) return;
    int oc = i / R, r = i - oc * R;
    out[r * OC + oc] = in[oc * R + r] * scale;
}

// ============================================================
// hi/lo bf16 convert, plain row-major
// ============================================================
__global__ void convert_hl_kernel(const float* __restrict__ src,
                                  __nv_bfloat16* __restrict__ hi,
                                  __nv_bfloat16* __restrict__ lo,
                                  int total)
{
    for (int i = blockIdx.x * 256 + threadIdx.x; i < total; i += gridDim.x * 256) {
        float v = src[i];
        __nv_bfloat16 h = __float2bfloat16(v);
        __nv_bfloat16 l = __float2bfloat16(v - __bfloat162float(h));
        hi[i] = h; lo[i] = l;
    }
}

// ============================================================
// HMMA bf16-split GEMM [R10, verified]: C = A@B^T + bias (+bias2)
// ============================================================
#define PAD 72
#define SM_GA   256
#define SM_GAL  (SM_GA  + 128 * PAD * 2)
#define SM_GBH  (SM_GAL + 128 * PAD * 2)
#define SM_GBL  (SM_GBH + 64 * PAD * 2)
#define MM_SMEM (SM_GBL + 64 * PAD * 2)

template <bool RELU, bool BIAS2>
__global__ void __launch_bounds__(256, 2)
mma_gemm_kernel(const __nv_bfloat16* __restrict__ Ah, const __nv_bfloat16* __restrict__ Al,
                const __nv_bfloat16* __restrict__ Bh, const __nv_bfloat16* __restrict__ Bl,
                const float* __restrict__ bias1, const float* __restrict__ bias2,
                float* __restrict__ C, int K, int Ntot)
{
    extern __shared__ char smc[];
    float* sbias = (float*)smc;
    const uint32_t sb = smem_u32(smc);
    const uint32_t sAh = sb + SM_GA,  sAl = sb + SM_GAL;
    const uint32_t sBh = sb + SM_GBH, sBl = sb + SM_GBL;

    const int tid = threadIdx.x, wid = tid >> 5, lid = tid & 31;
    const int bm = blockIdx.y * 128, bn = blockIdx.x * 64;
    const int wm = wid >> 2, wn = wid & 3;

    if (tid < 64) {
        float bv = bias1[bn + tid];
        if (BIAS2) bv += bias2[bn + tid];
        sbias[tid] = bv;
    }

    const int arow = lid & 15;
    const int acol = (lid & 16) ? 8 : 0;
    const int brow = (lid & 7) | ((lid & 16) >> 1);
    const int bcol = (lid & 8) ? 8 : 0;

    float acc[4][2][4];
#pragma unroll
    for (int mi = 0; mi < 4; ++mi)
#pragma unroll
        for (int ni = 0; ni < 2; ++ni)
#pragma unroll
            for (int q = 0; q < 4; ++q) acc[mi][ni][q] = 0.0f;

    for (int kb = 0; kb < K; kb += 64) {
        {
            char* base = smc;
#pragma unroll
            for (int h = 0; h < 4; ++h) {
                int i = tid + h * 256;
                int row = i >> 3, c = i & 7;
                *(float4*)(base + SM_GA + row * (PAD * 2) + c * 16) =
                    *(const float4*)(Ah + (size_t)(bm + row) * K + kb + c * 8);
            }
#pragma unroll
            for (int h = 0; h < 4; ++h) {
                int i = tid + h * 256;
                int row = i >> 3, c = i & 7;
                *(float4*)(base + SM_GAL + row * (PAD * 2) + c * 16) =
                    *(const float4*)(Al + (size_t)(bm + row) * K + kb + c * 8);
            }
#pragma unroll
            for (int h = 0; h < 2; ++h) {
                int i = tid + h * 256;
                int row = i >> 3, c = i & 7;
                *(float4*)(base + SM_GBH + row * (PAD * 2) + c * 16) =
                    *(const float4*)(Bh + (size_t)(bn + row) * K + kb + c * 8);
            }
#pragma unroll
            for (int h = 0; h < 2; ++h) {
                int i = tid + h * 256;
                int row = i >> 3, c = i & 7;
                *(float4*)(base + SM_GBL + row * (PAD * 2) + c * 16) =
                    *(const float4*)(Bl + (size_t)(bn + row) * K + kb + c * 8);
            }
        }
        __syncthreads();

#pragma unroll
        for (int ks = 0; ks < 4; ++ks) {
            const int k0 = ks * 16;
            uint32_t ah[4][4], al[4][4], bh[4], bl[4];
#pragma unroll
            for (int mi = 0; mi < 4; ++mi) {
                uint32_t ra = (uint32_t)((wm * 64 + mi * 16 + arow) * PAD + k0 + acol) * 2;
                ldsm_x4(ah[mi], sAh + ra);
                ldsm_x4(al[mi], sAl + ra);
            }
            {
                uint32_t rb = (uint32_t)((wn * 16 + brow) * PAD + k0 + bcol) * 2;
                ldsm_x4(bh, sBh + rb);
                ldsm_x4(bl, sBl + rb);
            }
#pragma unroll
            for (int mi = 0; mi < 4; ++mi)
#pragma unroll
                for (int ni = 0; ni < 2; ++ni) {
                    mma_bf16(acc[mi][ni], ah[mi], &bh[ni * 2]);
                    mma_bf16(acc[mi][ni], ah[mi], &bl[ni * 2]);
                    mma_bf16(acc[mi][ni], al[mi], &bh[ni * 2]);
                }
        }
        __syncthreads();
    }

    const int r = lid >> 2, c2 = (lid & 3) * 2;
#pragma unroll
    for (int mi = 0; mi < 4; ++mi)
#pragma unroll
        for (int ni = 0; ni < 2; ++ni) {
            int nloc = wn * 16 + ni * 8 + c2;
            float b0 = sbias[nloc], b1 = sbias[nloc + 1];
            int m0 = bm + wm * 64 + mi * 16 + r;
            float v0 = acc[mi][ni][0] + b0, v1 = acc[mi][ni][1] + b1;
            float v2 = acc[mi][ni][2] + b0, v3 = acc[mi][ni][3] + b1;
            if (RELU) {
                v0 = fmaxf(v0, 0.0f); v1 = fmaxf(v1, 0.0f);
                v2 = fmaxf(v2, 0.0f); v3 = fmaxf(v3, 0.0f);
            }
            *(float2*)(C + (size_t)m0 * Ntot + bn + nloc)       = make_float2(v0, v1);
            *(float2*)(C + (size_t)(m0 + 8) * Ntot + bn + nloc) = make_float2(v2, v3);
        }
}

// ============================================================
// conv2 via HMMA implicit GEMM: one CTA per image.
// M=81(pad96) x N=64 x K=512 (k = ic*16 + ky*4 + kx, native w2 flatten).
// 3-term bf16 split; in-smem im2col from the bf16 image planes.
// ============================================================
#define C2_SBIAS 0
#define C2_IMGH  256
#define C2_IMGL  (C2_IMGH + 25600)
#define C2_AH    (C2_IMGL + 25600)          // ushort[96*72]
#define C2_AL    (C2_AH + 13824)
#define C2_BH    (C2_AL + 13824)            // ushort[64*72]
#define C2_BL    (C2_BH + 9216)
#define C2_SMEM  (C2_BL + 9216)             // 97536

__global__ void __launch_bounds__(256, 2)
conv2_mma_kernel(const float* __restrict__ in, const __nv_bfloat16* __restrict__ wh,
                 const __nv_bfloat16* __restrict__ wl, const float* __restrict__ b,
                 float* __restrict__ out)
{
    extern __shared__ char smc[];
    float* sbias = (float*)(smc + C2_SBIAS);
    unsigned short* imgh = (unsigned short*)(smc + C2_IMGH);
    unsigned short* imgl = (unsigned short*)(smc + C2_IMGL);
    unsigned short* Ahs  = (unsigned short*)(smc + C2_AH);
    unsigned short* Als  = (unsigned short*)(smc + C2_AL);
    const uint32_t sb = smem_u32(smc);
    const uint32_t sAh = sb + C2_AH, sAl = sb + C2_AL;
    const uint32_t sBh = sb + C2_BH, sBl = sb + C2_BL;

    const int tid = threadIdx.x, wid = tid >> 5, lid = tid & 31;
    const int n = blockIdx.x;
    const int wm = wid >> 2, wn = wid & 3;          // warp tile (wm*48, wn*16)

    if (tid < 64) sbias[tid] = b[tid];

    // image fp32 -> bf16 hi/lo planes
    const float4* ig = (const float4*)(in + (size_t)n * 12800);
    for (int i = tid; i < 3200; i += 256) {
        float4 v = ig[i];
        float hx = __bfloat162float(__float2bfloat16(v.x));
        float hy = __bfloat162float(__float2bfloat16(v.y));
        float hz = __bfloat162float(__float2bfloat16(v.z));
        float hw = __bfloat162float(__float2bfloat16(v.w));
        ((uint2*)imgh)[i] = make_uint2(bf2(v.x, v.y), bf2(v.z, v.w));
        ((uint2*)imgl)[i] = make_uint2(bf2(v.x - hx, v.y - hy), bf2(v.z - hz, v.w - hw));
    }
    __syncthreads();

    const int arow = lid & 15;
    const int acol = (lid & 16) ? 8 : 0;
    const int brow = (lid & 7) | ((lid & 16) >> 1);
    const int bcol = (lid & 8) ? 8 : 0;

    float acc[3][2][4];
#pragma unroll
    for (int mi = 0; mi < 3; ++mi)
#pragma unroll
        for (int ni = 0; ni < 2; ++ni)
#pragma unroll
            for (int q = 0; q < 4; ++q) acc[mi][ni][q] = 0.0f;

    for (int kc = 0; kc < 8; ++kc) {
        // im2col A tiles (96 x 64)
#pragma unroll
        for (int h = 0; h < 24; ++h) {
            int idx = tid + h * 256;
            int p = idx >> 6, kk = idx & 63;
            int k = kc * 64 + kk;
            int ic = k >> 4, r = k & 15, ky = r >> 2, kx = r & 3;
            unsigned short vh = 0, vl = 0;
            if (p < 81) {
                int oy = p / 9, ox = p - oy * 9;
                int s = ic * 400 + (oy * 2 + ky) * 20 + ox * 2 + kx;
                vh = imgh[s]; vl = imgl[s];
            }
            Ahs[p * PAD + kk] = vh;
            Als[p * PAD + kk] = vl;
        }
        // B tiles (64 x 64) from gmem
#pragma unroll
        for (int h = 0; h < 2; ++h) {
            int i = tid + h * 256;
            int row = i >> 3, c = i & 7;
            *(float4*)(smc + C2_BH + (row * PAD + c * 8) * 2) =
                *(const float4*)(wh + (size_t)row * 512 + kc * 64 + c * 8);
            *(float4*)(smc + C2_BL + (row * PAD + c * 8) * 2) =
                *(const float4*)(wl + (size_t)row * 512 + kc * 64 + c * 8);
        }
        __syncthreads();

#pragma unroll
        for (int ks = 0; ks < 4; ++ks) {
            const int k0 = ks * 16;
            uint32_t ah[3][4], al[3][4], bh[4], bl[4];
#pragma unroll
            for (int mi = 0; mi < 3; ++mi) {
                uint32_t ra = (uint32_t)((wm * 48 + mi * 16 + arow) * PAD + k0 + acol) * 2;
                ldsm_x4(ah[mi], sAh + ra);
                ldsm_x4(al[mi], sAl + ra);
            }
            {
                uint32_t rb = (uint32_t)((wn * 16 + brow) * PAD + k0 + bcol) * 2;
                ldsm_x4(bh, sBh + rb);
                ldsm_x4(bl, sBl + rb);
            }
#pragma unroll
            for (int mi = 0; mi < 3; ++mi)
#pragma unroll
                for (int ni = 0; ni < 2; ++ni) {
                    mma_bf16(acc[mi][ni], ah[mi], &bh[ni * 2]);
                    mma_bf16(acc[mi][ni], ah[mi], &bl[ni * 2]);
                    mma_bf16(acc[mi][ni], al[mi], &bh[ni * 2]);
                }
        }
        __syncthreads();
    }

    const int r = lid >> 2, c2 = (lid & 3) * 2;
    float* ob = out + (size_t)n * 5184;
#pragma unroll
    for (int mi = 0; mi < 3; ++mi)
#pragma unroll
        for (int ni = 0; ni < 2; ++ni) {
            int oc = wn * 16 + ni * 8 + c2;
            float b0 = sbias[oc], b1 = sbias[oc + 1];
            int p0 = wm * 48 + mi * 16 + r;
            if (p0 < 81) {
                ob[oc * 81 + p0]       = fmaxf(acc[mi][ni][0] + b0, 0.0f);
                ob[(oc + 1) * 81 + p0] = fmaxf(acc[mi][ni][1] + b1, 0.0f);
            }
            int p1 = p0 + 8;
            if (p1 < 81) {
                ob[oc * 81 + p1]       = fmaxf(acc[mi][ni][2] + b0, 0.0f);
                ob[(oc + 1) * 81 + p1] = fmaxf(acc[mi][ni][3] + b1, 0.0f);
            }
        }
}

// ============================================================
// conv3 via HMMA implicit GEMM: one CTA per image.
// M=49(pad64) x N=64 x K=576 (k = ic*9 + ky*3 + kx, native w3 flatten).
// ============================================================
#define C3_SBIAS 0
#define C3_IMGH  256
#define C3_IMGL  (C3_IMGH + 10368)
#define C3_AH    (C3_IMGL + 10368)          // ushort[64*72]
#define C3_AL    (C3_AH + 9216)
#define C3_BH    (C3_AL + 9216)
#define C3_BL    (C3_BH + 9216)
#define C3_SMEM  (C3_BL + 9216)             // 57856

__global__ void __launch_bounds__(256, 3)
conv3_mma_kernel(const float* __restrict__ in, const __nv_bfloat16* __restrict__ wh,
                 const __nv_bfloat16* __restrict__ wl, const float* __restrict__ b,
                 float* __restrict__ out)
{
    extern __shared__ char smc[];
    float* sbias = (float*)(smc + C3_SBIAS);
    unsigned short* imgh = (unsigned short*)(smc + C3_IMGH);
    unsigned short* imgl = (unsigned short*)(smc + C3_IMGL);
    unsigned short* Ahs  = (unsigned short*)(smc + C3_AH);
    unsigned short* Als  = (unsigned short*)(smc + C3_AL);
    const uint32_t sb = smem_u32(smc);
    const uint32_t sAh = sb + C3_AH, sAl = sb + C3_AL;
    const uint32_t sBh = sb + C3_BH, sBl = sb + C3_BL;

    const int tid = threadIdx.x, wid = tid >> 5, lid = tid & 31;
    const int n = blockIdx.x;
    const int wm = wid >> 2, wn = wid & 3;          // warp tile (wm*32, wn*16)

    if (tid < 64) sbias[tid] = b[tid];

    const float4* ig = (const float4*)(in + (size_t)n * 5184);
    for (int i = tid; i < 1296; i += 256) {
        float4 v = ig[i];
        float hx = __bfloat162float(__float2bfloat16(v.x));
        float hy = __bfloat162float(__float2bfloat16(v.y));
        float hz = __bfloat162float(__float2bfloat16(v.z));
        float hw = __bfloat162float(__float2bfloat16(v.w));
        ((uint2*)imgh)[i] = make_uint2(bf2(v.x, v.y), bf2(v.z, v.w));
        ((uint2*)imgl)[i] = make_uint2(bf2(v.x - hx, v.y - hy), bf2(v.z - hz, v.w - hw));
    }
    __syncthreads();

    const int arow = lid & 15;
    const int acol = (lid & 16) ? 8 : 0;
    const int brow = (lid & 7) | ((lid & 16) >> 1);
    const int bcol = (lid & 8) ? 8 : 0;

    float acc[2][2][4];
#pragma unroll
    for (int mi = 0; mi < 2; ++mi)
#pragma unroll
        for (int ni = 0; ni < 2; ++ni)
#pragma unroll
            for (int q = 0; q < 4; ++q) acc[mi][ni][q] = 0.0f;

    for (int kc = 0; kc < 9; ++kc) {
        // im2col A tiles (64 x 64)
#pragma unroll
        for (int h = 0; h < 16; ++h) {
            int idx = tid + h * 256;
            int p = idx >> 6, kk = idx & 63;
            int k = kc * 64 + kk;
            int ic = k / 9, r = k - ic * 9;
            int ky = r / 3, kx = r - ky * 3;
            unsigned short vh = 0, vl = 0;
            if (p < 49) {
                int oy = p / 7, ox = p - oy * 7;
                int s = ic * 81 + (oy + ky) * 9 + ox + kx;
                vh = imgh[s]; vl = imgl[s];
            }
            Ahs[p * PAD + kk] = vh;
            Als[p * PAD + kk] = vl;
        }
#pragma unroll
        for (int h = 0; h < 2; ++h) {
            int i = tid + h * 256;
            int row = i >> 3, c = i & 7;
            *(float4*)(smc + C3_BH + (row * PAD + c * 8) * 2) =
                *(const float4*)(wh + (size_t)row * 576 + kc * 64 + c * 8);
            *(float4*)(smc + C3_BL + (row * PAD + c * 8) * 2) =
                *(const float4*)(wl + (size_t)row * 576 + kc * 64 + c * 8);
        }
        __syncthreads();

#pragma unroll
        for (int ks = 0; ks < 4; ++ks) {
            const int k0 = ks * 16;
            uint32_t ah[2][4], al[2][4], bh[4], bl[4];
#pragma unroll
            for (int mi = 0; mi < 2; ++mi) {
                uint32_t ra = (uint32_t)((wm * 32 + mi * 16 + arow) * PAD + k0 + acol) * 2;
                ldsm_x4(ah[mi], sAh + ra);
                ldsm_x4(al[mi], sAl + ra);
            }
            {
                uint32_t rb = (uint32_t)((wn * 16 + brow) * PAD + k0 + bcol) * 2;
                ldsm_x4(bh, sBh + rb);
                ldsm_x4(bl, sBl + rb);
            }
#pragma unroll
            for (int mi = 0; mi < 2; ++mi)
#pragma unroll
                for (int ni = 0; ni < 2; ++ni) {
                    mma_bf16(acc[mi][ni], ah[mi], &bh[ni * 2]);
                    mma_bf16(acc[mi][ni], ah[mi], &bl[ni * 2]);
                    mma_bf16(acc[mi][ni], al[mi], &bh[ni * 2]);
                }
        }
        __syncthreads();
    }

    const int r = lid >> 2, c2 = (lid & 3) * 2;
    float* ob = out + (size_t)n * 3136;
#pragma unroll
    for (int mi = 0; mi < 2; ++mi)
#pragma unroll
        for (int ni = 0; ni < 2; ++ni) {
            int oc = wn * 16 + ni * 8 + c2;
            float b0 = sbias[oc], b1 = sbias[oc + 1];
            int p0 = wm * 32 + mi * 16 + r;
            if (p0 < 49) {
                ob[oc * 49 + p0]       = fmaxf(acc[mi][ni][0] + b0, 0.0f);
                ob[(oc + 1) * 49 + p0] = fmaxf(acc[mi][ni][1] + b1, 0.0f);
            }
            int p1 = p0 + 8;
            if (p1 < 49) {
                ob[oc * 49 + p1]       = fmaxf(acc[mi][ni][2] + b0, 0.0f);
                ob[(oc + 1) * 49 + p1] = fmaxf(acc[mi][ni][3] + b1, 0.0f);
            }
        }
}

// ============================================================
// conv1 [R6, measured 693us]
// ============================================================
__global__ void __launch_bounds__(512, 2)
conv1_kernel(const float* __restrict__ x, const float* __restrict__ wr,
             const float* __restrict__ b, float* __restrict__ out)
{
    extern __shared__ float sm[];
    float* img = sm;            // 14784
    float* ws  = sm + 14784;    // 8192

    const int n = blockIdx.x >> 1, half = blockIdx.x & 1;
    const int t = threadIdx.x;
    const int r0 = half * 40;

    const float4* xg4 = (const float4*)(x + (size_t)n * 28224);
    float4* img4 = (float4*)img;
#pragma unroll 4
    for (int i = t; i < 3696; i += 512) {
        int ch = i / 924, rr = i - ch * 924;
        img4[i] = xg4[ch * 1764 + r0 * 21 + rr];
    }
    const float4* wg = (const float4*)wr;
    float4* ws4 = (float4*)ws;
#pragma unroll
    for (int i = t; i < 2048; i += 512) ws4[i] = wg[i];
    __syncthreads();

    const int ocg = t >> 7, p = t & 127;
    if (p >= 100) return;
    const int oyl = p / 10, xg = p % 10;

    u64 acc[2][4];
#pragma unroll
    for (int q = 0; q < 4; ++q) {
        u64 bq = pk2(b[ocg * 8 + 2 * q], b[ocg * 8 + 2 * q + 1]);
        acc[0][q] = bq; acc[1][q] = bq;
    }

#pragma unroll
    for (int ic = 0; ic < 4; ++ic) {
#pragma unroll
        for (int ky = 0; ky < 8; ++ky) {
            const float* row = &img[ic * 3696 + (oyl * 4 + ky) * 84 + xg * 8];
            float rv[12];
            *(float4*)&rv[0] = *(const float4*)&row[0];
            *(float4*)&rv[4] = *(const float4*)&row[4];
            *(float4*)&rv[8] = *(const float4*)&row[8];
            const float* wb = &ws[((ic * 8 + ky) * 8) * 32 + ocg * 8];
#pragma unroll
            for (int kx = 0; kx < 8; ++kx) {
                ulonglong2 w01 = *(const ulonglong2*)&wb[kx * 32];
                ulonglong2 w23 = *(const ulonglong2*)&wb[kx * 32 + 4];
                u64 v0 = dup2(rv[kx]);
                u64 v1 = dup2(rv[4 + kx]);
                ffma2(acc[0][0], v0, w01.x); ffma2(acc[0][1], v0, w01.y);
                ffma2(acc[0][2], v0, w23.x); ffma2(acc[0][3], v0, w23.y);
                ffma2(acc[1][0], v1, w01.x); ffma2(acc[1][1], v1, w01.y);
                ffma2(acc[1][2], v1, w23.x); ffma2(acc[1][3], v1, w23.y);
            }
        }
    }
    float* op = out + (size_t)n * 12800 + (half * 10 + oyl) * 20 + xg * 2;
#pragma unroll
    for (int q = 0; q < 4; ++q) {
        float lo0, hi0, lo1, hi1;
        upk2(acc[0][q], lo0, hi0);
        upk2(acc[1][q], lo1, hi1);
        int oc0 = ocg * 8 + 2 * q;
        *(float2*)(op + (size_t)oc0 * 400)       = make_float2(fmaxf(lo0, 0.0f), fmaxf(lo1, 0.0f));
        *(float2*)(op + (size_t)(oc0 + 1) * 400) = make_float2(fmaxf(hi0, 0.0f), fmaxf(hi1, 0.0f));
    }
}

// ============================================================
// LSTM recurrence: one CTA per env (32 CTAs), 512 threads.
// ============================================================
#define LSTM_SMEM_BYTES (16 * 512 * 16 + 128 * 4 + 512 * 4)

__global__ void __launch_bounds__(512, 1)
lstm_kernel(const float* __restrict__ gx, const float* __restrict__ whh,
            const int* __restrict__ done, const float* __restrict__ h0,
            const float* __restrict__ c0, float* __restrict__ hid)
{
    extern __shared__ float sm[];
    float4* wp4  = (float4*)sm;
    float*  h_sh = sm + 16 * 512 * 4;
    float*  act  = h_sh + 128;

    const int env = blockIdx.x;
    const int j = threadIdx.x;

    const float* wrow = whh + (size_t)j * 128;
    float wreg[64];
#pragma unroll
    for (int k = 0; k < 64; k += 4) {
        float4 v = *(const float4*)(wrow + k);
        wreg[k] = v.x; wreg[k + 1] = v.y; wreg[k + 2] = v.z; wreg[k + 3] = v.w;
    }
#pragma unroll
    for (int kk = 0; kk < 16; ++kk)
        wp4[kk * 512 + j] = *(const float4*)(wrow + 64 + kk * 4);

    float c = 0.0f, hprev = 0.0f;
    if (j < 128) {
        hprev = h0[env * 128 + j];
        c     = c0[env * 128 + j];
    }
    __syncthreads();

    for (int t = 0; t < TT; ++t) {
        if (j < 128) {
            float m = 1.0f - (float)done[t * BB + env];
            h_sh[j] = hprev * m;
            c *= m;
        }
        __syncthreads();

        float accv = gx[((size_t)t * BB + env) * 512 + j];
#pragma unroll
        for (int k = 0; k < 64; k += 4) {
            float4 hv = *(const float4*)&h_sh[k];
            accv += hv.x * wreg[k] + hv.y * wreg[k + 1]
                  + hv.z * wreg[k + 2] + hv.w * wreg[k + 3];
        }
#pragma unroll
        for (int kk = 0; kk < 16; ++kk) {
            float4 wv = wp4[kk * 512 + j];
            float4 hv = *(const float4*)&h_sh[64 + kk * 4];
            accv += wv.x * hv.x + wv.y * hv.y + wv.z * hv.z + wv.w * hv.w;
        }

        float a;
        if (j < 256 || j >= 384) a = 1.0f / (1.0f + expf(-accv));
        else                     a = tanhf(accv);
        act[j] = a;
        __syncthreads();

        if (j < 128) {
            float ig = act[j],       fg = act[128 + j];
            float gg = act[256 + j], og = act[384 + j];
            c = fg * c + ig * gg;
            hprev = og * tanhf(c);
            hid[((size_t)t * BB + env) * 128 + j] = hprev;
        }
    }
}

// ============================================================
// heads
// ============================================================
__global__ void __launch_bounds__(304, 4)
heads_kernel(const float* __restrict__ hid, const float* __restrict__ wa,
             const float* __restrict__ ba, const float* __restrict__ wc,
             const float* __restrict__ bc, float* __restrict__ out)
{
    __shared__ float wsh[19 * 128];
    __shared__ float hsh[16 * 128];
    __shared__ float bsh[19];

    const int t = threadIdx.x;
    const int rb = blockIdx.x * 16;

    for (int i = t; i < 18 * 128; i += 304) wsh[i] = wa[i];
    for (int i = t; i < 128; i += 304)      wsh[18 * 128 + i] = wc[i];
    for (int i = t; i < 2048; i += 304)     hsh[i] = hid[(size_t)rb * 128 + i];
    if (t < 18) bsh[t] = ba[t];
    if (t == 18) bsh[18] = bc[0];
    __syncthreads();

    const int r = t / 19, cidx = t % 19;
    float accv = bsh[cidx];
    const float* hr = &hsh[r * 128];
    const float* wr = &wsh[cidx * 128];
#pragma unroll
    for (int k = 0; k < 128; k += 4) {
        float4 hv = *(const float4*)(hr + k);
        float4 wv = *(const float4*)(wr + k);
        accv += hv.x * wv.x + hv.y * wv.y + hv.z * wv.z + hv.w * wv.w;
    }
    out[(size_t)(rb + r) * OUTC + cidx] = accv;
}

// ============================================================
// host launcher
// ============================================================
extern "C" void kernel_launch(void* const* d_in, const int* in_sizes, int n_in,
                              void* d_out, int out_size)
{
    const float* x    = (const float*)d_in[0];
    const int*   done = (const int*)  d_in[1];
    const float* h0   = (const float*)d_in[2];
    const float* c0   = (const float*)d_in[3];
    const float* w1   = (const float*)d_in[4];
    const float* b1   = (const float*)d_in[5];
    const float* w2   = (const float*)d_in[6];
    const float* b2   = (const float*)d_in[7];
    const float* w3   = (const float*)d_in[8];
    const float* b3   = (const float*)d_in[9];
    const float* wf   = (const float*)d_in[10];
    const float* bf   = (const float*)d_in[11];
    const float* w_ih = (const float*)d_in[12];
    const float* w_hh = (const float*)d_in[13];
    const float* b_ih = (const float*)d_in[14];
    const float* b_hh = (const float*)d_in[15];
    const float* wa   = (const float*)d_in[16];
    const float* ba   = (const float*)d_in[17];
    const float* wc   = (const float*)d_in[18];
    const float* bc   = (const float*)d_in[19];
    float* out = (float*)d_out;

    float *c1, *c2, *c3, *feat, *gx, *hidp, *w1r;
    cudaGetSymbolAddress((void**)&c1,   g_c1);
    cudaGetSymbolAddress((void**)&c2,   g_c2);
    cudaGetSymbolAddress((void**)&c3,   g_c3);
    cudaGetSymbolAddress((void**)&feat, g_feat);
    cudaGetSymbolAddress((void**)&gx,   g_gx);
    cudaGetSymbolAddress((void**)&hidp, g_hid);
    cudaGetSymbolAddress((void**)&w1r,  g_w1r);
    __nv_bfloat16 *w2h, *w2l, *w3h, *w3l;
    __nv_bfloat16 *a1h, *a1l, *b1h, *b1l, *a2h, *a2l, *b2h, *b2l;
    cudaGetSymbolAddress((void**)&w2h, g_w2h);
    cudaGetSymbolAddress((void**)&w2l, g_w2l);
    cudaGetSymbolAddress((void**)&w3h, g_w3h);
    cudaGetSymbolAddress((void**)&w3l, g_w3l);
    cudaGetSymbolAddress((void**)&a1h, g_a1h);
    cudaGetSymbolAddress((void**)&a1l, g_a1l);
    cudaGetSymbolAddress((void**)&b1h, g_b1h);
    cudaGetSymbolAddress((void**)&b1l, g_b1l);
    cudaGetSymbolAddress((void**)&a2h, g_a2h);
    cudaGetSymbolAddress((void**)&a2l, g_a2l);
    cudaGetSymbolAddress((void**)&b2h, g_b2h);
    cudaGetSymbolAddress((void**)&b2l, g_b2l);

    const int c1_smem = (14784 + 8192) * 4;
    cudaFuncSetAttribute(conv1_kernel, cudaFuncAttributeMaxDynamicSharedMemorySize, c1_smem);
    cudaFuncSetAttribute(conv2_mma_kernel, cudaFuncAttributeMaxDynamicSharedMemorySize, C2_SMEM);
    cudaFuncSetAttribute(conv3_mma_kernel, cudaFuncAttributeMaxDynamicSharedMemorySize, C3_SMEM);
    cudaFuncSetAttribute(lstm_kernel,  cudaFuncAttributeMaxDynamicSharedMemorySize, LSTM_SMEM_BYTES);
    cudaFuncSetAttribute(mma_gemm_kernel<true,  false>, cudaFuncAttributeMaxDynamicSharedMemorySize, MM_SMEM);
    cudaFuncSetAttribute(mma_gemm_kernel<false, true>,  cudaFuncAttributeMaxDynamicSharedMemorySize, MM_SMEM);

    reorder_w_kernel<<<(8192 + 255) / 256, 256>>>(w1, w1r, 256, 32, 1.0f / 255.0f);

    // weight hi/lo converts (native row-major flattens)
    convert_hl_kernel<<<128,  256>>>(w2,   w2h, w2l, 64 * 512);
    convert_hl_kernel<<<144,  256>>>(w3,   w3h, w3l, 64 * 576);
    convert_hl_kernel<<<2048, 256>>>(wf,   b1h, b1l, FEAT * 3136);
    convert_hl_kernel<<<512,  256>>>(w_ih, b2h, b2l, FEAT * FEAT);

    conv1_kernel<<<TB * 2, 512, c1_smem>>>(x, w1r, b1, c1);
    conv2_mma_kernel<<<TB, 256, C2_SMEM>>>(c1, w2h, w2l, b2, c2);
    conv3_mma_kernel<<<TB, 256, C3_SMEM>>>(c2, w3h, w3l, b3, c3);

    // feat = relu(c3 @ wf^T + bf)  via HMMA bf16-split (K=3136)
    convert_hl_kernel<<<4096, 256>>>(c3, a1h, a1l, TB * 3136);
    mma_gemm_kernel<true, false><<<dim3(FEAT / 64, TB / 128), 256, MM_SMEM>>>(
        a1h, a1l, b1h, b1l, bf, nullptr, feat, 3136, FEAT);

    // gx = feat @ w_ih^T + b_ih + b_hh  via HMMA bf16-split (K=512)
    convert_hl_kernel<<<2048, 256>>>(feat, a2h, a2l, TB * FEAT);
    mma_gemm_kernel<false, true><<<dim3(FEAT / 64, TB / 128), 256, MM_SMEM>>>(
        a2h, a2l, b2h, b2l, b_ih, b_hh, gx, FEAT, FEAT);

    lstm_kernel<<<BB, 512, LSTM_SMEM_BYTES>>>(gx, w_hh, done, h0, c0, hidp);

    heads_kernel<<<TB / 16, 304>>>(hidp, wa, ba, wc, bc, out);
}

// round 12
// speedup vs baseline: 1.5564x; 1.5564x over previous
#include <cuda_runtime.h>
#include <cuda_bf16.h>
#include <math.h>
#include <stdint.h>

// ---------------- problem constants ----------------
#define TT   128
#define BB   32
#define TB   (TT*BB)          // 4096
#define HID  128
#define FEAT 512
#define AA   18
#define OUTC (AA+1)           // 19

typedef unsigned long long u64;

// ---------------- packed f32x2 helpers (SASS FFMA2) ----------------
__device__ __forceinline__ u64 pk2(float x, float y) {
    u64 r; asm("mov.b64 %0, {%1, %2};" : "=l"(r) : "f"(x), "f"(y)); return r;
}
__device__ __forceinline__ u64 dup2(float x) { return pk2(x, x); }
__device__ __forceinline__ void ffma2(u64& d, u64 a, u64 b) {
    asm("fma.rn.f32x2 %0, %1, %2, %0;" : "+l"(d) : "l"(a), "l"(b));
}
__device__ __forceinline__ void upk2(u64 v, float& x, float& y) {
    asm("mov.b64 {%0, %1}, %2;" : "=f"(x), "=f"(y) : "l"(v));
}

// ---------------- HMMA helpers (base ISA: mma.sync + ldmatrix) ----------------
__device__ __forceinline__ uint32_t smem_u32(const void* p) {
    uint32_t a;
    asm("{ .reg .u64 t; cvta.to.shared.u64 t, %1; cvt.u32.u64 %0, t; }" : "=r"(a) : "l"(p));
    return a;
}
__device__ __forceinline__ void ldsm_x4(uint32_t* r, uint32_t addr) {
    asm volatile("ldmatrix.sync.aligned.m8n8.x4.shared.b16 {%0,%1,%2,%3}, [%4];"
        : "=r"(r[0]), "=r"(r[1]), "=r"(r[2]), "=r"(r[3]) : "r"(addr));
}
__device__ __forceinline__ void mma_bf16(float* d, const uint32_t* a, const uint32_t* b) {
    asm volatile("mma.sync.aligned.m16n8k16.row.col.f32.bf16.bf16.f32 "
        "{%0,%1,%2,%3}, {%4,%5,%6,%7}, {%8,%9}, {%0,%1,%2,%3};"
        : "+f"(d[0]), "+f"(d[1]), "+f"(d[2]), "+f"(d[3])
        : "r"(a[0]), "r"(a[1]), "r"(a[2]), "r"(a[3]), "r"(b[0]), "r"(b[1]));
}
__device__ __forceinline__ uint32_t bf2(float a, float b) {
    __nv_bfloat162 t = __floats2bfloat162_rn(a, b);
    return *(uint32_t*)&t;
}

// ---------------- scratch (static device allocations) ----------------
__device__ float g_c1[TB * 32 * 20 * 20];
__device__ float g_c2[TB * 64 * 9 * 9];
__device__ float g_c3[TB * 64 * 7 * 7];
__device__ float g_feat[TB * FEAT];
__device__ float g_gx[TB * 4 * HID];
__device__ float g_hid[TB * HID];
__device__ float g_w1r[8192];
// bf16 hi/lo split operands (plain row-major)
__device__ __nv_bfloat16 g_w2h[64 * 512],  g_w2l[64 * 512];       // conv2 weights
__device__ __nv_bfloat16 g_w3h[64 * 576],  g_w3l[64 * 576];       // conv3 weights
__device__ __nv_bfloat16 g_a1h[TB * 3136], g_a1l[TB * 3136];      // c3
__device__ __nv_bfloat16 g_b1h[FEAT * 3136], g_b1l[FEAT * 3136];  // wf
__device__ __nv_bfloat16 g_a2h[TB * FEAT], g_a2l[TB * FEAT];      // feat
__device__ __nv_bfloat16 g_b2h[FEAT * FEAT], g_b2l[FEAT * FEAT];  // w_ih

// ============================================================
// weight reorder (conv1 only): out[r*OC+oc] = in[oc*R+r] * scale
// ============================================================
__global__ void reorder_w_kernel(const float* __restrict__ in,
                                 float* __restrict__ out,
                                 int R, int OC, float scale)
{
    int i = blockIdx.x * 256 + threadIdx.x;
    if (i >= R * OC) return;
    int oc = i / R, r = i - oc * R;
    out[r * OC + oc] = in[oc * R + r] * scale;
}

// ============================================================
// hi/lo bf16 convert, plain row-major
// ============================================================
__global__ void convert_hl_kernel(const float* __restrict__ src,
                                  __nv_bfloat16* __restrict__ hi,
                                  __nv_bfloat16* __restrict__ lo,
                                  int total)
{
    for (int i = blockIdx.x * 256 + threadIdx.x; i < total; i += gridDim.x * 256) {
        float v = src[i];
        __nv_bfloat16 h = __float2bfloat16(v);
        __nv_bfloat16 l = __float2bfloat16(v - __bfloat162float(h));
        hi[i] = h; lo[i] = l;
    }
}

// ============================================================
// HMMA bf16-split GEMM [R10, verified]: C = A@B^T + bias (+bias2)
// ============================================================
#define PAD 72
#define SM_GA   256
#define SM_GAL  (SM_GA  + 128 * PAD * 2)
#define SM_GBH  (SM_GAL + 128 * PAD * 2)
#define SM_GBL  (SM_GBH + 64 * PAD * 2)
#define MM_SMEM (SM_GBL + 64 * PAD * 2)

template <bool RELU, bool BIAS2>
__global__ void __launch_bounds__(256, 2)
mma_gemm_kernel(const __nv_bfloat16* __restrict__ Ah, const __nv_bfloat16* __restrict__ Al,
                const __nv_bfloat16* __restrict__ Bh, const __nv_bfloat16* __restrict__ Bl,
                const float* __restrict__ bias1, const float* __restrict__ bias2,
                float* __restrict__ C, int K, int Ntot)
{
    extern __shared__ char smc[];
    float* sbias = (float*)smc;
    const uint32_t sb = smem_u32(smc);
    const uint32_t sAh = sb + SM_GA,  sAl = sb + SM_GAL;
    const uint32_t sBh = sb + SM_GBH, sBl = sb + SM_GBL;

    const int tid = threadIdx.x, wid = tid >> 5, lid = tid & 31;
    const int bm = blockIdx.y * 128, bn = blockIdx.x * 64;
    const int wm = wid >> 2, wn = wid & 3;

    if (tid < 64) {
        float bv = bias1[bn + tid];
        if (BIAS2) bv += bias2[bn + tid];
        sbias[tid] = bv;
    }

    const int arow = lid & 15;
    const int acol = (lid & 16) ? 8 : 0;
    const int brow = (lid & 7) | ((lid & 16) >> 1);
    const int bcol = (lid & 8) ? 8 : 0;

    float acc[4][2][4];
#pragma unroll
    for (int mi = 0; mi < 4; ++mi)
#pragma unroll
        for (int ni = 0; ni < 2; ++ni)
#pragma unroll
            for (int q = 0; q < 4; ++q) acc[mi][ni][q] = 0.0f;

    for (int kb = 0; kb < K; kb += 64) {
        {
            char* base = smc;
#pragma unroll
            for (int h = 0; h < 4; ++h) {
                int i = tid + h * 256;
                int row = i >> 3, c = i & 7;
                *(float4*)(base + SM_GA + row * (PAD * 2) + c * 16) =
                    *(const float4*)(Ah + (size_t)(bm + row) * K + kb + c * 8);
            }
#pragma unroll
            for (int h = 0; h < 4; ++h) {
                int i = tid + h * 256;
                int row = i >> 3, c = i & 7;
                *(float4*)(base + SM_GAL + row * (PAD * 2) + c * 16) =
                    *(const float4*)(Al + (size_t)(bm + row) * K + kb + c * 8);
            }
#pragma unroll
            for (int h = 0; h < 2; ++h) {
                int i = tid + h * 256;
                int row = i >> 3, c = i & 7;
                *(float4*)(base + SM_GBH + row * (PAD * 2) + c * 16) =
                    *(const float4*)(Bh + (size_t)(bn + row) * K + kb + c * 8);
            }
#pragma unroll
            for (int h = 0; h < 2; ++h) {
                int i = tid + h * 256;
                int row = i >> 3, c = i & 7;
                *(float4*)(base + SM_GBL + row * (PAD * 2) + c * 16) =
                    *(const float4*)(Bl + (size_t)(bn + row) * K + kb + c * 8);
            }
        }
        __syncthreads();

#pragma unroll
        for (int ks = 0; ks < 4; ++ks) {
            const int k0 = ks * 16;
            uint32_t ah[4][4], al[4][4], bh[4], bl[4];
#pragma unroll
            for (int mi = 0; mi < 4; ++mi) {
                uint32_t ra = (uint32_t)((wm * 64 + mi * 16 + arow) * PAD + k0 + acol) * 2;
                ldsm_x4(ah[mi], sAh + ra);
                ldsm_x4(al[mi], sAl + ra);
            }
            {
                uint32_t rb = (uint32_t)((wn * 16 + brow) * PAD + k0 + bcol) * 2;
                ldsm_x4(bh, sBh + rb);
                ldsm_x4(bl, sBl + rb);
            }
#pragma unroll
            for (int mi = 0; mi < 4; ++mi)
#pragma unroll
                for (int ni = 0; ni < 2; ++ni) {
                    mma_bf16(acc[mi][ni], ah[mi], &bh[ni * 2]);
                    mma_bf16(acc[mi][ni], ah[mi], &bl[ni * 2]);
                    mma_bf16(acc[mi][ni], al[mi], &bh[ni * 2]);
                }
        }
        __syncthreads();
    }

    const int r = lid >> 2, c2 = (lid & 3) * 2;
#pragma unroll
    for (int mi = 0; mi < 4; ++mi)
#pragma unroll
        for (int ni = 0; ni < 2; ++ni) {
            int nloc = wn * 16 + ni * 8 + c2;
            float b0 = sbias[nloc], b1 = sbias[nloc + 1];
            int m0 = bm + wm * 64 + mi * 16 + r;
            float v0 = acc[mi][ni][0] + b0, v1 = acc[mi][ni][1] + b1;
            float v2 = acc[mi][ni][2] + b0, v3 = acc[mi][ni][3] + b1;
            if (RELU) {
                v0 = fmaxf(v0, 0.0f); v1 = fmaxf(v1, 0.0f);
                v2 = fmaxf(v2, 0.0f); v3 = fmaxf(v3, 0.0f);
            }
            *(float2*)(C + (size_t)m0 * Ntot + bn + nloc)       = make_float2(v0, v1);
            *(float2*)(C + (size_t)(m0 + 8) * Ntot + bn + nloc) = make_float2(v2, v3);
        }
}

// ============================================================
// conv2 via HMMA implicit GEMM: one CTA per image.
// M=81(pad96) x N=64 x K=512 (k = ic*16 + ky*4 + kx, native w2 flatten).
// 3-term bf16 split; in-smem im2col from the bf16 image planes.
// ============================================================
#define C2_SBIAS 0
#define C2_IMGH  256
#define C2_IMGL  (C2_IMGH + 25600)
#define C2_AH    (C2_IMGL + 25600)          // ushort[96*72]
#define C2_AL    (C2_AH + 13824)
#define C2_BH    (C2_AL + 13824)            // ushort[64*72]
#define C2_BL    (C2_BH + 9216)
#define C2_SMEM  (C2_BL + 9216)             // 97536

__global__ void __launch_bounds__(256, 2)
conv2_mma_kernel(const float* __restrict__ in, const __nv_bfloat16* __restrict__ wh,
                 const __nv_bfloat16* __restrict__ wl, const float* __restrict__ b,
                 float* __restrict__ out)
{
    extern __shared__ char smc[];
    float* sbias = (float*)(smc + C2_SBIAS);
    unsigned short* imgh = (unsigned short*)(smc + C2_IMGH);
    unsigned short* imgl = (unsigned short*)(smc + C2_IMGL);
    unsigned short* Ahs  = (unsigned short*)(smc + C2_AH);
    unsigned short* Als  = (unsigned short*)(smc + C2_AL);
    const uint32_t sb = smem_u32(smc);
    const uint32_t sAh = sb + C2_AH, sAl = sb + C2_AL;
    const uint32_t sBh = sb + C2_BH, sBl = sb + C2_BL;

    const int tid = threadIdx.x, wid = tid >> 5, lid = tid & 31;
    const int n = blockIdx.x;
    const int wm = wid >> 2, wn = wid & 3;          // warp tile (wm*48, wn*16)

    if (tid < 64) sbias[tid] = b[tid];

    // image fp32 -> bf16 hi/lo planes
    const float4* ig = (const float4*)(in + (size_t)n * 12800);
    for (int i = tid; i < 3200; i += 256) {
        float4 v = ig[i];
        float hx = __bfloat162float(__float2bfloat16(v.x));
        float hy = __bfloat162float(__float2bfloat16(v.y));
        float hz = __bfloat162float(__float2bfloat16(v.z));
        float hw = __bfloat162float(__float2bfloat16(v.w));
        ((uint2*)imgh)[i] = make_uint2(bf2(v.x, v.y), bf2(v.z, v.w));
        ((uint2*)imgl)[i] = make_uint2(bf2(v.x - hx, v.y - hy), bf2(v.z - hz, v.w - hw));
    }
    __syncthreads();

    const int arow = lid & 15;
    const int acol = (lid & 16) ? 8 : 0;
    const int brow = (lid & 7) | ((lid & 16) >> 1);
    const int bcol = (lid & 8) ? 8 : 0;

    float acc[3][2][4];
#pragma unroll
    for (int mi = 0; mi < 3; ++mi)
#pragma unroll
        for (int ni = 0; ni < 2; ++ni)
#pragma unroll
            for (int q = 0; q < 4; ++q) acc[mi][ni][q] = 0.0f;

    for (int kc = 0; kc < 8; ++kc) {
        // im2col A tiles (96 x 64)
#pragma unroll
        for (int h = 0; h < 24; ++h) {
            int idx = tid + h * 256;
            int p = idx >> 6, kk = idx & 63;
            int k = kc * 64 + kk;
            int ic = k >> 4, r = k & 15, ky = r >> 2, kx = r & 3;
            unsigned short vh = 0, vl = 0;
            if (p < 81) {
                int oy = p / 9, ox = p - oy * 9;
                int s = ic * 400 + (oy * 2 + ky) * 20 + ox * 2 + kx;
                vh = imgh[s]; vl = imgl[s];
            }
            Ahs[p * PAD + kk] = vh;
            Als[p * PAD + kk] = vl;
        }
        // B tiles (64 x 64) from gmem
#pragma unroll
        for (int h = 0; h < 2; ++h) {
            int i = tid + h * 256;
            int row = i >> 3, c = i & 7;
            *(float4*)(smc + C2_BH + (row * PAD + c * 8) * 2) =
                *(const float4*)(wh + (size_t)row * 512 + kc * 64 + c * 8);
            *(float4*)(smc + C2_BL + (row * PAD + c * 8) * 2) =
                *(const float4*)(wl + (size_t)row * 512 + kc * 64 + c * 8);
        }
        __syncthreads();

#pragma unroll
        for (int ks = 0; ks < 4; ++ks) {
            const int k0 = ks * 16;
            uint32_t ah[3][4], al[3][4], bh[4], bl[4];
#pragma unroll
            for (int mi = 0; mi < 3; ++mi) {
                uint32_t ra = (uint32_t)((wm * 48 + mi * 16 + arow) * PAD + k0 + acol) * 2;
                ldsm_x4(ah[mi], sAh + ra);
                ldsm_x4(al[mi], sAl + ra);
            }
            {
                uint32_t rb = (uint32_t)((wn * 16 + brow) * PAD + k0 + bcol) * 2;
                ldsm_x4(bh, sBh + rb);
                ldsm_x4(bl, sBl + rb);
            }
#pragma unroll
            for (int mi = 0; mi < 3; ++mi)
#pragma unroll
                for (int ni = 0; ni < 2; ++ni) {
                    mma_bf16(acc[mi][ni], ah[mi], &bh[ni * 2]);
                    mma_bf16(acc[mi][ni], ah[mi], &bl[ni * 2]);
                    mma_bf16(acc[mi][ni], al[mi], &bh[ni * 2]);
                }
        }
        __syncthreads();
    }

    const int r = lid >> 2, c2 = (lid & 3) * 2;
    float* ob = out + (size_t)n * 5184;
#pragma unroll
    for (int mi = 0; mi < 3; ++mi)
#pragma unroll
        for (int ni = 0; ni < 2; ++ni) {
            int oc = wn * 16 + ni * 8 + c2;
            float b0 = sbias[oc], b1 = sbias[oc + 1];
            int p0 = wm * 48 + mi * 16 + r;
            if (p0 < 81) {
                ob[oc * 81 + p0]       = fmaxf(acc[mi][ni][0] + b0, 0.0f);
                ob[(oc + 1) * 81 + p0] = fmaxf(acc[mi][ni][1] + b1, 0.0f);
            }
            int p1 = p0 + 8;
            if (p1 < 81) {
                ob[oc * 81 + p1]       = fmaxf(acc[mi][ni][2] + b0, 0.0f);
                ob[(oc + 1) * 81 + p1] = fmaxf(acc[mi][ni][3] + b1, 0.0f);
            }
        }
}

// ============================================================
// conv3 via HMMA implicit GEMM: one CTA per image.
// M=49(pad64) x N=64 x K=576 (k = ic*9 + ky*3 + kx, native w3 flatten).
// ============================================================
#define C3_SBIAS 0
#define C3_IMGH  256
#define C3_IMGL  (C3_IMGH + 10368)
#define C3_AH    (C3_IMGL + 10368)          // ushort[64*72]
#define C3_AL    (C3_AH + 9216)
#define C3_BH    (C3_AL + 9216)
#define C3_BL    (C3_BH + 9216)
#define C3_SMEM  (C3_BL + 9216)             // 57856

__global__ void __launch_bounds__(256, 3)
conv3_mma_kernel(const float* __restrict__ in, const __nv_bfloat16* __restrict__ wh,
                 const __nv_bfloat16* __restrict__ wl, const float* __restrict__ b,
                 float* __restrict__ out)
{
    extern __shared__ char smc[];
    float* sbias = (float*)(smc + C3_SBIAS);
    unsigned short* imgh = (unsigned short*)(smc + C3_IMGH);
    unsigned short* imgl = (unsigned short*)(smc + C3_IMGL);
    unsigned short* Ahs  = (unsigned short*)(smc + C3_AH);
    unsigned short* Als  = (unsigned short*)(smc + C3_AL);
    const uint32_t sb = smem_u32(smc);
    const uint32_t sAh = sb + C3_AH, sAl = sb + C3_AL;
    const uint32_t sBh = sb + C3_BH, sBl = sb + C3_BL;

    const int tid = threadIdx.x, wid = tid >> 5, lid = tid & 31;
    const int n = blockIdx.x;
    const int wm = wid >> 2, wn = wid & 3;          // warp tile (wm*32, wn*16)

    if (tid < 64) sbias[tid] = b[tid];

    const float4* ig = (const float4*)(in + (size_t)n * 5184);
    for (int i = tid; i < 1296; i += 256) {
        float4 v = ig[i];
        float hx = __bfloat162float(__float2bfloat16(v.x));
        float hy = __bfloat162float(__float2bfloat16(v.y));
        float hz = __bfloat162float(__float2bfloat16(v.z));
        float hw = __bfloat162float(__float2bfloat16(v.w));
        ((uint2*)imgh)[i] = make_uint2(bf2(v.x, v.y), bf2(v.z, v.w));
        ((uint2*)imgl)[i] = make_uint2(bf2(v.x - hx, v.y - hy), bf2(v.z - hz, v.w - hw));
    }
    __syncthreads();

    const int arow = lid & 15;
    const int acol = (lid & 16) ? 8 : 0;
    const int brow = (lid & 7) | ((lid & 16) >> 1);
    const int bcol = (lid & 8) ? 8 : 0;

    float acc[2][2][4];
#pragma unroll
    for (int mi = 0; mi < 2; ++mi)
#pragma unroll
        for (int ni = 0; ni < 2; ++ni)
#pragma unroll
            for (int q = 0; q < 4; ++q) acc[mi][ni][q] = 0.0f;

    for (int kc = 0; kc < 9; ++kc) {
        // im2col A tiles (64 x 64)
#pragma unroll
        for (int h = 0; h < 16; ++h) {
            int idx = tid + h * 256;
            int p = idx >> 6, kk = idx & 63;
            int k = kc * 64 + kk;
            int ic = k / 9, r = k - ic * 9;
            int ky = r / 3, kx = r - ky * 3;
            unsigned short vh = 0, vl = 0;
            if (p < 49) {
                int oy = p / 7, ox = p - oy * 7;
                int s = ic * 81 + (oy + ky) * 9 + ox + kx;
                vh = imgh[s]; vl = imgl[s];
            }
            Ahs[p * PAD + kk] = vh;
            Als[p * PAD + kk] = vl;
        }
#pragma unroll
        for (int h = 0; h < 2; ++h) {
            int i = tid + h * 256;
            int row = i >> 3, c = i & 7;
            *(float4*)(smc + C3_BH + (row * PAD + c * 8) * 2) =
                *(const float4*)(wh + (size_t)row * 576 + kc * 64 + c * 8);
            *(float4*)(smc + C3_BL + (row * PAD + c * 8) * 2) =
                *(const float4*)(wl + (size_t)row * 576 + kc * 64 + c * 8);
        }
        __syncthreads();

#pragma unroll
        for (int ks = 0; ks < 4; ++ks) {
            const int k0 = ks * 16;
            uint32_t ah[2][4], al[2][4], bh[4], bl[4];
#pragma unroll
            for (int mi = 0; mi < 2; ++mi) {
                uint32_t ra = (uint32_t)((wm * 32 + mi * 16 + arow) * PAD + k0 + acol) * 2;
                ldsm_x4(ah[mi], sAh + ra);
                ldsm_x4(al[mi], sAl + ra);
            }
            {
                uint32_t rb = (uint32_t)((wn * 16 + brow) * PAD + k0 + bcol) * 2;
                ldsm_x4(bh, sBh + rb);
                ldsm_x4(bl, sBl + rb);
            }
#pragma unroll
            for (int mi = 0; mi < 2; ++mi)
#pragma unroll
                for (int ni = 0; ni < 2; ++ni) {
                    mma_bf16(acc[mi][ni], ah[mi], &bh[ni * 2]);
                    mma_bf16(acc[mi][ni], ah[mi], &bl[ni * 2]);
                    mma_bf16(acc[mi][ni], al[mi], &bh[ni * 2]);
                }
        }
        __syncthreads();
    }

    const int r = lid >> 2, c2 = (lid & 3) * 2;
    float* ob = out + (size_t)n * 3136;
#pragma unroll
    for (int mi = 0; mi < 2; ++mi)
#pragma unroll
        for (int ni = 0; ni < 2; ++ni) {
            int oc = wn * 16 + ni * 8 + c2;
            float b0 = sbias[oc], b1 = sbias[oc + 1];
            int p0 = wm * 32 + mi * 16 + r;
            if (p0 < 49) {
                ob[oc * 49 + p0]       = fmaxf(acc[mi][ni][0] + b0, 0.0f);
                ob[(oc + 1) * 49 + p0] = fmaxf(acc[mi][ni][1] + b1, 0.0f);
            }
            int p1 = p0 + 8;
            if (p1 < 49) {
                ob[oc * 49 + p1]       = fmaxf(acc[mi][ni][2] + b0, 0.0f);
                ob[(oc + 1) * 49 + p1] = fmaxf(acc[mi][ni][3] + b1, 0.0f);
            }
        }
}

// ============================================================
// conv1 [R6, measured 693us]
// ============================================================
__global__ void __launch_bounds__(512, 2)
conv1_kernel(const float* __restrict__ x, const float* __restrict__ wr,
             const float* __restrict__ b, float* __restrict__ out)
{
    extern __shared__ float sm[];
    float* img = sm;            // 14784
    float* ws  = sm + 14784;    // 8192

    const int n = blockIdx.x >> 1, half = blockIdx.x & 1;
    const int t = threadIdx.x;
    const int r0 = half * 40;

    const float4* xg4 = (const float4*)(x + (size_t)n * 28224);
    float4* img4 = (float4*)img;
#pragma unroll 4
    for (int i = t; i < 3696; i += 512) {
        int ch = i / 924, rr = i - ch * 924;
        img4[i] = xg4[ch * 1764 + r0 * 21 + rr];
    }
    const float4* wg = (const float4*)wr;
    float4* ws4 = (float4*)ws;
#pragma unroll
    for (int i = t; i < 2048; i += 512) ws4[i] = wg[i];
    __syncthreads();

    const int ocg = t >> 7, p = t & 127;
    if (p >= 100) return;
    const int oyl = p / 10, xg = p % 10;

    u64 acc[2][4];
#pragma unroll
    for (int q = 0; q < 4; ++q) {
        u64 bq = pk2(b[ocg * 8 + 2 * q], b[ocg * 8 + 2 * q + 1]);
        acc[0][q] = bq; acc[1][q] = bq;
    }

#pragma unroll
    for (int ic = 0; ic < 4; ++ic) {
#pragma unroll
        for (int ky = 0; ky < 8; ++ky) {
            const float* row = &img[ic * 3696 + (oyl * 4 + ky) * 84 + xg * 8];
            float rv[12];
            *(float4*)&rv[0] = *(const float4*)&row[0];
            *(float4*)&rv[4] = *(const float4*)&row[4];
            *(float4*)&rv[8] = *(const float4*)&row[8];
            const float* wb = &ws[((ic * 8 + ky) * 8) * 32 + ocg * 8];
#pragma unroll
            for (int kx = 0; kx < 8; ++kx) {
                ulonglong2 w01 = *(const ulonglong2*)&wb[kx * 32];
                ulonglong2 w23 = *(const ulonglong2*)&wb[kx * 32 + 4];
                u64 v0 = dup2(rv[kx]);
                u64 v1 = dup2(rv[4 + kx]);
                ffma2(acc[0][0], v0, w01.x); ffma2(acc[0][1], v0, w01.y);
                ffma2(acc[0][2], v0, w23.x); ffma2(acc[0][3], v0, w23.y);
                ffma2(acc[1][0], v1, w01.x); ffma2(acc[1][1], v1, w01.y);
                ffma2(acc[1][2], v1, w23.x); ffma2(acc[1][3], v1, w23.y);
            }
        }
    }
    float* op = out + (size_t)n * 12800 + (half * 10 + oyl) * 20 + xg * 2;
#pragma unroll
    for (int q = 0; q < 4; ++q) {
        float lo0, hi0, lo1, hi1;
        upk2(acc[0][q], lo0, hi0);
        upk2(acc[1][q], lo1, hi1);
        int oc0 = ocg * 8 + 2 * q;
        *(float2*)(op + (size_t)oc0 * 400)       = make_float2(fmaxf(lo0, 0.0f), fmaxf(lo1, 0.0f));
        *(float2*)(op + (size_t)(oc0 + 1) * 400) = make_float2(fmaxf(hi0, 0.0f), fmaxf(hi1, 0.0f));
    }
}

// ============================================================
// LSTM recurrence: one CTA per env (32 CTAs), 512 threads.
// ============================================================
#define LSTM_SMEM_BYTES (16 * 512 * 16 + 128 * 4 + 512 * 4)

__global__ void __launch_bounds__(512, 1)
lstm_kernel(const float* __restrict__ gx, const float* __restrict__ whh,
            const int* __restrict__ done, const float* __restrict__ h0,
            const float* __restrict__ c0, float* __restrict__ hid)
{
    extern __shared__ float sm[];
    float4* wp4  = (float4*)sm;
    float*  h_sh = sm + 16 * 512 * 4;
    float*  act  = h_sh + 128;

    const int env = blockIdx.x;
    const int j = threadIdx.x;

    const float* wrow = whh + (size_t)j * 128;
    float wreg[64];
#pragma unroll
    for (int k = 0; k < 64; k += 4) {
        float4 v = *(const float4*)(wrow + k);
        wreg[k] = v.x; wreg[k + 1] = v.y; wreg[k + 2] = v.z; wreg[k + 3] = v.w;
    }
#pragma unroll
    for (int kk = 0; kk < 16; ++kk)
        wp4[kk * 512 + j] = *(const float4*)(wrow + 64 + kk * 4);

    float c = 0.0f, hprev = 0.0f;
    if (j < 128) {
        hprev = h0[env * 128 + j];
        c     = c0[env * 128 + j];
    }
    __syncthreads();

    for (int t = 0; t < TT; ++t) {
        if (j < 128) {
            float m = 1.0f - (float)done[t * BB + env];
            h_sh[j] = hprev * m;
            c *= m;
        }
        __syncthreads();

        float accv = gx[((size_t)t * BB + env) * 512 + j];
#pragma unroll
        for (int k = 0; k < 64; k += 4) {
            float4 hv = *(const float4*)&h_sh[k];
            accv += hv.x * wreg[k] + hv.y * wreg[k + 1]
                  + hv.z * wreg[k + 2] + hv.w * wreg[k + 3];
        }
#pragma unroll
        for (int kk = 0; kk < 16; ++kk) {
            float4 wv = wp4[kk * 512 + j];
            float4 hv = *(const float4*)&h_sh[64 + kk * 4];
            accv += wv.x * hv.x + wv.y * hv.y + wv.z * hv.z + wv.w * hv.w;
        }

        float a;
        if (j < 256 || j >= 384) a = 1.0f / (1.0f + expf(-accv));
        else                     a = tanhf(accv);
        act[j] = a;
        __syncthreads();

        if (j < 128) {
            float ig = act[j],       fg = act[128 + j];
            float gg = act[256 + j], og = act[384 + j];
            c = fg * c + ig * gg;
            hprev = og * tanhf(c);
            hid[((size_t)t * BB + env) * 128 + j] = hprev;
        }
    }
}

// ============================================================
// heads
// ============================================================
__global__ void __launch_bounds__(304, 4)
heads_kernel(const float* __restrict__ hid, const float* __restrict__ wa,
             const float* __restrict__ ba, const float* __restrict__ wc,
             const float* __restrict__ bc, float* __restrict__ out)
{
    __shared__ float wsh[19 * 128];
    __shared__ float hsh[16 * 128];
    __shared__ float bsh[19];

    const int t = threadIdx.x;
    const int rb = blockIdx.x * 16;

    for (int i = t; i < 18 * 128; i += 304) wsh[i] = wa[i];
    for (int i = t; i < 128; i += 304)      wsh[18 * 128 + i] = wc[i];
    for (int i = t; i < 2048; i += 304)     hsh[i] = hid[(size_t)rb * 128 + i];
    if (t < 18) bsh[t] = ba[t];
    if (t == 18) bsh[18] = bc[0];
    __syncthreads();

    const int r = t / 19, cidx = t % 19;
    float accv = bsh[cidx];
    const float* hr = &hsh[r * 128];
    const float* wr = &wsh[cidx * 128];
#pragma unroll
    for (int k = 0; k < 128; k += 4) {
        float4 hv = *(const float4*)(hr + k);
        float4 wv = *(const float4*)(wr + k);
        accv += hv.x * wv.x + hv.y * wv.y + hv.z * wv.z + hv.w * wv.w;
    }
    out[(size_t)(rb + r) * OUTC + cidx] = accv;
}

// ============================================================
// host launcher
// ============================================================
extern "C" void kernel_launch(void* const* d_in, const int* in_sizes, int n_in,
                              void* d_out, int out_size)
{
    const float* x    = (const float*)d_in[0];
    const int*   done = (const int*)  d_in[1];
    const float* h0   = (const float*)d_in[2];
    const float* c0   = (const float*)d_in[3];
    const float* w1   = (const float*)d_in[4];
    const float* b1   = (const float*)d_in[5];
    const float* w2   = (const float*)d_in[6];
    const float* b2   = (const float*)d_in[7];
    const float* w3   = (const float*)d_in[8];
    const float* b3   = (const float*)d_in[9];
    const float* wf   = (const float*)d_in[10];
    const float* bf   = (const float*)d_in[11];
    const float* w_ih = (const float*)d_in[12];
    const float* w_hh = (const float*)d_in[13];
    const float* b_ih = (const float*)d_in[14];
    const float* b_hh = (const float*)d_in[15];
    const float* wa   = (const float*)d_in[16];
    const float* ba   = (const float*)d_in[17];
    const float* wc   = (const float*)d_in[18];
    const float* bc   = (const float*)d_in[19];
    float* out = (float*)d_out;

    float *c1, *c2, *c3, *feat, *gx, *hidp, *w1r;
    cudaGetSymbolAddress((void**)&c1,   g_c1);
    cudaGetSymbolAddress((void**)&c2,   g_c2);
    cudaGetSymbolAddress((void**)&c3,   g_c3);
    cudaGetSymbolAddress((void**)&feat, g_feat);
    cudaGetSymbolAddress((void**)&gx,   g_gx);
    cudaGetSymbolAddress((void**)&hidp, g_hid);
    cudaGetSymbolAddress((void**)&w1r,  g_w1r);
    __nv_bfloat16 *w2h, *w2l, *w3h, *w3l;
    __nv_bfloat16 *a1h, *a1l, *b1h, *b1l, *a2h, *a2l, *b2h, *b2l;
    cudaGetSymbolAddress((void**)&w2h, g_w2h);
    cudaGetSymbolAddress((void**)&w2l, g_w2l);
    cudaGetSymbolAddress((void**)&w3h, g_w3h);
    cudaGetSymbolAddress((void**)&w3l, g_w3l);
    cudaGetSymbolAddress((void**)&a1h, g_a1h);
    cudaGetSymbolAddress((void**)&a1l, g_a1l);
    cudaGetSymbolAddress((void**)&b1h, g_b1h);
    cudaGetSymbolAddress((void**)&b1l, g_b1l);
    cudaGetSymbolAddress((void**)&a2h, g_a2h);
    cudaGetSymbolAddress((void**)&a2l, g_a2l);
    cudaGetSymbolAddress((void**)&b2h, g_b2h);
    cudaGetSymbolAddress((void**)&b2l, g_b2l);

    const int c1_smem = (14784 + 8192) * 4;
    cudaFuncSetAttribute(conv1_kernel, cudaFuncAttributeMaxDynamicSharedMemorySize, c1_smem);
    cudaFuncSetAttribute(conv2_mma_kernel, cudaFuncAttributeMaxDynamicSharedMemorySize, C2_SMEM);
    cudaFuncSetAttribute(conv3_mma_kernel, cudaFuncAttributeMaxDynamicSharedMemorySize, C3_SMEM);
    cudaFuncSetAttribute(lstm_kernel,  cudaFuncAttributeMaxDynamicSharedMemorySize, LSTM_SMEM_BYTES);
    cudaFuncSetAttribute(mma_gemm_kernel<true,  false>, cudaFuncAttributeMaxDynamicSharedMemorySize, MM_SMEM);
    cudaFuncSetAttribute(mma_gemm_kernel<false, true>,  cudaFuncAttributeMaxDynamicSharedMemorySize, MM_SMEM);

    reorder_w_kernel<<<(8192 + 255) / 256, 256>>>(w1, w1r, 256, 32, 1.0f / 255.0f);

    // weight hi/lo converts (native row-major flattens)
    convert_hl_kernel<<<128,  256>>>(w2,   w2h, w2l, 64 * 512);
    convert_hl_kernel<<<144,  256>>>(w3,   w3h, w3l, 64 * 576);
    convert_hl_kernel<<<2048, 256>>>(wf,   b1h, b1l, FEAT * 3136);
    convert_hl_kernel<<<512,  256>>>(w_ih, b2h, b2l, FEAT * FEAT);

    conv1_kernel<<<TB * 2, 512, c1_smem>>>(x, w1r, b1, c1);
    conv2_mma_kernel<<<TB, 256, C2_SMEM>>>(c1, w2h, w2l, b2, c2);
    conv3_mma_kernel<<<TB, 256, C3_SMEM>>>(c2, w3h, w3l, b3, c3);

    // feat = relu(c3 @ wf^T + bf)  via HMMA bf16-split (K=3136)
    convert_hl_kernel<<<4096, 256>>>(c3, a1h, a1l, TB * 3136);
    mma_gemm_kernel<true, false><<<dim3(FEAT / 64, TB / 128), 256, MM_SMEM>>>(
        a1h, a1l, b1h, b1l, bf, nullptr, feat, 3136, FEAT);

    // gx = feat @ w_ih^T + b_ih + b_hh  via HMMA bf16-split (K=512)
    convert_hl_kernel<<<2048, 256>>>(feat, a2h, a2l, TB * FEAT);
    mma_gemm_kernel<false, true><<<dim3(FEAT / 64, TB / 128), 256, MM_SMEM>>>(
        a2h, a2l, b2h, b2l, b_ih, b_hh, gx, FEAT, FEAT);

    lstm_kernel<<<BB, 512, LSTM_SMEM_BYTES>>>(gx, w_hh, done, h0, c0, hidp);

    heads_kernel<<<TB / 16, 304>>>(hidp, wa, ba, wc, bc, out);
}

// round 13
// speedup vs baseline: 1.6044x; 1.0308x over previous
#include <cuda_runtime.h>
#include <cuda_bf16.h>
#include <math.h>
#include <stdint.h>

// ---------------- problem constants ----------------
#define TT   128
#define BB   32
#define TB   (TT*BB)          // 4096
#define HID  128
#define FEAT 512
#define AA   18
#define OUTC (AA+1)           // 19

typedef unsigned long long u64;

// ---------------- HMMA helpers (base ISA: mma.sync + ldmatrix) ----------------
__device__ __forceinline__ uint32_t smem_u32(const void* p) {
    uint32_t a;
    asm("{ .reg .u64 t; cvta.to.shared.u64 t, %1; cvt.u32.u64 %0, t; }" : "=r"(a) : "l"(p));
    return a;
}
__device__ __forceinline__ void ldsm_x4(uint32_t* r, uint32_t addr) {
    asm volatile("ldmatrix.sync.aligned.m8n8.x4.shared.b16 {%0,%1,%2,%3}, [%4];"
        : "=r"(r[0]), "=r"(r[1]), "=r"(r[2]), "=r"(r[3]) : "r"(addr));
}
__device__ __forceinline__ void mma_bf16(float* d, const uint32_t* a, const uint32_t* b) {
    asm volatile("mma.sync.aligned.m16n8k16.row.col.f32.bf16.bf16.f32 "
        "{%0,%1,%2,%3}, {%4,%5,%6,%7}, {%8,%9}, {%0,%1,%2,%3};"
        : "+f"(d[0]), "+f"(d[1]), "+f"(d[2]), "+f"(d[3])
        : "r"(a[0]), "r"(a[1]), "r"(a[2]), "r"(a[3]), "r"(b[0]), "r"(b[1]));
}
__device__ __forceinline__ uint32_t bf2(float a, float b) {
    __nv_bfloat162 t = __floats2bfloat162_rn(a, b);
    return *(uint32_t*)&t;
}

// ---------------- scratch (static device allocations) ----------------
__device__ float g_c1[TB * 32 * 20 * 20];
__device__ float g_c2[TB * 64 * 9 * 9];
__device__ float g_c3[TB * 64 * 7 * 7];
__device__ float g_feat[TB * FEAT];
__device__ float g_gx[TB * 4 * HID];
__device__ float g_hid[TB * HID];
// bf16 hi/lo split operands (plain row-major)
__device__ __nv_bfloat16 g_w1h[32 * 256],  g_w1l[32 * 256];       // conv1 w (x 1/255)
__device__ __nv_bfloat16 g_w2h[64 * 512],  g_w2l[64 * 512];       // conv2 weights
__device__ __nv_bfloat16 g_w3h[64 * 576],  g_w3l[64 * 576];       // conv3 weights
__device__ __nv_bfloat16 g_a1h[TB * 3136], g_a1l[TB * 3136];      // c3
__device__ __nv_bfloat16 g_b1h[FEAT * 3136], g_b1l[FEAT * 3136];  // wf
__device__ __nv_bfloat16 g_a2h[TB * FEAT], g_a2l[TB * FEAT];      // feat
__device__ __nv_bfloat16 g_b2h[FEAT * FEAT], g_b2l[FEAT * FEAT];  // w_ih

// ============================================================
// hi/lo bf16 convert, plain row-major, optional scale
// ============================================================
__global__ void convert_hl_kernel(const float* __restrict__ src,
                                  __nv_bfloat16* __restrict__ hi,
                                  __nv_bfloat16* __restrict__ lo,
                                  int total, float scale)
{
    for (int i = blockIdx.x * 256 + threadIdx.x; i < total; i += gridDim.x * 256) {
        float v = src[i] * scale;
        __nv_bfloat16 h = __float2bfloat16(v);
        __nv_bfloat16 l = __float2bfloat16(v - __bfloat162float(h));
        hi[i] = h; lo[i] = l;
    }
}

// ============================================================
// HMMA bf16-split GEMM [R10, verified]: C = A@B^T + bias (+bias2)
// ============================================================
#define PAD 72
#define SM_GA   256
#define SM_GAL  (SM_GA  + 128 * PAD * 2)
#define SM_GBH  (SM_GAL + 128 * PAD * 2)
#define SM_GBL  (SM_GBH + 64 * PAD * 2)
#define MM_SMEM (SM_GBL + 64 * PAD * 2)

template <bool RELU, bool BIAS2>
__global__ void __launch_bounds__(256, 2)
mma_gemm_kernel(const __nv_bfloat16* __restrict__ Ah, const __nv_bfloat16* __restrict__ Al,
                const __nv_bfloat16* __restrict__ Bh, const __nv_bfloat16* __restrict__ Bl,
                const float* __restrict__ bias1, const float* __restrict__ bias2,
                float* __restrict__ C, int K, int Ntot)
{
    extern __shared__ char smc[];
    float* sbias = (float*)smc;
    const uint32_t sb = smem_u32(smc);
    const uint32_t sAh = sb + SM_GA,  sAl = sb + SM_GAL;
    const uint32_t sBh = sb + SM_GBH, sBl = sb + SM_GBL;

    const int tid = threadIdx.x, wid = tid >> 5, lid = tid & 31;
    const int bm = blockIdx.y * 128, bn = blockIdx.x * 64;
    const int wm = wid >> 2, wn = wid & 3;

    if (tid < 64) {
        float bv = bias1[bn + tid];
        if (BIAS2) bv += bias2[bn + tid];
        sbias[tid] = bv;
    }

    const int arow = lid & 15;
    const int acol = (lid & 16) ? 8 : 0;
    const int brow = (lid & 7) | ((lid & 16) >> 1);
    const int bcol = (lid & 8) ? 8 : 0;

    float acc[4][2][4];
#pragma unroll
    for (int mi = 0; mi < 4; ++mi)
#pragma unroll
        for (int ni = 0; ni < 2; ++ni)
#pragma unroll
            for (int q = 0; q < 4; ++q) acc[mi][ni][q] = 0.0f;

    for (int kb = 0; kb < K; kb += 64) {
        {
            char* base = smc;
#pragma unroll
            for (int h = 0; h < 4; ++h) {
                int i = tid + h * 256;
                int row = i >> 3, c = i & 7;
                *(float4*)(base + SM_GA + row * (PAD * 2) + c * 16) =
                    *(const float4*)(Ah + (size_t)(bm + row) * K + kb + c * 8);
            }
#pragma unroll
            for (int h = 0; h < 4; ++h) {
                int i = tid + h * 256;
                int row = i >> 3, c = i & 7;
                *(float4*)(base + SM_GAL + row * (PAD * 2) + c * 16) =
                    *(const float4*)(Al + (size_t)(bm + row) * K + kb + c * 8);
            }
#pragma unroll
            for (int h = 0; h < 2; ++h) {
                int i = tid + h * 256;
                int row = i >> 3, c = i & 7;
                *(float4*)(base + SM_GBH + row * (PAD * 2) + c * 16) =
                    *(const float4*)(Bh + (size_t)(bn + row) * K + kb + c * 8);
            }
#pragma unroll
            for (int h = 0; h < 2; ++h) {
                int i = tid + h * 256;
                int row = i >> 3, c = i & 7;
                *(float4*)(base + SM_GBL + row * (PAD * 2) + c * 16) =
                    *(const float4*)(Bl + (size_t)(bn + row) * K + kb + c * 8);
            }
        }
        __syncthreads();

#pragma unroll
        for (int ks = 0; ks < 4; ++ks) {
            const int k0 = ks * 16;
            uint32_t ah[4][4], al[4][4], bh[4], bl[4];
#pragma unroll
            for (int mi = 0; mi < 4; ++mi) {
                uint32_t ra = (uint32_t)((wm * 64 + mi * 16 + arow) * PAD + k0 + acol) * 2;
                ldsm_x4(ah[mi], sAh + ra);
                ldsm_x4(al[mi], sAl + ra);
            }
            {
                uint32_t rb = (uint32_t)((wn * 16 + brow) * PAD + k0 + bcol) * 2;
                ldsm_x4(bh, sBh + rb);
                ldsm_x4(bl, sBl + rb);
            }
#pragma unroll
            for (int mi = 0; mi < 4; ++mi)
#pragma unroll
                for (int ni = 0; ni < 2; ++ni) {
                    mma_bf16(acc[mi][ni], ah[mi], &bh[ni * 2]);
                    mma_bf16(acc[mi][ni], ah[mi], &bl[ni * 2]);
                    mma_bf16(acc[mi][ni], al[mi], &bh[ni * 2]);
                }
        }
        __syncthreads();
    }

    const int r = lid >> 2, c2 = (lid & 3) * 2;
#pragma unroll
    for (int mi = 0; mi < 4; ++mi)
#pragma unroll
        for (int ni = 0; ni < 2; ++ni) {
            int nloc = wn * 16 + ni * 8 + c2;
            float b0 = sbias[nloc], b1 = sbias[nloc + 1];
            int m0 = bm + wm * 64 + mi * 16 + r;
            float v0 = acc[mi][ni][0] + b0, v1 = acc[mi][ni][1] + b1;
            float v2 = acc[mi][ni][2] + b0, v3 = acc[mi][ni][3] + b1;
            if (RELU) {
                v0 = fmaxf(v0, 0.0f); v1 = fmaxf(v1, 0.0f);
                v2 = fmaxf(v2, 0.0f); v3 = fmaxf(v3, 0.0f);
            }
            *(float2*)(C + (size_t)m0 * Ntot + bn + nloc)       = make_float2(v0, v1);
            *(float2*)(C + (size_t)(m0 + 8) * Ntot + bn + nloc) = make_float2(v2, v3);
        }
}

// ============================================================
// conv1 via HMMA implicit GEMM: one CTA per HALF image (10 out rows).
// M=200(pad 256) x N=32 x K=256 (k = ic*64 + ky*8 + kx, native w1 flatten;
// 1/255 folded into weights). K-chunks of 32, PAD1=40 shorts.
// ============================================================
#define PAD1 40
#define C1_SBIAS 0
#define C1_IMGH  128
#define C1_IMGL  (C1_IMGH + 29568)          // 14784 shorts each
#define C1_AH    (C1_IMGL + 29568)          // 256*40 shorts
#define C1_AL    (C1_AH + 20480)
#define C1_BH    (C1_AL + 20480)            // 32*40 shorts
#define C1_BL    (C1_BH + 2560)
#define C1_SMEM  (C1_BL + 2560)             // 105344

__global__ void __launch_bounds__(256, 2)
conv1_mma_kernel(const float* __restrict__ x, const __nv_bfloat16* __restrict__ wh,
                 const __nv_bfloat16* __restrict__ wl, const float* __restrict__ b,
                 float* __restrict__ out)
{
    extern __shared__ char smc[];
    float* sbias = (float*)(smc + C1_SBIAS);
    unsigned short* imgh = (unsigned short*)(smc + C1_IMGH);
    unsigned short* imgl = (unsigned short*)(smc + C1_IMGL);
    unsigned short* Ahs  = (unsigned short*)(smc + C1_AH);
    unsigned short* Als  = (unsigned short*)(smc + C1_AL);
    const uint32_t sb = smem_u32(smc);
    const uint32_t sAh = sb + C1_AH, sAl = sb + C1_AL;
    const uint32_t sBh = sb + C1_BH, sBl = sb + C1_BL;

    const int tid = threadIdx.x, wid = tid >> 5, lid = tid & 31;
    const int n = blockIdx.x >> 1, half = blockIdx.x & 1;
    const int r0 = half * 40;
    const int wm = wid;                        // 8 warps: warp M tile = 32

    if (tid < 32) sbias[tid] = b[tid];

    // image half (44 rows x 4 ch) fp32 gmem -> bf16 hi/lo planes (raw values;
    // 1/255 is folded into the weights)
    const float4* xg4 = (const float4*)(x + (size_t)n * 28224);
    for (int i = tid; i < 3696; i += 256) {
        int ch = i / 924, rr = i - ch * 924;
        float4 v = xg4[ch * 1764 + r0 * 21 + rr];
        float hx = __bfloat162float(__float2bfloat16(v.x));
        float hy = __bfloat162float(__float2bfloat16(v.y));
        float hz = __bfloat162float(__float2bfloat16(v.z));
        float hw = __bfloat162float(__float2bfloat16(v.w));
        ((uint2*)imgh)[i] = make_uint2(bf2(v.x, v.y), bf2(v.z, v.w));
        ((uint2*)imgl)[i] = make_uint2(bf2(v.x - hx, v.y - hy), bf2(v.z - hz, v.w - hw));
    }
    __syncthreads();

    const int arow = lid & 15;
    const int acol = (lid & 16) ? 8 : 0;
    const int brow = (lid & 7) | ((lid & 16) >> 1);
    const int bcol = (lid & 8) ? 8 : 0;

    float acc[2][4][4];                        // [mi][n8 group][frag]
#pragma unroll
    for (int mi = 0; mi < 2; ++mi)
#pragma unroll
        for (int ni = 0; ni < 4; ++ni)
#pragma unroll
            for (int q = 0; q < 4; ++q) acc[mi][ni][q] = 0.0f;

    for (int kc = 0; kc < 8; ++kc) {
        // ---- im2col A tiles (256 x 32), hi+lo ----
#pragma unroll
        for (int h = 0; h < 32; ++h) {
            int idx = tid + h * 256;
            int p = idx >> 5, kk = idx & 31;
            int k = kc * 32 + kk;
            int ic = k >> 6, r = k & 63, ky = r >> 3, kx = r & 7;
            unsigned short vh = 0, vl = 0;
            if (p < 200) {
                int oy = p / 20, ox = p - oy * 20;
                int s = ic * 3696 + (oy * 4 + ky) * 84 + ox * 4 + kx;
                vh = imgh[s]; vl = imgl[s];
            }
            Ahs[p * PAD1 + kk] = vh;
            Als[p * PAD1 + kk] = vl;
        }
        // ---- B tiles (32 x 32): tid<128 hi, else lo ----
        {
            int i = tid & 127;
            int row = i >> 2, c = i & 3;        // 4 float4 (=8 shorts) per row
            const __nv_bfloat16* wsrc = (tid < 128) ? wh : wl;
            char* wdst = smc + ((tid < 128) ? C1_BH : C1_BL);
            *(float4*)(wdst + (row * PAD1 + c * 8) * 2) =
                *(const float4*)(wsrc + (size_t)row * 256 + kc * 32 + c * 8);
        }
        __syncthreads();

#pragma unroll
        for (int ks = 0; ks < 2; ++ks) {
            const int k0 = ks * 16;
            uint32_t ah[2][4], al[2][4], bh[2][4], bl[2][4];
#pragma unroll
            for (int mi = 0; mi < 2; ++mi) {
                uint32_t ra = (uint32_t)((wm * 32 + mi * 16 + arow) * PAD1 + k0 + acol) * 2;
                ldsm_x4(ah[mi], sAh + ra);
                ldsm_x4(al[mi], sAl + ra);
            }
#pragma unroll
            for (int g = 0; g < 2; ++g) {
                uint32_t rb = (uint32_t)((g * 16 + brow) * PAD1 + k0 + bcol) * 2;
                ldsm_x4(bh[g], sBh + rb);
                ldsm_x4(bl[g], sBl + rb);
            }
#pragma unroll
            for (int mi = 0; mi < 2; ++mi)
#pragma unroll
                for (int ni = 0; ni < 4; ++ni) {
                    int g = ni >> 1, j = (ni & 1) * 2;
                    mma_bf16(acc[mi][ni], ah[mi], &bh[g][j]);
                    mma_bf16(acc[mi][ni], ah[mi], &bl[g][j]);
                    mma_bf16(acc[mi][ni], al[mi], &bh[g][j]);
                }
        }
        __syncthreads();
    }

    // ---- epilogue: c1 layout [n][oc][400], pos = half*200 + p ----
    const int r = lid >> 2, c2 = (lid & 3) * 2;
    float* ob = out + (size_t)n * 12800 + half * 200;
#pragma unroll
    for (int mi = 0; mi < 2; ++mi)
#pragma unroll
        for (int ni = 0; ni < 4; ++ni) {
            int oc = ni * 8 + c2;
            float b0 = sbias[oc], b1 = sbias[oc + 1];
            int p0 = wm * 32 + mi * 16 + r;
            if (p0 < 200) {
                ob[oc * 400 + p0]       = fmaxf(acc[mi][ni][0] + b0, 0.0f);
                ob[(oc + 1) * 400 + p0] = fmaxf(acc[mi][ni][1] + b1, 0.0f);
            }
            int p1 = p0 + 8;
            if (p1 < 200) {
                ob[oc * 400 + p1]       = fmaxf(acc[mi][ni][2] + b0, 0.0f);
                ob[(oc + 1) * 400 + p1] = fmaxf(acc[mi][ni][3] + b1, 0.0f);
            }
        }
}

// ============================================================
// conv2 via HMMA implicit GEMM [R12, verified]
// ============================================================
#define C2_SBIAS 0
#define C2_IMGH  256
#define C2_IMGL  (C2_IMGH + 25600)
#define C2_AH    (C2_IMGL + 25600)
#define C2_AL    (C2_AH + 13824)
#define C2_BH    (C2_AL + 13824)
#define C2_BL    (C2_BH + 9216)
#define C2_SMEM  (C2_BL + 9216)

__global__ void __launch_bounds__(256, 2)
conv2_mma_kernel(const float* __restrict__ in, const __nv_bfloat16* __restrict__ wh,
                 const __nv_bfloat16* __restrict__ wl, const float* __restrict__ b,
                 float* __restrict__ out)
{
    extern __shared__ char smc[];
    float* sbias = (float*)(smc + C2_SBIAS);
    unsigned short* imgh = (unsigned short*)(smc + C2_IMGH);
    unsigned short* imgl = (unsigned short*)(smc + C2_IMGL);
    unsigned short* Ahs  = (unsigned short*)(smc + C2_AH);
    unsigned short* Als  = (unsigned short*)(smc + C2_AL);
    const uint32_t sb = smem_u32(smc);
    const uint32_t sAh = sb + C2_AH, sAl = sb + C2_AL;
    const uint32_t sBh = sb + C2_BH, sBl = sb + C2_BL;

    const int tid = threadIdx.x, wid = tid >> 5, lid = tid & 31;
    const int n = blockIdx.x;
    const int wm = wid >> 2, wn = wid & 3;

    if (tid < 64) sbias[tid] = b[tid];

    const float4* ig = (const float4*)(in + (size_t)n * 12800);
    for (int i = tid; i < 3200; i += 256) {
        float4 v = ig[i];
        float hx = __bfloat162float(__float2bfloat16(v.x));
        float hy = __bfloat162float(__float2bfloat16(v.y));
        float hz = __bfloat162float(__float2bfloat16(v.z));
        float hw = __bfloat162float(__float2bfloat16(v.w));
        ((uint2*)imgh)[i] = make_uint2(bf2(v.x, v.y), bf2(v.z, v.w));
        ((uint2*)imgl)[i] = make_uint2(bf2(v.x - hx, v.y - hy), bf2(v.z - hz, v.w - hw));
    }
    __syncthreads();

    const int arow = lid & 15;
    const int acol = (lid & 16) ? 8 : 0;
    const int brow = (lid & 7) | ((lid & 16) >> 1);
    const int bcol = (lid & 8) ? 8 : 0;

    float acc[3][2][4];
#pragma unroll
    for (int mi = 0; mi < 3; ++mi)
#pragma unroll
        for (int ni = 0; ni < 2; ++ni)
#pragma unroll
            for (int q = 0; q < 4; ++q) acc[mi][ni][q] = 0.0f;

    for (int kc = 0; kc < 8; ++kc) {
#pragma unroll
        for (int h = 0; h < 24; ++h) {
            int idx = tid + h * 256;
            int p = idx >> 6, kk = idx & 63;
            int k = kc * 64 + kk;
            int ic = k >> 4, r = k & 15, ky = r >> 2, kx = r & 3;
            unsigned short vh = 0, vl = 0;
            if (p < 81) {
                int oy = p / 9, ox = p - oy * 9;
                int s = ic * 400 + (oy * 2 + ky) * 20 + ox * 2 + kx;
                vh = imgh[s]; vl = imgl[s];
            }
            Ahs[p * PAD + kk] = vh;
            Als[p * PAD + kk] = vl;
        }
#pragma unroll
        for (int h = 0; h < 2; ++h) {
            int i = tid + h * 256;
            int row = i >> 3, c = i & 7;
            *(float4*)(smc + C2_BH + (row * PAD + c * 8) * 2) =
                *(const float4*)(wh + (size_t)row * 512 + kc * 64 + c * 8);
            *(float4*)(smc + C2_BL + (row * PAD + c * 8) * 2) =
                *(const float4*)(wl + (size_t)row * 512 + kc * 64 + c * 8);
        }
        __syncthreads();

#pragma unroll
        for (int ks = 0; ks < 4; ++ks) {
            const int k0 = ks * 16;
            uint32_t ah[3][4], al[3][4], bh[4], bl[4];
#pragma unroll
            for (int mi = 0; mi < 3; ++mi) {
                uint32_t ra = (uint32_t)((wm * 48 + mi * 16 + arow) * PAD + k0 + acol) * 2;
                ldsm_x4(ah[mi], sAh + ra);
                ldsm_x4(al[mi], sAl + ra);
            }
            {
                uint32_t rb = (uint32_t)((wn * 16 + brow) * PAD + k0 + bcol) * 2;
                ldsm_x4(bh, sBh + rb);
                ldsm_x4(bl, sBl + rb);
            }
#pragma unroll
            for (int mi = 0; mi < 3; ++mi)
#pragma unroll
                for (int ni = 0; ni < 2; ++ni) {
                    mma_bf16(acc[mi][ni], ah[mi], &bh[ni * 2]);
                    mma_bf16(acc[mi][ni], ah[mi], &bl[ni * 2]);
                    mma_bf16(acc[mi][ni], al[mi], &bh[ni * 2]);
                }
        }
        __syncthreads();
    }

    const int r = lid >> 2, c2 = (lid & 3) * 2;
    float* ob = out + (size_t)n * 5184;
#pragma unroll
    for (int mi = 0; mi < 3; ++mi)
#pragma unroll
        for (int ni = 0; ni < 2; ++ni) {
            int oc = wn * 16 + ni * 8 + c2;
            float b0 = sbias[oc], b1 = sbias[oc + 1];
            int p0 = wm * 48 + mi * 16 + r;
            if (p0 < 81) {
                ob[oc * 81 + p0]       = fmaxf(acc[mi][ni][0] + b0, 0.0f);
                ob[(oc + 1) * 81 + p0] = fmaxf(acc[mi][ni][1] + b1, 0.0f);
            }
            int p1 = p0 + 8;
            if (p1 < 81) {
                ob[oc * 81 + p1]       = fmaxf(acc[mi][ni][2] + b0, 0.0f);
                ob[(oc + 1) * 81 + p1] = fmaxf(acc[mi][ni][3] + b1, 0.0f);
            }
        }
}

// ============================================================
// conv3 via HMMA implicit GEMM [R12, verified]
// ============================================================
#define C3_SBIAS 0
#define C3_IMGH  256
#define C3_IMGL  (C3_IMGH + 10368)
#define C3_AH    (C3_IMGL + 10368)
#define C3_AL    (C3_AH + 9216)
#define C3_BH    (C3_AL + 9216)
#define C3_BL    (C3_BH + 9216)
#define C3_SMEM  (C3_BL + 9216)

__global__ void __launch_bounds__(256, 3)
conv3_mma_kernel(const float* __restrict__ in, const __nv_bfloat16* __restrict__ wh,
                 const __nv_bfloat16* __restrict__ wl, const float* __restrict__ b,
                 float* __restrict__ out)
{
    extern __shared__ char smc[];
    float* sbias = (float*)(smc + C3_SBIAS);
    unsigned short* imgh = (unsigned short*)(smc + C3_IMGH);
    unsigned short* imgl = (unsigned short*)(smc + C3_IMGL);
    unsigned short* Ahs  = (unsigned short*)(smc + C3_AH);
    unsigned short* Als  = (unsigned short*)(smc + C3_AL);
    const uint32_t sb = smem_u32(smc);
    const uint32_t sAh = sb + C3_AH, sAl = sb + C3_AL;
    const uint32_t sBh = sb + C3_BH, sBl = sb + C3_BL;

    const int tid = threadIdx.x, wid = tid >> 5, lid = tid & 31;
    const int n = blockIdx.x;
    const int wm = wid >> 2, wn = wid & 3;

    if (tid < 64) sbias[tid] = b[tid];

    const float4* ig = (const float4*)(in + (size_t)n * 5184);
    for (int i = tid; i < 1296; i += 256) {
        float4 v = ig[i];
        float hx = __bfloat162float(__float2bfloat16(v.x));
        float hy = __bfloat162float(__float2bfloat16(v.y));
        float hz = __bfloat162float(__float2bfloat16(v.z));
        float hw = __bfloat162float(__float2bfloat16(v.w));
        ((uint2*)imgh)[i] = make_uint2(bf2(v.x, v.y), bf2(v.z, v.w));
        ((uint2*)imgl)[i] = make_uint2(bf2(v.x - hx, v.y - hy), bf2(v.z - hz, v.w - hw));
    }
    __syncthreads();

    const int arow = lid & 15;
    const int acol = (lid & 16) ? 8 : 0;
    const int brow = (lid & 7) | ((lid & 16) >> 1);
    const int bcol = (lid & 8) ? 8 : 0;

    float acc[2][2][4];
#pragma unroll
    for (int mi = 0; mi < 2; ++mi)
#pragma unroll
        for (int ni = 0; ni < 2; ++ni)
#pragma unroll
            for (int q = 0; q < 4; ++q) acc[mi][ni][q] = 0.0f;

    for (int kc = 0; kc < 9; ++kc) {
#pragma unroll
        for (int h = 0; h < 16; ++h) {
            int idx = tid + h * 256;
            int p = idx >> 6, kk = idx & 63;
            int k = kc * 64 + kk;
            int ic = k / 9, r = k - ic * 9;
            int ky = r / 3, kx = r - ky * 3;
            unsigned short vh = 0, vl = 0;
            if (p < 49) {
                int oy = p / 7, ox = p - oy * 7;
                int s = ic * 81 + (oy + ky) * 9 + ox + kx;
                vh = imgh[s]; vl = imgl[s];
            }
            Ahs[p * PAD + kk] = vh;
            Als[p * PAD + kk] = vl;
        }
#pragma unroll
        for (int h = 0; h < 2; ++h) {
            int i = tid + h * 256;
            int row = i >> 3, c = i & 7;
            *(float4*)(smc + C3_BH + (row * PAD + c * 8) * 2) =
                *(const float4*)(wh + (size_t)row * 576 + kc * 64 + c * 8);
            *(float4*)(smc + C3_BL + (row * PAD + c * 8) * 2) =
                *(const float4*)(wl + (size_t)row * 576 + kc * 64 + c * 8);
        }
        __syncthreads();

#pragma unroll
        for (int ks = 0; ks < 4; ++ks) {
            const int k0 = ks * 16;
            uint32_t ah[2][4], al[2][4], bh[4], bl[4];
#pragma unroll
            for (int mi = 0; mi < 2; ++mi) {
                uint32_t ra = (uint32_t)((wm * 32 + mi * 16 + arow) * PAD + k0 + acol) * 2;
                ldsm_x4(ah[mi], sAh + ra);
                ldsm_x4(al[mi], sAl + ra);
            }
            {
                uint32_t rb = (uint32_t)((wn * 16 + brow) * PAD + k0 + bcol) * 2;
                ldsm_x4(bh, sBh + rb);
                ldsm_x4(bl, sBl + rb);
            }
#pragma unroll
            for (int mi = 0; mi < 2; ++mi)
#pragma unroll
                for (int ni = 0; ni < 2; ++ni) {
                    mma_bf16(acc[mi][ni], ah[mi], &bh[ni * 2]);
                    mma_bf16(acc[mi][ni], ah[mi], &bl[ni * 2]);
                    mma_bf16(acc[mi][ni], al[mi], &bh[ni * 2]);
                }
        }
        __syncthreads();
    }

    const int r = lid >> 2, c2 = (lid & 3) * 2;
    float* ob = out + (size_t)n * 3136;
#pragma unroll
    for (int mi = 0; mi < 2; ++mi)
#pragma unroll
        for (int ni = 0; ni < 2; ++ni) {
            int oc = wn * 16 + ni * 8 + c2;
            float b0 = sbias[oc], b1 = sbias[oc + 1];
            int p0 = wm * 32 + mi * 16 + r;
            if (p0 < 49) {
                ob[oc * 49 + p0]       = fmaxf(acc[mi][ni][0] + b0, 0.0f);
                ob[(oc + 1) * 49 + p0] = fmaxf(acc[mi][ni][1] + b1, 0.0f);
            }
            int p1 = p0 + 8;
            if (p1 < 49) {
                ob[oc * 49 + p1]       = fmaxf(acc[mi][ni][2] + b0, 0.0f);
                ob[(oc + 1) * 49 + p1] = fmaxf(acc[mi][ni][3] + b1, 0.0f);
            }
        }
}

// ============================================================
// LSTM recurrence [verified]
// ============================================================
#define LSTM_SMEM_BYTES (16 * 512 * 16 + 128 * 4 + 512 * 4)

__global__ void __launch_bounds__(512, 1)
lstm_kernel(const float* __restrict__ gx, const float* __restrict__ whh,
            const int* __restrict__ done, const float* __restrict__ h0,
            const float* __restrict__ c0, float* __restrict__ hid)
{
    extern __shared__ float sm[];
    float4* wp4  = (float4*)sm;
    float*  h_sh = sm + 16 * 512 * 4;
    float*  act  = h_sh + 128;

    const int env = blockIdx.x;
    const int j = threadIdx.x;

    const float* wrow = whh + (size_t)j * 128;
    float wreg[64];
#pragma unroll
    for (int k = 0; k < 64; k += 4) {
        float4 v = *(const float4*)(wrow + k);
        wreg[k] = v.x; wreg[k + 1] = v.y; wreg[k + 2] = v.z; wreg[k + 3] = v.w;
    }
#pragma unroll
    for (int kk = 0; kk < 16; ++kk)
        wp4[kk * 512 + j] = *(const float4*)(wrow + 64 + kk * 4);

    float c = 0.0f, hprev = 0.0f;
    if (j < 128) {
        hprev = h0[env * 128 + j];
        c     = c0[env * 128 + j];
    }
    __syncthreads();

    for (int t = 0; t < TT; ++t) {
        if (j < 128) {
            float m = 1.0f - (float)done[t * BB + env];
            h_sh[j] = hprev * m;
            c *= m;
        }
        __syncthreads();

        float accv = gx[((size_t)t * BB + env) * 512 + j];
#pragma unroll
        for (int k = 0; k < 64; k += 4) {
            float4 hv = *(const float4*)&h_sh[k];
            accv += hv.x * wreg[k] + hv.y * wreg[k + 1]
                  + hv.z * wreg[k + 2] + hv.w * wreg[k + 3];
        }
#pragma unroll
        for (int kk = 0; kk < 16; ++kk) {
            float4 wv = wp4[kk * 512 + j];
            float4 hv = *(const float4*)&h_sh[64 + kk * 4];
            accv += wv.x * hv.x + wv.y * hv.y + wv.z * hv.z + wv.w * hv.w;
        }

        float a;
        if (j < 256 || j >= 384) a = 1.0f / (1.0f + expf(-accv));
        else                     a = tanhf(accv);
        act[j] = a;
        __syncthreads();

        if (j < 128) {
            float ig = act[j],       fg = act[128 + j];
            float gg = act[256 + j], og = act[384 + j];
            c = fg * c + ig * gg;
            hprev = og * tanhf(c);
            hid[((size_t)t * BB + env) * 128 + j] = hprev;
        }
    }
}

// ============================================================
// heads [verified]
// ============================================================
__global__ void __launch_bounds__(304, 4)
heads_kernel(const float* __restrict__ hid, const float* __restrict__ wa,
             const float* __restrict__ ba, const float* __restrict__ wc,
             const float* __restrict__ bc, float* __restrict__ out)
{
    __shared__ float wsh[19 * 128];
    __shared__ float hsh[16 * 128];
    __shared__ float bsh[19];

    const int t = threadIdx.x;
    const int rb = blockIdx.x * 16;

    for (int i = t; i < 18 * 128; i += 304) wsh[i] = wa[i];
    for (int i = t; i < 128; i += 304)      wsh[18 * 128 + i] = wc[i];
    for (int i = t; i < 2048; i += 304)     hsh[i] = hid[(size_t)rb * 128 + i];
    if (t < 18) bsh[t] = ba[t];
    if (t == 18) bsh[18] = bc[0];
    __syncthreads();

    const int r = t / 19, cidx = t % 19;
    float accv = bsh[cidx];
    const float* hr = &hsh[r * 128];
    const float* wr = &wsh[cidx * 128];
#pragma unroll
    for (int k = 0; k < 128; k += 4) {
        float4 hv = *(const float4*)(hr + k);
        float4 wv = *(const float4*)(wr + k);
        accv += hv.x * wv.x + hv.y * wv.y + hv.z * wv.z + hv.w * wv.w;
    }
    out[(size_t)(rb + r) * OUTC + cidx] = accv;
}

// ============================================================
// host launcher
// ============================================================
extern "C" void kernel_launch(void* const* d_in, const int* in_sizes, int n_in,
                              void* d_out, int out_size)
{
    const float* x    = (const float*)d_in[0];
    const int*   done = (const int*)  d_in[1];
    const float* h0   = (const float*)d_in[2];
    const float* c0   = (const float*)d_in[3];
    const float* w1   = (const float*)d_in[4];
    const float* b1   = (const float*)d_in[5];
    const float* w2   = (const float*)d_in[6];
    const float* b2   = (const float*)d_in[7];
    const float* w3   = (const float*)d_in[8];
    const float* b3   = (const float*)d_in[9];
    const float* wf   = (const float*)d_in[10];
    const float* bf   = (const float*)d_in[11];
    const float* w_ih = (const float*)d_in[12];
    const float* w_hh = (const float*)d_in[13];
    const float* b_ih = (const float*)d_in[14];
    const float* b_hh = (const float*)d_in[15];
    const float* wa   = (const float*)d_in[16];
    const float* ba   = (const float*)d_in[17];
    const float* wc   = (const float*)d_in[18];
    const float* bc   = (const float*)d_in[19];
    float* out = (float*)d_out;

    float *c1, *c2, *c3, *feat, *gx, *hidp;
    cudaGetSymbolAddress((void**)&c1,   g_c1);
    cudaGetSymbolAddress((void**)&c2,   g_c2);
    cudaGetSymbolAddress((void**)&c3,   g_c3);
    cudaGetSymbolAddress((void**)&feat, g_feat);
    cudaGetSymbolAddress((void**)&gx,   g_gx);
    cudaGetSymbolAddress((void**)&hidp, g_hid);
    __nv_bfloat16 *w1h, *w1l, *w2h, *w2l, *w3h, *w3l;
    __nv_bfloat16 *a1h, *a1l, *b1h, *b1l, *a2h, *a2l, *b2h, *b2l;
    cudaGetSymbolAddress((void**)&w1h, g_w1h);
    cudaGetSymbolAddress((void**)&w1l, g_w1l);
    cudaGetSymbolAddress((void**)&w2h, g_w2h);
    cudaGetSymbolAddress((void**)&w2l, g_w2l);
    cudaGetSymbolAddress((void**)&w3h, g_w3h);
    cudaGetSymbolAddress((void**)&w3l, g_w3l);
    cudaGetSymbolAddress((void**)&a1h, g_a1h);
    cudaGetSymbolAddress((void**)&a1l, g_a1l);
    cudaGetSymbolAddress((void**)&b1h, g_b1h);
    cudaGetSymbolAddress((void**)&b1l, g_b1l);
    cudaGetSymbolAddress((void**)&a2h, g_a2h);
    cudaGetSymbolAddress((void**)&a2l, g_a2l);
    cudaGetSymbolAddress((void**)&b2h, g_b2h);
    cudaGetSymbolAddress((void**)&b2l, g_b2l);

    cudaFuncSetAttribute(conv1_mma_kernel, cudaFuncAttributeMaxDynamicSharedMemorySize, C1_SMEM);
    cudaFuncSetAttribute(conv2_mma_kernel, cudaFuncAttributeMaxDynamicSharedMemorySize, C2_SMEM);
    cudaFuncSetAttribute(conv3_mma_kernel, cudaFuncAttributeMaxDynamicSharedMemorySize, C3_SMEM);
    cudaFuncSetAttribute(lstm_kernel,  cudaFuncAttributeMaxDynamicSharedMemorySize, LSTM_SMEM_BYTES);
    cudaFuncSetAttribute(mma_gemm_kernel<true,  false>, cudaFuncAttributeMaxDynamicSharedMemorySize, MM_SMEM);
    cudaFuncSetAttribute(mma_gemm_kernel<false, true>,  cudaFuncAttributeMaxDynamicSharedMemorySize, MM_SMEM);

    // weight hi/lo converts (native row-major flattens; conv1 folds 1/255)
    convert_hl_kernel<<<32,   256>>>(w1,   w1h, w1l, 32 * 256,  1.0f / 255.0f);
    convert_hl_kernel<<<128,  256>>>(w2,   w2h, w2l, 64 * 512,  1.0f);
    convert_hl_kernel<<<144,  256>>>(w3,   w3h, w3l, 64 * 576,  1.0f);
    convert_hl_kernel<<<2048, 256>>>(wf,   b1h, b1l, FEAT * 3136, 1.0f);
    convert_hl_kernel<<<512,  256>>>(w_ih, b2h, b2l, FEAT * FEAT, 1.0f);

    conv1_mma_kernel<<<TB * 2, 256, C1_SMEM>>>(x, w1h, w1l, b1, c1);
    conv2_mma_kernel<<<TB, 256, C2_SMEM>>>(c1, w2h, w2l, b2, c2);
    conv3_mma_kernel<<<TB, 256, C3_SMEM>>>(c2, w3h, w3l, b3, c3);

    // feat = relu(c3 @ wf^T + bf)  via HMMA bf16-split (K=3136)
    convert_hl_kernel<<<4096, 256>>>(c3, a1h, a1l, TB * 3136, 1.0f);
    mma_gemm_kernel<true, false><<<dim3(FEAT / 64, TB / 128), 256, MM_SMEM>>>(
        a1h, a1l, b1h, b1l, bf, nullptr, feat, 3136, FEAT);

    // gx = feat @ w_ih^T + b_ih + b_hh  via HMMA bf16-split (K=512)
    convert_hl_kernel<<<2048, 256>>>(feat, a2h, a2l, TB * FEAT, 1.0f);
    mma_gemm_kernel<false, true><<<dim3(FEAT / 64, TB / 128), 256, MM_SMEM>>>(
        a2h, a2l, b2h, b2l, b_ih, b_hh, gx, FEAT, FEAT);

    lstm_kernel<<<BB, 512, LSTM_SMEM_BYTES>>>(gx, w_hh, done, h0, c0, hidp);

    heads_kernel<<<TB / 16, 304>>>(hidp, wa, ba, wc, bc, out);
}

// round 14
// speedup vs baseline: 1.6806x; 1.0475x over previous
#include <cuda_runtime.h>
#include <cuda_bf16.h>
#include <math.h>
#include <stdint.h>

// ---------------- problem constants ----------------
#define TT   128
#define BB   32
#define TB   (TT*BB)          // 4096
#define HID  128
#define FEAT 512
#define AA   18
#define OUTC (AA+1)           // 19

typedef unsigned long long u64;

// ---------------- HMMA helpers (base ISA: mma.sync + ldmatrix) ----------------
__device__ __forceinline__ uint32_t smem_u32(const void* p) {
    uint32_t a;
    asm("{ .reg .u64 t; cvta.to.shared.u64 t, %1; cvt.u32.u64 %0, t; }" : "=r"(a) : "l"(p));
    return a;
}
__device__ __forceinline__ void ldsm_x4(uint32_t* r, uint32_t addr) {
    asm volatile("ldmatrix.sync.aligned.m8n8.x4.shared.b16 {%0,%1,%2,%3}, [%4];"
        : "=r"(r[0]), "=r"(r[1]), "=r"(r[2]), "=r"(r[3]) : "r"(addr));
}
__device__ __forceinline__ void mma_bf16(float* d, const uint32_t* a, const uint32_t* b) {
    asm volatile("mma.sync.aligned.m16n8k16.row.col.f32.bf16.bf16.f32 "
        "{%0,%1,%2,%3}, {%4,%5,%6,%7}, {%8,%9}, {%0,%1,%2,%3};"
        : "+f"(d[0]), "+f"(d[1]), "+f"(d[2]), "+f"(d[3])
        : "r"(a[0]), "r"(a[1]), "r"(a[2]), "r"(a[3]), "r"(b[0]), "r"(b[1]));
}
__device__ __forceinline__ uint32_t bf2(float a, float b) {
    __nv_bfloat162 t = __floats2bfloat162_rn(a, b);
    return *(uint32_t*)&t;
}

// ---------------- scratch (static device allocations) ----------------
__device__ float g_c1[TB * 32 * 20 * 20];
__device__ float g_c2[TB * 64 * 9 * 9];
__device__ float g_c3[TB * 64 * 7 * 7];
__device__ float g_feat[TB * FEAT];
__device__ float g_gx[TB * 4 * HID];
__device__ float g_hid[TB * HID];
// bf16 hi/lo split operands (plain row-major)
__device__ __nv_bfloat16 g_w1h[32 * 256],  g_w1l[32 * 256];       // conv1 w (x 1/255)
__device__ __nv_bfloat16 g_w2h[64 * 512],  g_w2l[64 * 512];       // conv2 weights
__device__ __nv_bfloat16 g_w3h[64 * 576],  g_w3l[64 * 576];       // conv3 weights
__device__ __nv_bfloat16 g_a1h[TB * 3136], g_a1l[TB * 3136];      // c3
__device__ __nv_bfloat16 g_b1h[FEAT * 3136], g_b1l[FEAT * 3136];  // wf
__device__ __nv_bfloat16 g_a2h[TB * FEAT], g_a2l[TB * FEAT];      // feat
__device__ __nv_bfloat16 g_b2h[FEAT * FEAT], g_b2l[FEAT * FEAT];  // w_ih

// ============================================================
// hi/lo bf16 convert, plain row-major, optional scale
// ============================================================
__global__ void convert_hl_kernel(const float* __restrict__ src,
                                  __nv_bfloat16* __restrict__ hi,
                                  __nv_bfloat16* __restrict__ lo,
                                  int total, float scale)
{
    for (int i = blockIdx.x * 256 + threadIdx.x; i < total; i += gridDim.x * 256) {
        float v = src[i] * scale;
        __nv_bfloat16 h = __float2bfloat16(v);
        __nv_bfloat16 l = __float2bfloat16(v - __bfloat162float(h));
        hi[i] = h; lo[i] = l;
    }
}

// ============================================================
// HMMA bf16-split GEMM [R10, verified]: C = A@B^T + bias (+bias2)
// ============================================================
#define PAD 72
#define SM_GA   256
#define SM_GAL  (SM_GA  + 128 * PAD * 2)
#define SM_GBH  (SM_GAL + 128 * PAD * 2)
#define SM_GBL  (SM_GBH + 64 * PAD * 2)
#define MM_SMEM (SM_GBL + 64 * PAD * 2)

template <bool RELU, bool BIAS2>
__global__ void __launch_bounds__(256, 2)
mma_gemm_kernel(const __nv_bfloat16* __restrict__ Ah, const __nv_bfloat16* __restrict__ Al,
                const __nv_bfloat16* __restrict__ Bh, const __nv_bfloat16* __restrict__ Bl,
                const float* __restrict__ bias1, const float* __restrict__ bias2,
                float* __restrict__ C, int K, int Ntot)
{
    extern __shared__ char smc[];
    float* sbias = (float*)smc;
    const uint32_t sb = smem_u32(smc);
    const uint32_t sAh = sb + SM_GA,  sAl = sb + SM_GAL;
    const uint32_t sBh = sb + SM_GBH, sBl = sb + SM_GBL;

    const int tid = threadIdx.x, wid = tid >> 5, lid = tid & 31;
    const int bm = blockIdx.y * 128, bn = blockIdx.x * 64;
    const int wm = wid >> 2, wn = wid & 3;

    if (tid < 64) {
        float bv = bias1[bn + tid];
        if (BIAS2) bv += bias2[bn + tid];
        sbias[tid] = bv;
    }

    const int arow = lid & 15;
    const int acol = (lid & 16) ? 8 : 0;
    const int brow = (lid & 7) | ((lid & 16) >> 1);
    const int bcol = (lid & 8) ? 8 : 0;

    float acc[4][2][4];
#pragma unroll
    for (int mi = 0; mi < 4; ++mi)
#pragma unroll
        for (int ni = 0; ni < 2; ++ni)
#pragma unroll
            for (int q = 0; q < 4; ++q) acc[mi][ni][q] = 0.0f;

    for (int kb = 0; kb < K; kb += 64) {
        {
            char* base = smc;
#pragma unroll
            for (int h = 0; h < 4; ++h) {
                int i = tid + h * 256;
                int row = i >> 3, c = i & 7;
                *(float4*)(base + SM_GA + row * (PAD * 2) + c * 16) =
                    *(const float4*)(Ah + (size_t)(bm + row) * K + kb + c * 8);
            }
#pragma unroll
            for (int h = 0; h < 4; ++h) {
                int i = tid + h * 256;
                int row = i >> 3, c = i & 7;
                *(float4*)(base + SM_GAL + row * (PAD * 2) + c * 16) =
                    *(const float4*)(Al + (size_t)(bm + row) * K + kb + c * 8);
            }
#pragma unroll
            for (int h = 0; h < 2; ++h) {
                int i = tid + h * 256;
                int row = i >> 3, c = i & 7;
                *(float4*)(base + SM_GBH + row * (PAD * 2) + c * 16) =
                    *(const float4*)(Bh + (size_t)(bn + row) * K + kb + c * 8);
            }
#pragma unroll
            for (int h = 0; h < 2; ++h) {
                int i = tid + h * 256;
                int row = i >> 3, c = i & 7;
                *(float4*)(base + SM_GBL + row * (PAD * 2) + c * 16) =
                    *(const float4*)(Bl + (size_t)(bn + row) * K + kb + c * 8);
            }
        }
        __syncthreads();

#pragma unroll
        for (int ks = 0; ks < 4; ++ks) {
            const int k0 = ks * 16;
            uint32_t ah[4][4], al[4][4], bh[4], bl[4];
#pragma unroll
            for (int mi = 0; mi < 4; ++mi) {
                uint32_t ra = (uint32_t)((wm * 64 + mi * 16 + arow) * PAD + k0 + acol) * 2;
                ldsm_x4(ah[mi], sAh + ra);
                ldsm_x4(al[mi], sAl + ra);
            }
            {
                uint32_t rb = (uint32_t)((wn * 16 + brow) * PAD + k0 + bcol) * 2;
                ldsm_x4(bh, sBh + rb);
                ldsm_x4(bl, sBl + rb);
            }
#pragma unroll
            for (int mi = 0; mi < 4; ++mi)
#pragma unroll
                for (int ni = 0; ni < 2; ++ni) {
                    mma_bf16(acc[mi][ni], ah[mi], &bh[ni * 2]);
                    mma_bf16(acc[mi][ni], ah[mi], &bl[ni * 2]);
                    mma_bf16(acc[mi][ni], al[mi], &bh[ni * 2]);
                }
        }
        __syncthreads();
    }

    const int r = lid >> 2, c2 = (lid & 3) * 2;
#pragma unroll
    for (int mi = 0; mi < 4; ++mi)
#pragma unroll
        for (int ni = 0; ni < 2; ++ni) {
            int nloc = wn * 16 + ni * 8 + c2;
            float b0 = sbias[nloc], b1 = sbias[nloc + 1];
            int m0 = bm + wm * 64 + mi * 16 + r;
            float v0 = acc[mi][ni][0] + b0, v1 = acc[mi][ni][1] + b1;
            float v2 = acc[mi][ni][2] + b0, v3 = acc[mi][ni][3] + b1;
            if (RELU) {
                v0 = fmaxf(v0, 0.0f); v1 = fmaxf(v1, 0.0f);
                v2 = fmaxf(v2, 0.0f); v3 = fmaxf(v3, 0.0f);
            }
            *(float2*)(C + (size_t)m0 * Ntot + bn + nloc)       = make_float2(v0, v1);
            *(float2*)(C + (size_t)(m0 + 8) * Ntot + bn + nloc) = make_float2(v2, v3);
        }
}

// ============================================================
// conv1 via HMMA implicit GEMM, VECTORIZED im2col (uint2 = 4 bf16/copy).
// One CTA per HALF image. M=200(pad256) x N=32 x K=256.
// k = ic*64 + ky*8 + kx (native w1 flatten; 1/255 folded into weights).
// ============================================================
#define PAD1 40
#define C1_SBIAS 0
#define C1_IMGH  128
#define C1_IMGL  (C1_IMGH + 29568)          // 14784 shorts each
#define C1_AH    (C1_IMGL + 29568)          // 256*40 shorts
#define C1_AL    (C1_AH + 20480)
#define C1_BH    (C1_AL + 20480)            // 32*40 shorts
#define C1_BL    (C1_BH + 2560)
#define C1_SMEM  (C1_BL + 2560)             // 105344

__global__ void __launch_bounds__(256, 2)
conv1_mma_kernel(const float* __restrict__ x, const __nv_bfloat16* __restrict__ wh,
                 const __nv_bfloat16* __restrict__ wl, const float* __restrict__ b,
                 float* __restrict__ out)
{
    extern __shared__ char smc[];
    float* sbias = (float*)(smc + C1_SBIAS);
    unsigned short* imgh = (unsigned short*)(smc + C1_IMGH);
    unsigned short* imgl = (unsigned short*)(smc + C1_IMGL);
    unsigned short* Ahs  = (unsigned short*)(smc + C1_AH);
    unsigned short* Als  = (unsigned short*)(smc + C1_AL);
    const uint32_t sb = smem_u32(smc);
    const uint32_t sAh = sb + C1_AH, sAl = sb + C1_AL;
    const uint32_t sBh = sb + C1_BH, sBl = sb + C1_BL;

    const int tid = threadIdx.x, wid = tid >> 5, lid = tid & 31;
    const int n = blockIdx.x >> 1, half = blockIdx.x & 1;
    const int r0 = half * 40;
    const int wm = wid;

    if (tid < 32) sbias[tid] = b[tid];

    const float4* xg4 = (const float4*)(x + (size_t)n * 28224);
    for (int i = tid; i < 3696; i += 256) {
        int ch = i / 924, rr = i - ch * 924;
        float4 v = xg4[ch * 1764 + r0 * 21 + rr];
        float hx = __bfloat162float(__float2bfloat16(v.x));
        float hy = __bfloat162float(__float2bfloat16(v.y));
        float hz = __bfloat162float(__float2bfloat16(v.z));
        float hw = __bfloat162float(__float2bfloat16(v.w));
        ((uint2*)imgh)[i] = make_uint2(bf2(v.x, v.y), bf2(v.z, v.w));
        ((uint2*)imgl)[i] = make_uint2(bf2(v.x - hx, v.y - hy), bf2(v.z - hz, v.w - hw));
    }
    __syncthreads();

    // precompute per-thread (p, g) decomposition invariants
    const int arow = lid & 15;
    const int acol = (lid & 16) ? 8 : 0;
    const int brow = (lid & 7) | ((lid & 16) >> 1);
    const int bcol = (lid & 8) ? 8 : 0;

    float acc[2][4][4];
#pragma unroll
    for (int mi = 0; mi < 2; ++mi)
#pragma unroll
        for (int ni = 0; ni < 4; ++ni)
#pragma unroll
            for (int q = 0; q < 4; ++q) acc[mi][ni][q] = 0.0f;

    for (int kc = 0; kc < 8; ++kc) {
        // ---- im2col A tiles: 256 rows x 8 uint2-groups (4 bf16 each) ----
        const int icc = kc >> 1;                 // ic for this chunk
        const int kyb = (kc & 1) * 4;            // ky base (0 or 4)
#pragma unroll
        for (int h = 0; h < 8; ++h) {
            int idx = tid + h * 256;
            int p = idx >> 3, g = idx & 7;       // g: ky off = g>>1, kx0 = (g&1)*4
            int ky = kyb + (g >> 1), kx0 = (g & 1) * 4;
            uint2 vh = make_uint2(0u, 0u), vl = make_uint2(0u, 0u);
            if (p < 200) {
                int oy = p / 20, ox = p - oy * 20;
                int s = icc * 3696 + (oy * 4 + ky) * 84 + ox * 4 + kx0;
                vh = *(const uint2*)(imgh + s);
                vl = *(const uint2*)(imgl + s);
            }
            *(uint2*)(Ahs + p * PAD1 + g * 4) = vh;
            *(uint2*)(Als + p * PAD1 + g * 4) = vl;
        }
        // ---- B tiles (32 x 32): tid<128 hi, else lo ----
        {
            int i = tid & 127;
            int row = i >> 2, c = i & 3;
            const __nv_bfloat16* wsrc = (tid < 128) ? wh : wl;
            char* wdst = smc + ((tid < 128) ? C1_BH : C1_BL);
            *(float4*)(wdst + (row * PAD1 + c * 8) * 2) =
                *(const float4*)(wsrc + (size_t)row * 256 + kc * 32 + c * 8);
        }
        __syncthreads();

#pragma unroll
        for (int ks = 0; ks < 2; ++ks) {
            const int k0 = ks * 16;
            uint32_t ah[2][4], al[2][4], bh[2][4], bl[2][4];
#pragma unroll
            for (int mi = 0; mi < 2; ++mi) {
                uint32_t ra = (uint32_t)((wm * 32 + mi * 16 + arow) * PAD1 + k0 + acol) * 2;
                ldsm_x4(ah[mi], sAh + ra);
                ldsm_x4(al[mi], sAl + ra);
            }
#pragma unroll
            for (int g = 0; g < 2; ++g) {
                uint32_t rb = (uint32_t)((g * 16 + brow) * PAD1 + k0 + bcol) * 2;
                ldsm_x4(bh[g], sBh + rb);
                ldsm_x4(bl[g], sBl + rb);
            }
#pragma unroll
            for (int mi = 0; mi < 2; ++mi)
#pragma unroll
                for (int ni = 0; ni < 4; ++ni) {
                    int g = ni >> 1, j = (ni & 1) * 2;
                    mma_bf16(acc[mi][ni], ah[mi], &bh[g][j]);
                    mma_bf16(acc[mi][ni], ah[mi], &bl[g][j]);
                    mma_bf16(acc[mi][ni], al[mi], &bh[g][j]);
                }
        }
        __syncthreads();
    }

    const int r = lid >> 2, c2 = (lid & 3) * 2;
    float* ob = out + (size_t)n * 12800 + half * 200;
#pragma unroll
    for (int mi = 0; mi < 2; ++mi)
#pragma unroll
        for (int ni = 0; ni < 4; ++ni) {
            int oc = ni * 8 + c2;
            float b0 = sbias[oc], b1 = sbias[oc + 1];
            int p0 = wm * 32 + mi * 16 + r;
            if (p0 < 200) {
                ob[oc * 400 + p0]       = fmaxf(acc[mi][ni][0] + b0, 0.0f);
                ob[(oc + 1) * 400 + p0] = fmaxf(acc[mi][ni][1] + b1, 0.0f);
            }
            int p1 = p0 + 8;
            if (p1 < 200) {
                ob[oc * 400 + p1]       = fmaxf(acc[mi][ni][2] + b0, 0.0f);
                ob[(oc + 1) * 400 + p1] = fmaxf(acc[mi][ni][3] + b1, 0.0f);
            }
        }
}

// ============================================================
// conv2 via HMMA implicit GEMM, uint-vectorized im2col (2 bf16/copy)
// ============================================================
#define C2_SBIAS 0
#define C2_IMGH  256
#define C2_IMGL  (C2_IMGH + 25600)
#define C2_AH    (C2_IMGL + 25600)
#define C2_AL    (C2_AH + 13824)
#define C2_BH    (C2_AL + 13824)
#define C2_BL    (C2_BH + 9216)
#define C2_SMEM  (C2_BL + 9216)

__global__ void __launch_bounds__(256, 2)
conv2_mma_kernel(const float* __restrict__ in, const __nv_bfloat16* __restrict__ wh,
                 const __nv_bfloat16* __restrict__ wl, const float* __restrict__ b,
                 float* __restrict__ out)
{
    extern __shared__ char smc[];
    float* sbias = (float*)(smc + C2_SBIAS);
    unsigned short* imgh = (unsigned short*)(smc + C2_IMGH);
    unsigned short* imgl = (unsigned short*)(smc + C2_IMGL);
    unsigned short* Ahs  = (unsigned short*)(smc + C2_AH);
    unsigned short* Als  = (unsigned short*)(smc + C2_AL);
    const uint32_t sb = smem_u32(smc);
    const uint32_t sAh = sb + C2_AH, sAl = sb + C2_AL;
    const uint32_t sBh = sb + C2_BH, sBl = sb + C2_BL;

    const int tid = threadIdx.x, wid = tid >> 5, lid = tid & 31;
    const int n = blockIdx.x;
    const int wm = wid >> 2, wn = wid & 3;

    if (tid < 64) sbias[tid] = b[tid];

    const float4* ig = (const float4*)(in + (size_t)n * 12800);
    for (int i = tid; i < 3200; i += 256) {
        float4 v = ig[i];
        float hx = __bfloat162float(__float2bfloat16(v.x));
        float hy = __bfloat162float(__float2bfloat16(v.y));
        float hz = __bfloat162float(__float2bfloat16(v.z));
        float hw = __bfloat162float(__float2bfloat16(v.w));
        ((uint2*)imgh)[i] = make_uint2(bf2(v.x, v.y), bf2(v.z, v.w));
        ((uint2*)imgl)[i] = make_uint2(bf2(v.x - hx, v.y - hy), bf2(v.z - hz, v.w - hw));
    }
    __syncthreads();

    const int arow = lid & 15;
    const int acol = (lid & 16) ? 8 : 0;
    const int brow = (lid & 7) | ((lid & 16) >> 1);
    const int bcol = (lid & 8) ? 8 : 0;

    float acc[3][2][4];
#pragma unroll
    for (int mi = 0; mi < 3; ++mi)
#pragma unroll
        for (int ni = 0; ni < 2; ++ni)
#pragma unroll
            for (int q = 0; q < 4; ++q) acc[mi][ni][q] = 0.0f;

    for (int kc = 0; kc < 8; ++kc) {
        // im2col A: 96 rows x 32 uint-groups (2 bf16 each) = 3072
#pragma unroll
        for (int h = 0; h < 12; ++h) {
            int idx = tid + h * 256;
            int p = idx >> 5, g = idx & 31;
            int k0 = kc * 64 + g * 2;
            int ic = k0 >> 4, rr = k0 & 15, ky = rr >> 2, kx0 = rr & 3;
            unsigned int vh = 0u, vl = 0u;
            if (p < 81) {
                int oy = p / 9, ox = p - oy * 9;
                int s = ic * 400 + (oy * 2 + ky) * 20 + ox * 2 + kx0;
                vh = *(const unsigned int*)(imgh + s);
                vl = *(const unsigned int*)(imgl + s);
            }
            *(unsigned int*)(Ahs + p * PAD + g * 2) = vh;
            *(unsigned int*)(Als + p * PAD + g * 2) = vl;
        }
#pragma unroll
        for (int h = 0; h < 2; ++h) {
            int i = tid + h * 256;
            int row = i >> 3, c = i & 7;
            *(float4*)(smc + C2_BH + (row * PAD + c * 8) * 2) =
                *(const float4*)(wh + (size_t)row * 512 + kc * 64 + c * 8);
            *(float4*)(smc + C2_BL + (row * PAD + c * 8) * 2) =
                *(const float4*)(wl + (size_t)row * 512 + kc * 64 + c * 8);
        }
        __syncthreads();

#pragma unroll
        for (int ks = 0; ks < 4; ++ks) {
            const int k0 = ks * 16;
            uint32_t ah[3][4], al[3][4], bh[4], bl[4];
#pragma unroll
            for (int mi = 0; mi < 3; ++mi) {
                uint32_t ra = (uint32_t)((wm * 48 + mi * 16 + arow) * PAD + k0 + acol) * 2;
                ldsm_x4(ah[mi], sAh + ra);
                ldsm_x4(al[mi], sAl + ra);
            }
            {
                uint32_t rb = (uint32_t)((wn * 16 + brow) * PAD + k0 + bcol) * 2;
                ldsm_x4(bh, sBh + rb);
                ldsm_x4(bl, sBl + rb);
            }
#pragma unroll
            for (int mi = 0; mi < 3; ++mi)
#pragma unroll
                for (int ni = 0; ni < 2; ++ni) {
                    mma_bf16(acc[mi][ni], ah[mi], &bh[ni * 2]);
                    mma_bf16(acc[mi][ni], ah[mi], &bl[ni * 2]);
                    mma_bf16(acc[mi][ni], al[mi], &bh[ni * 2]);
                }
        }
        __syncthreads();
    }

    const int r = lid >> 2, c2 = (lid & 3) * 2;
    float* ob = out + (size_t)n * 5184;
#pragma unroll
    for (int mi = 0; mi < 3; ++mi)
#pragma unroll
        for (int ni = 0; ni < 2; ++ni) {
            int oc = wn * 16 + ni * 8 + c2;
            float b0 = sbias[oc], b1 = sbias[oc + 1];
            int p0 = wm * 48 + mi * 16 + r;
            if (p0 < 81) {
                ob[oc * 81 + p0]       = fmaxf(acc[mi][ni][0] + b0, 0.0f);
                ob[(oc + 1) * 81 + p0] = fmaxf(acc[mi][ni][1] + b1, 0.0f);
            }
            int p1 = p0 + 8;
            if (p1 < 81) {
                ob[oc * 81 + p1]       = fmaxf(acc[mi][ni][2] + b0, 0.0f);
                ob[(oc + 1) * 81 + p1] = fmaxf(acc[mi][ni][3] + b1, 0.0f);
            }
        }
}

// ============================================================
// conv3 via HMMA implicit GEMM [R12, verified]
// ============================================================
#define C3_SBIAS 0
#define C3_IMGH  256
#define C3_IMGL  (C3_IMGH + 10368)
#define C3_AH    (C3_IMGL + 10368)
#define C3_AL    (C3_AH + 9216)
#define C3_BH    (C3_AL + 9216)
#define C3_BL    (C3_BH + 9216)
#define C3_SMEM  (C3_BL + 9216)

__global__ void __launch_bounds__(256, 3)
conv3_mma_kernel(const float* __restrict__ in, const __nv_bfloat16* __restrict__ wh,
                 const __nv_bfloat16* __restrict__ wl, const float* __restrict__ b,
                 float* __restrict__ out)
{
    extern __shared__ char smc[];
    float* sbias = (float*)(smc + C3_SBIAS);
    unsigned short* imgh = (unsigned short*)(smc + C3_IMGH);
    unsigned short* imgl = (unsigned short*)(smc + C3_IMGL);
    unsigned short* Ahs  = (unsigned short*)(smc + C3_AH);
    unsigned short* Als  = (unsigned short*)(smc + C3_AL);
    const uint32_t sb = smem_u32(smc);
    const uint32_t sAh = sb + C3_AH, sAl = sb + C3_AL;
    const uint32_t sBh = sb + C3_BH, sBl = sb + C3_BL;

    const int tid = threadIdx.x, wid = tid >> 5, lid = tid & 31;
    const int n = blockIdx.x;
    const int wm = wid >> 2, wn = wid & 3;

    if (tid < 64) sbias[tid] = b[tid];

    const float4* ig = (const float4*)(in + (size_t)n * 5184);
    for (int i = tid; i < 1296; i += 256) {
        float4 v = ig[i];
        float hx = __bfloat162float(__float2bfloat16(v.x));
        float hy = __bfloat162float(__float2bfloat16(v.y));
        float hz = __bfloat162float(__float2bfloat16(v.z));
        float hw = __bfloat162float(__float2bfloat16(v.w));
        ((uint2*)imgh)[i] = make_uint2(bf2(v.x, v.y), bf2(v.z, v.w));
        ((uint2*)imgl)[i] = make_uint2(bf2(v.x - hx, v.y - hy), bf2(v.z - hz, v.w - hw));
    }
    __syncthreads();

    const int arow = lid & 15;
    const int acol = (lid & 16) ? 8 : 0;
    const int brow = (lid & 7) | ((lid & 16) >> 1);
    const int bcol = (lid & 8) ? 8 : 0;

    float acc[2][2][4];
#pragma unroll
    for (int mi = 0; mi < 2; ++mi)
#pragma unroll
        for (int ni = 0; ni < 2; ++ni)
#pragma unroll
            for (int q = 0; q < 4; ++q) acc[mi][ni][q] = 0.0f;

    for (int kc = 0; kc < 9; ++kc) {
#pragma unroll
        for (int h = 0; h < 16; ++h) {
            int idx = tid + h * 256;
            int p = idx >> 6, kk = idx & 63;
            int k = kc * 64 + kk;
            int ic = k / 9, r = k - ic * 9;
            int ky = r / 3, kx = r - ky * 3;
            unsigned short vh = 0, vl = 0;
            if (p < 49) {
                int oy = p / 7, ox = p - oy * 7;
                int s = ic * 81 + (oy + ky) * 9 + ox + kx;
                vh = imgh[s]; vl = imgl[s];
            }
            Ahs[p * PAD + kk] = vh;
            Als[p * PAD + kk] = vl;
        }
#pragma unroll
        for (int h = 0; h < 2; ++h) {
            int i = tid + h * 256;
            int row = i >> 3, c = i & 7;
            *(float4*)(smc + C3_BH + (row * PAD + c * 8) * 2) =
                *(const float4*)(wh + (size_t)row * 576 + kc * 64 + c * 8);
            *(float4*)(smc + C3_BL + (row * PAD + c * 8) * 2) =
                *(const float4*)(wl + (size_t)row * 576 + kc * 64 + c * 8);
        }
        __syncthreads();

#pragma unroll
        for (int ks = 0; ks < 4; ++ks) {
            const int k0 = ks * 16;
            uint32_t ah[2][4], al[2][4], bh[4], bl[4];
#pragma unroll
            for (int mi = 0; mi < 2; ++mi) {
                uint32_t ra = (uint32_t)((wm * 32 + mi * 16 + arow) * PAD + k0 + acol) * 2;
                ldsm_x4(ah[mi], sAh + ra);
                ldsm_x4(al[mi], sAl + ra);
            }
            {
                uint32_t rb = (uint32_t)((wn * 16 + brow) * PAD + k0 + bcol) * 2;
                ldsm_x4(bh, sBh + rb);
                ldsm_x4(bl, sBl + rb);
            }
#pragma unroll
            for (int mi = 0; mi < 2; ++mi)
#pragma unroll
                for (int ni = 0; ni < 2; ++ni) {
                    mma_bf16(acc[mi][ni], ah[mi], &bh[ni * 2]);
                    mma_bf16(acc[mi][ni], ah[mi], &bl[ni * 2]);
                    mma_bf16(acc[mi][ni], al[mi], &bh[ni * 2]);
                }
        }
        __syncthreads();
    }

    const int r = lid >> 2, c2 = (lid & 3) * 2;
    float* ob = out + (size_t)n * 3136;
#pragma unroll
    for (int mi = 0; mi < 2; ++mi)
#pragma unroll
        for (int ni = 0; ni < 2; ++ni) {
            int oc = wn * 16 + ni * 8 + c2;
            float b0 = sbias[oc], b1 = sbias[oc + 1];
            int p0 = wm * 32 + mi * 16 + r;
            if (p0 < 49) {
                ob[oc * 49 + p0]       = fmaxf(acc[mi][ni][0] + b0, 0.0f);
                ob[(oc + 1) * 49 + p0] = fmaxf(acc[mi][ni][1] + b1, 0.0f);
            }
            int p1 = p0 + 8;
            if (p1 < 49) {
                ob[oc * 49 + p1]       = fmaxf(acc[mi][ni][2] + b0, 0.0f);
                ob[(oc + 1) * 49 + p1] = fmaxf(acc[mi][ni][3] + b1, 0.0f);
            }
        }
}

// ============================================================
// LSTM recurrence [verified]
// ============================================================
#define LSTM_SMEM_BYTES (16 * 512 * 16 + 128 * 4 + 512 * 4)

__global__ void __launch_bounds__(512, 1)
lstm_kernel(const float* __restrict__ gx, const float* __restrict__ whh,
            const int* __restrict__ done, const float* __restrict__ h0,
            const float* __restrict__ c0, float* __restrict__ hid)
{
    extern __shared__ float sm[];
    float4* wp4  = (float4*)sm;
    float*  h_sh = sm + 16 * 512 * 4;
    float*  act  = h_sh + 128;

    const int env = blockIdx.x;
    const int j = threadIdx.x;

    const float* wrow = whh + (size_t)j * 128;
    float wreg[64];
#pragma unroll
    for (int k = 0; k < 64; k += 4) {
        float4 v = *(const float4*)(wrow + k);
        wreg[k] = v.x; wreg[k + 1] = v.y; wreg[k + 2] = v.z; wreg[k + 3] = v.w;
    }
#pragma unroll
    for (int kk = 0; kk < 16; ++kk)
        wp4[kk * 512 + j] = *(const float4*)(wrow + 64 + kk * 4);

    float c = 0.0f, hprev = 0.0f;
    if (j < 128) {
        hprev = h0[env * 128 + j];
        c     = c0[env * 128 + j];
    }
    __syncthreads();

    for (int t = 0; t < TT; ++t) {
        if (j < 128) {
            float m = 1.0f - (float)done[t * BB + env];
            h_sh[j] = hprev * m;
            c *= m;
        }
        __syncthreads();

        float accv = gx[((size_t)t * BB + env) * 512 + j];
#pragma unroll
        for (int k = 0; k < 64; k += 4) {
            float4 hv = *(const float4*)&h_sh[k];
            accv += hv.x * wreg[k] + hv.y * wreg[k + 1]
                  + hv.z * wreg[k + 2] + hv.w * wreg[k + 3];
        }
#pragma unroll
        for (int kk = 0; kk < 16; ++kk) {
            float4 wv = wp4[kk * 512 + j];
            float4 hv = *(const float4*)&h_sh[64 + kk * 4];
            accv += wv.x * hv.x + wv.y * hv.y + wv.z * hv.z + wv.w * hv.w;
        }

        float a;
        if (j < 256 || j >= 384) a = 1.0f / (1.0f + expf(-accv));
        else                     a = tanhf(accv);
        act[j] = a;
        __syncthreads();

        if (j < 128) {
            float ig = act[j],       fg = act[128 + j];
            float gg = act[256 + j], og = act[384 + j];
            c = fg * c + ig * gg;
            hprev = og * tanhf(c);
            hid[((size_t)t * BB + env) * 128 + j] = hprev;
        }
    }
}

// ============================================================
// heads [verified]
// ============================================================
__global__ void __launch_bounds__(304, 4)
heads_kernel(const float* __restrict__ hid, const float* __restrict__ wa,
             const float* __restrict__ ba, const float* __restrict__ wc,
             const float* __restrict__ bc, float* __restrict__ out)
{
    __shared__ float wsh[19 * 128];
    __shared__ float hsh[16 * 128];
    __shared__ float bsh[19];

    const int t = threadIdx.x;
    const int rb = blockIdx.x * 16;

    for (int i = t; i < 18 * 128; i += 304) wsh[i] = wa[i];
    for (int i = t; i < 128; i += 304)      wsh[18 * 128 + i] = wc[i];
    for (int i = t; i < 2048; i += 304)     hsh[i] = hid[(size_t)rb * 128 + i];
    if (t < 18) bsh[t] = ba[t];
    if (t == 18) bsh[18] = bc[0];
    __syncthreads();

    const int r = t / 19, cidx = t % 19;
    float accv = bsh[cidx];
    const float* hr = &hsh[r * 128];
    const float* wr = &wsh[cidx * 128];
#pragma unroll
    for (int k = 0; k < 128; k += 4) {
        float4 hv = *(const float4*)(hr + k);
        float4 wv = *(const float4*)(wr + k);
        accv += hv.x * wv.x + hv.y * wv.y + hv.z * wv.z + hv.w * wv.w;
    }
    out[(size_t)(rb + r) * OUTC + cidx] = accv;
}

// ============================================================
// host launcher
// ============================================================
extern "C" void kernel_launch(void* const* d_in, const int* in_sizes, int n_in,
                              void* d_out, int out_size)
{
    const float* x    = (const float*)d_in[0];
    const int*   done = (const int*)  d_in[1];
    const float* h0   = (const float*)d_in[2];
    const float* c0   = (const float*)d_in[3];
    const float* w1   = (const float*)d_in[4];
    const float* b1   = (const float*)d_in[5];
    const float* w2   = (const float*)d_in[6];
    const float* b2   = (const float*)d_in[7];
    const float* w3   = (const float*)d_in[8];
    const float* b3   = (const float*)d_in[9];
    const float* wf   = (const float*)d_in[10];
    const float* bf   = (const float*)d_in[11];
    const float* w_ih = (const float*)d_in[12];
    const float* w_hh = (const float*)d_in[13];
    const float* b_ih = (const float*)d_in[14];
    const float* b_hh = (const float*)d_in[15];
    const float* wa   = (const float*)d_in[16];
    const float* ba   = (const float*)d_in[17];
    const float* wc   = (const float*)d_in[18];
    const float* bc   = (const float*)d_in[19];
    float* out = (float*)d_out;

    float *c1, *c2, *c3, *feat, *gx, *hidp;
    cudaGetSymbolAddress((void**)&c1,   g_c1);
    cudaGetSymbolAddress((void**)&c2,   g_c2);
    cudaGetSymbolAddress((void**)&c3,   g_c3);
    cudaGetSymbolAddress((void**)&feat, g_feat);
    cudaGetSymbolAddress((void**)&gx,   g_gx);
    cudaGetSymbolAddress((void**)&hidp, g_hid);
    __nv_bfloat16 *w1h, *w1l, *w2h, *w2l, *w3h, *w3l;
    __nv_bfloat16 *a1h, *a1l, *b1h, *b1l, *a2h, *a2l, *b2h, *b2l;
    cudaGetSymbolAddress((void**)&w1h, g_w1h);
    cudaGetSymbolAddress((void**)&w1l, g_w1l);
    cudaGetSymbolAddress((void**)&w2h, g_w2h);
    cudaGetSymbolAddress((void**)&w2l, g_w2l);
    cudaGetSymbolAddress((void**)&w3h, g_w3h);
    cudaGetSymbolAddress((void**)&w3l, g_w3l);
    cudaGetSymbolAddress((void**)&a1h, g_a1h);
    cudaGetSymbolAddress((void**)&a1l, g_a1l);
    cudaGetSymbolAddress((void**)&b1h, g_b1h);
    cudaGetSymbolAddress((void**)&b1l, g_b1l);
    cudaGetSymbolAddress((void**)&a2h, g_a2h);
    cudaGetSymbolAddress((void**)&a2l, g_a2l);
    cudaGetSymbolAddress((void**)&b2h, g_b2h);
    cudaGetSymbolAddress((void**)&b2l, g_b2l);

    cudaFuncSetAttribute(conv1_mma_kernel, cudaFuncAttributeMaxDynamicSharedMemorySize, C1_SMEM);
    cudaFuncSetAttribute(conv2_mma_kernel, cudaFuncAttributeMaxDynamicSharedMemorySize, C2_SMEM);
    cudaFuncSetAttribute(conv3_mma_kernel, cudaFuncAttributeMaxDynamicSharedMemorySize, C3_SMEM);
    cudaFuncSetAttribute(lstm_kernel,  cudaFuncAttributeMaxDynamicSharedMemorySize, LSTM_SMEM_BYTES);
    cudaFuncSetAttribute(mma_gemm_kernel<true,  false>, cudaFuncAttributeMaxDynamicSharedMemorySize, MM_SMEM);
    cudaFuncSetAttribute(mma_gemm_kernel<false, true>,  cudaFuncAttributeMaxDynamicSharedMemorySize, MM_SMEM);

    convert_hl_kernel<<<32,   256>>>(w1,   w1h, w1l, 32 * 256,  1.0f / 255.0f);
    convert_hl_kernel<<<128,  256>>>(w2,   w2h, w2l, 64 * 512,  1.0f);
    convert_hl_kernel<<<144,  256>>>(w3,   w3h, w3l, 64 * 576,  1.0f);
    convert_hl_kernel<<<2048, 256>>>(wf,   b1h, b1l, FEAT * 3136, 1.0f);
    convert_hl_kernel<<<512,  256>>>(w_ih, b2h, b2l, FEAT * FEAT, 1.0f);

    conv1_mma_kernel<<<TB * 2, 256, C1_SMEM>>>(x, w1h, w1l, b1, c1);
    conv2_mma_kernel<<<TB, 256, C2_SMEM>>>(c1, w2h, w2l, b2, c2);
    conv3_mma_kernel<<<TB, 256, C3_SMEM>>>(c2, w3h, w3l, b3, c3);

    convert_hl_kernel<<<4096, 256>>>(c3, a1h, a1l, TB * 3136, 1.0f);
    mma_gemm_kernel<true, false><<<dim3(FEAT / 64, TB / 128), 256, MM_SMEM>>>(
        a1h, a1l, b1h, b1l, bf, nullptr, feat, 3136, FEAT);

    convert_hl_kernel<<<2048, 256>>>(feat, a2h, a2l, TB * FEAT, 1.0f);
    mma_gemm_kernel<false, true><<<dim3(FEAT / 64, TB / 128), 256, MM_SMEM>>>(
        a2h, a2l, b2h, b2l, b_ih, b_hh, gx, FEAT, FEAT);

    lstm_kernel<<<BB, 512, LSTM_SMEM_BYTES>>>(gx, w_hh, done, h0, c0, hidp);

    heads_kernel<<<TB / 16, 304>>>(hidp, wa, ba, wc, bc, out);
}

// round 15
// speedup vs baseline: 1.7033x; 1.0135x over previous
#include <cuda_runtime.h>
#include <cuda_bf16.h>
#include <math.h>
#include <stdint.h>

// ---------------- problem constants ----------------
#define TT   128
#define BB   32
#define TB   (TT*BB)          // 4096
#define HID  128
#define FEAT 512
#define AA   18
#define OUTC (AA+1)           // 19

typedef unsigned long long u64;

// ---------------- HMMA helpers (base ISA: mma.sync + ldmatrix) ----------------
__device__ __forceinline__ uint32_t smem_u32(const void* p) {
    uint32_t a;
    asm("{ .reg .u64 t; cvta.to.shared.u64 t, %1; cvt.u32.u64 %0, t; }" : "=r"(a) : "l"(p));
    return a;
}
__device__ __forceinline__ void ldsm_x4(uint32_t* r, uint32_t addr) {
    asm volatile("ldmatrix.sync.aligned.m8n8.x4.shared.b16 {%0,%1,%2,%3}, [%4];"
        : "=r"(r[0]), "=r"(r[1]), "=r"(r[2]), "=r"(r[3]) : "r"(addr));
}
__device__ __forceinline__ void mma_bf16(float* d, const uint32_t* a, const uint32_t* b) {
    asm volatile("mma.sync.aligned.m16n8k16.row.col.f32.bf16.bf16.f32 "
        "{%0,%1,%2,%3}, {%4,%5,%6,%7}, {%8,%9}, {%0,%1,%2,%3};"
        : "+f"(d[0]), "+f"(d[1]), "+f"(d[2]), "+f"(d[3])
        : "r"(a[0]), "r"(a[1]), "r"(a[2]), "r"(a[3]), "r"(b[0]), "r"(b[1]));
}
__device__ __forceinline__ uint32_t bf2(float a, float b) {
    __nv_bfloat162 t = __floats2bfloat162_rn(a, b);
    return *(uint32_t*)&t;
}
__device__ __forceinline__ void hl_split(float v, __nv_bfloat16& h, __nv_bfloat16& l) {
    h = __float2bfloat16(v);
    l = __float2bfloat16(v - __bfloat162float(h));
}

// ---------------- scratch (static device allocations) ----------------
__device__ float g_feat[TB * FEAT];
__device__ float g_gx[TB * 4 * HID];
__device__ float g_hid[TB * HID];
// activations as bf16 hi/lo planes (numerically identical to fp32->split)
__device__ __nv_bfloat16 g_c1h[TB * 12800], g_c1l[TB * 12800];
__device__ __nv_bfloat16 g_c2h[TB * 5184],  g_c2l[TB * 5184];
// bf16 hi/lo split operands (plain row-major)
__device__ __nv_bfloat16 g_w1h[32 * 256],  g_w1l[32 * 256];       // conv1 w (x 1/255)
__device__ __nv_bfloat16 g_w2h[64 * 512],  g_w2l[64 * 512];
__device__ __nv_bfloat16 g_w3h[64 * 576],  g_w3l[64 * 576];
__device__ __nv_bfloat16 g_a1h[TB * 3136], g_a1l[TB * 3136];      // c3 (written by conv3)
__device__ __nv_bfloat16 g_b1h[FEAT * 3136], g_b1l[FEAT * 3136];  // wf
__device__ __nv_bfloat16 g_a2h[TB * FEAT], g_a2l[TB * FEAT];      // feat
__device__ __nv_bfloat16 g_b2h[FEAT * FEAT], g_b2l[FEAT * FEAT];  // w_ih

// ============================================================
// hi/lo bf16 convert, plain row-major, optional scale
// ============================================================
__global__ void convert_hl_kernel(const float* __restrict__ src,
                                  __nv_bfloat16* __restrict__ hi,
                                  __nv_bfloat16* __restrict__ lo,
                                  int total, float scale)
{
    for (int i = blockIdx.x * 256 + threadIdx.x; i < total; i += gridDim.x * 256) {
        float v = src[i] * scale;
        __nv_bfloat16 h, l;
        hl_split(v, h, l);
        hi[i] = h; lo[i] = l;
    }
}

// ============================================================
// HMMA bf16-split GEMM [R10, verified]: C = A@B^T + bias (+bias2)
// ============================================================
#define PAD 72
#define SM_GA   256
#define SM_GAL  (SM_GA  + 128 * PAD * 2)
#define SM_GBH  (SM_GAL + 128 * PAD * 2)
#define SM_GBL  (SM_GBH + 64 * PAD * 2)
#define MM_SMEM (SM_GBL + 64 * PAD * 2)

template <bool RELU, bool BIAS2>
__global__ void __launch_bounds__(256, 2)
mma_gemm_kernel(const __nv_bfloat16* __restrict__ Ah, const __nv_bfloat16* __restrict__ Al,
                const __nv_bfloat16* __restrict__ Bh, const __nv_bfloat16* __restrict__ Bl,
                const float* __restrict__ bias1, const float* __restrict__ bias2,
                float* __restrict__ C, int K, int Ntot)
{
    extern __shared__ char smc[];
    float* sbias = (float*)smc;
    const uint32_t sb = smem_u32(smc);
    const uint32_t sAh = sb + SM_GA,  sAl = sb + SM_GAL;
    const uint32_t sBh = sb + SM_GBH, sBl = sb + SM_GBL;

    const int tid = threadIdx.x, wid = tid >> 5, lid = tid & 31;
    const int bm = blockIdx.y * 128, bn = blockIdx.x * 64;
    const int wm = wid >> 2, wn = wid & 3;

    if (tid < 64) {
        float bv = bias1[bn + tid];
        if (BIAS2) bv += bias2[bn + tid];
        sbias[tid] = bv;
    }

    const int arow = lid & 15;
    const int acol = (lid & 16) ? 8 : 0;
    const int brow = (lid & 7) | ((lid & 16) >> 1);
    const int bcol = (lid & 8) ? 8 : 0;

    float acc[4][2][4];
#pragma unroll
    for (int mi = 0; mi < 4; ++mi)
#pragma unroll
        for (int ni = 0; ni < 2; ++ni)
#pragma unroll
            for (int q = 0; q < 4; ++q) acc[mi][ni][q] = 0.0f;

    for (int kb = 0; kb < K; kb += 64) {
        {
            char* base = smc;
#pragma unroll
            for (int h = 0; h < 4; ++h) {
                int i = tid + h * 256;
                int row = i >> 3, c = i & 7;
                *(float4*)(base + SM_GA + row * (PAD * 2) + c * 16) =
                    *(const float4*)(Ah + (size_t)(bm + row) * K + kb + c * 8);
            }
#pragma unroll
            for (int h = 0; h < 4; ++h) {
                int i = tid + h * 256;
                int row = i >> 3, c = i & 7;
                *(float4*)(base + SM_GAL + row * (PAD * 2) + c * 16) =
                    *(const float4*)(Al + (size_t)(bm + row) * K + kb + c * 8);
            }
#pragma unroll
            for (int h = 0; h < 2; ++h) {
                int i = tid + h * 256;
                int row = i >> 3, c = i & 7;
                *(float4*)(base + SM_GBH + row * (PAD * 2) + c * 16) =
                    *(const float4*)(Bh + (size_t)(bn + row) * K + kb + c * 8);
            }
#pragma unroll
            for (int h = 0; h < 2; ++h) {
                int i = tid + h * 256;
                int row = i >> 3, c = i & 7;
                *(float4*)(base + SM_GBL + row * (PAD * 2) + c * 16) =
                    *(const float4*)(Bl + (size_t)(bn + row) * K + kb + c * 8);
            }
        }
        __syncthreads();

#pragma unroll
        for (int ks = 0; ks < 4; ++ks) {
            const int k0 = ks * 16;
            uint32_t ah[4][4], al[4][4], bh[4], bl[4];
#pragma unroll
            for (int mi = 0; mi < 4; ++mi) {
                uint32_t ra = (uint32_t)((wm * 64 + mi * 16 + arow) * PAD + k0 + acol) * 2;
                ldsm_x4(ah[mi], sAh + ra);
                ldsm_x4(al[mi], sAl + ra);
            }
            {
                uint32_t rb = (uint32_t)((wn * 16 + brow) * PAD + k0 + bcol) * 2;
                ldsm_x4(bh, sBh + rb);
                ldsm_x4(bl, sBl + rb);
            }
#pragma unroll
            for (int mi = 0; mi < 4; ++mi)
#pragma unroll
                for (int ni = 0; ni < 2; ++ni) {
                    mma_bf16(acc[mi][ni], ah[mi], &bh[ni * 2]);
                    mma_bf16(acc[mi][ni], ah[mi], &bl[ni * 2]);
                    mma_bf16(acc[mi][ni], al[mi], &bh[ni * 2]);
                }
        }
        __syncthreads();
    }

    const int r = lid >> 2, c2 = (lid & 3) * 2;
#pragma unroll
    for (int mi = 0; mi < 4; ++mi)
#pragma unroll
        for (int ni = 0; ni < 2; ++ni) {
            int nloc = wn * 16 + ni * 8 + c2;
            float b0 = sbias[nloc], b1 = sbias[nloc + 1];
            int m0 = bm + wm * 64 + mi * 16 + r;
            float v0 = acc[mi][ni][0] + b0, v1 = acc[mi][ni][1] + b1;
            float v2 = acc[mi][ni][2] + b0, v3 = acc[mi][ni][3] + b1;
            if (RELU) {
                v0 = fmaxf(v0, 0.0f); v1 = fmaxf(v1, 0.0f);
                v2 = fmaxf(v2, 0.0f); v3 = fmaxf(v3, 0.0f);
            }
            *(float2*)(C + (size_t)m0 * Ntot + bn + nloc)       = make_float2(v0, v1);
            *(float2*)(C + (size_t)(m0 + 8) * Ntot + bn + nloc) = make_float2(v2, v3);
        }
}

// ============================================================
// conv1 via HMMA implicit GEMM (vectorized im2col, dead-warp trimmed).
// One CTA per HALF image. M=200(pad224 live) x N=32 x K=256.
// Outputs bf16 hi/lo planes (identical numerics to fp32 + later split).
// ============================================================
#define PAD1 40
#define C1_SBIAS 0
#define C1_IMGH  128
#define C1_IMGL  (C1_IMGH + 29568)
#define C1_AH    (C1_IMGL + 29568)          // 256*40 shorts
#define C1_AL    (C1_AH + 20480)
#define C1_BH    (C1_AL + 20480)
#define C1_BL    (C1_BH + 2560)
#define C1_SMEM  (C1_BL + 2560)             // 105344

__global__ void __launch_bounds__(256, 2)
conv1_mma_kernel(const float* __restrict__ x, const __nv_bfloat16* __restrict__ wh,
                 const __nv_bfloat16* __restrict__ wl, const float* __restrict__ b,
                 __nv_bfloat16* __restrict__ outh, __nv_bfloat16* __restrict__ outl)
{
    extern __shared__ char smc[];
    float* sbias = (float*)(smc + C1_SBIAS);
    unsigned short* imgh = (unsigned short*)(smc + C1_IMGH);
    unsigned short* imgl = (unsigned short*)(smc + C1_IMGL);
    unsigned short* Ahs  = (unsigned short*)(smc + C1_AH);
    unsigned short* Als  = (unsigned short*)(smc + C1_AL);
    const uint32_t sb = smem_u32(smc);
    const uint32_t sAh = sb + C1_AH, sAl = sb + C1_AL;
    const uint32_t sBh = sb + C1_BH, sBl = sb + C1_BL;

    const int tid = threadIdx.x, wid = tid >> 5, lid = tid & 31;
    const int n = blockIdx.x >> 1, half = blockIdx.x & 1;
    const int r0 = half * 40;
    const int wm = wid;

    if (tid < 32) sbias[tid] = b[tid];

    const float4* xg4 = (const float4*)(x + (size_t)n * 28224);
    for (int i = tid; i < 3696; i += 256) {
        int ch = i / 924, rr = i - ch * 924;
        float4 v = xg4[ch * 1764 + r0 * 21 + rr];
        float hx = __bfloat162float(__float2bfloat16(v.x));
        float hy = __bfloat162float(__float2bfloat16(v.y));
        float hz = __bfloat162float(__float2bfloat16(v.z));
        float hw = __bfloat162float(__float2bfloat16(v.w));
        ((uint2*)imgh)[i] = make_uint2(bf2(v.x, v.y), bf2(v.z, v.w));
        ((uint2*)imgl)[i] = make_uint2(bf2(v.x - hx, v.y - hy), bf2(v.z - hz, v.w - hw));
    }
    __syncthreads();

    const int arow = lid & 15;
    const int acol = (lid & 16) ? 8 : 0;
    const int brow = (lid & 7) | ((lid & 16) >> 1);
    const int bcol = (lid & 8) ? 8 : 0;

    float acc[2][4][4];
#pragma unroll
    for (int mi = 0; mi < 2; ++mi)
#pragma unroll
        for (int ni = 0; ni < 4; ++ni)
#pragma unroll
            for (int q = 0; q < 4; ++q) acc[mi][ni][q] = 0.0f;

    for (int kc = 0; kc < 8; ++kc) {
        const int icc = kc >> 1;
        const int kyb = (kc & 1) * 4;
        // im2col: rows [0,224) only (rows 224-255 belong to dead warp 7)
#pragma unroll
        for (int h = 0; h < 7; ++h) {
            int idx = tid + h * 256;
            int p = idx >> 3, g = idx & 7;
            int ky = kyb + (g >> 1), kx0 = (g & 1) * 4;
            uint2 vh = make_uint2(0u, 0u), vl = make_uint2(0u, 0u);
            if (p < 200) {
                int oy = p / 20, ox = p - oy * 20;
                int s = icc * 3696 + (oy * 4 + ky) * 84 + ox * 4 + kx0;
                vh = *(const uint2*)(imgh + s);
                vl = *(const uint2*)(imgl + s);
            }
            *(uint2*)(Ahs + p * PAD1 + g * 4) = vh;
            *(uint2*)(Als + p * PAD1 + g * 4) = vl;
        }
        {
            int i = tid & 127;
            int row = i >> 2, c = i & 3;
            const __nv_bfloat16* wsrc = (tid < 128) ? wh : wl;
            char* wdst = smc + ((tid < 128) ? C1_BH : C1_BL);
            *(float4*)(wdst + (row * PAD1 + c * 8) * 2) =
                *(const float4*)(wsrc + (size_t)row * 256 + kc * 32 + c * 8);
        }
        __syncthreads();

        if (wm < 7) {     // warp 7 covers rows 224-255: all dead
#pragma unroll
            for (int ks = 0; ks < 2; ++ks) {
                const int k0 = ks * 16;
                uint32_t ah[2][4], al[2][4], bh[2][4], bl[2][4];
#pragma unroll
                for (int mi = 0; mi < 2; ++mi) {
                    uint32_t ra = (uint32_t)((wm * 32 + mi * 16 + arow) * PAD1 + k0 + acol) * 2;
                    ldsm_x4(ah[mi], sAh + ra);
                    ldsm_x4(al[mi], sAl + ra);
                }
#pragma unroll
                for (int g = 0; g < 2; ++g) {
                    uint32_t rb = (uint32_t)((g * 16 + brow) * PAD1 + k0 + bcol) * 2;
                    ldsm_x4(bh[g], sBh + rb);
                    ldsm_x4(bl[g], sBl + rb);
                }
#pragma unroll
                for (int mi = 0; mi < 2; ++mi)
#pragma unroll
                    for (int ni = 0; ni < 4; ++ni) {
                        int g = ni >> 1, j = (ni & 1) * 2;
                        mma_bf16(acc[mi][ni], ah[mi], &bh[g][j]);
                        mma_bf16(acc[mi][ni], ah[mi], &bl[g][j]);
                        mma_bf16(acc[mi][ni], al[mi], &bh[g][j]);
                    }
            }
        }
        __syncthreads();
    }

    if (wm < 7) {
        const int r = lid >> 2, c2 = (lid & 3) * 2;
        size_t obase = (size_t)n * 12800 + half * 200;
#pragma unroll
        for (int mi = 0; mi < 2; ++mi)
#pragma unroll
            for (int ni = 0; ni < 4; ++ni) {
                int oc = ni * 8 + c2;
                float b0 = sbias[oc], b1 = sbias[oc + 1];
                int p0 = wm * 32 + mi * 16 + r;
#pragma unroll
                for (int hh = 0; hh < 2; ++hh) {
                    int p = p0 + hh * 8;
                    if (p < 200) {
                        float v0 = fmaxf(acc[mi][ni][hh * 2 + 0] + b0, 0.0f);
                        float v1 = fmaxf(acc[mi][ni][hh * 2 + 1] + b1, 0.0f);
                        __nv_bfloat16 h0, l0, h1, l1;
                        hl_split(v0, h0, l0);
                        hl_split(v1, h1, l1);
                        outh[obase + (size_t)oc * 400 + p]       = h0;
                        outl[obase + (size_t)oc * 400 + p]       = l0;
                        outh[obase + (size_t)(oc + 1) * 400 + p] = h1;
                        outl[obase + (size_t)(oc + 1) * 400 + p] = l1;
                    }
                }
            }
    }
}

// ============================================================
// conv2: input already bf16 hi/lo planes -> pure uint4 copies.
// Outputs bf16 hi/lo planes.
// ============================================================
#define C2_SBIAS 0
#define C2_IMGH  256
#define C2_IMGL  (C2_IMGH + 25600)
#define C2_AH    (C2_IMGL + 25600)
#define C2_AL    (C2_AH + 13824)
#define C2_BH    (C2_AL + 13824)
#define C2_BL    (C2_BH + 9216)
#define C2_SMEM  (C2_BL + 9216)

__global__ void __launch_bounds__(256, 2)
conv2_mma_kernel(const __nv_bfloat16* __restrict__ inh, const __nv_bfloat16* __restrict__ inl,
                 const __nv_bfloat16* __restrict__ wh,  const __nv_bfloat16* __restrict__ wl,
                 const float* __restrict__ b,
                 __nv_bfloat16* __restrict__ outh, __nv_bfloat16* __restrict__ outl)
{
    extern __shared__ char smc[];
    float* sbias = (float*)(smc + C2_SBIAS);
    unsigned short* imgh = (unsigned short*)(smc + C2_IMGH);
    unsigned short* imgl = (unsigned short*)(smc + C2_IMGL);
    unsigned short* Ahs  = (unsigned short*)(smc + C2_AH);
    unsigned short* Als  = (unsigned short*)(smc + C2_AL);
    const uint32_t sb = smem_u32(smc);
    const uint32_t sAh = sb + C2_AH, sAl = sb + C2_AL;
    const uint32_t sBh = sb + C2_BH, sBl = sb + C2_BL;

    const int tid = threadIdx.x, wid = tid >> 5, lid = tid & 31;
    const int n = blockIdx.x;
    const int wm = wid >> 2, wn = wid & 3;

    if (tid < 64) sbias[tid] = b[tid];

    const uint4* ih4 = (const uint4*)(inh + (size_t)n * 12800);
    const uint4* il4 = (const uint4*)(inl + (size_t)n * 12800);
    for (int i = tid; i < 1600; i += 256) {
        ((uint4*)imgh)[i] = ih4[i];
        ((uint4*)imgl)[i] = il4[i];
    }
    __syncthreads();

    const int arow = lid & 15;
    const int acol = (lid & 16) ? 8 : 0;
    const int brow = (lid & 7) | ((lid & 16) >> 1);
    const int bcol = (lid & 8) ? 8 : 0;

    float acc[3][2][4];
#pragma unroll
    for (int mi = 0; mi < 3; ++mi)
#pragma unroll
        for (int ni = 0; ni < 2; ++ni)
#pragma unroll
            for (int q = 0; q < 4; ++q) acc[mi][ni][q] = 0.0f;

    for (int kc = 0; kc < 8; ++kc) {
#pragma unroll
        for (int h = 0; h < 12; ++h) {
            int idx = tid + h * 256;
            int p = idx >> 5, g = idx & 31;
            int k0 = kc * 64 + g * 2;
            int ic = k0 >> 4, rr = k0 & 15, ky = rr >> 2, kx0 = rr & 3;
            unsigned int vh = 0u, vl = 0u;
            if (p < 81) {
                int oy = p / 9, ox = p - oy * 9;
                int s = ic * 400 + (oy * 2 + ky) * 20 + ox * 2 + kx0;
                vh = *(const unsigned int*)(imgh + s);
                vl = *(const unsigned int*)(imgl + s);
            }
            *(unsigned int*)(Ahs + p * PAD + g * 2) = vh;
            *(unsigned int*)(Als + p * PAD + g * 2) = vl;
        }
#pragma unroll
        for (int h = 0; h < 2; ++h) {
            int i = tid + h * 256;
            int row = i >> 3, c = i & 7;
            *(float4*)(smc + C2_BH + (row * PAD + c * 8) * 2) =
                *(const float4*)(wh + (size_t)row * 512 + kc * 64 + c * 8);
            *(float4*)(smc + C2_BL + (row * PAD + c * 8) * 2) =
                *(const float4*)(wl + (size_t)row * 512 + kc * 64 + c * 8);
        }
        __syncthreads();

#pragma unroll
        for (int ks = 0; ks < 4; ++ks) {
            const int k0 = ks * 16;
            uint32_t ah[3][4], al[3][4], bh[4], bl[4];
#pragma unroll
            for (int mi = 0; mi < 3; ++mi) {
                uint32_t ra = (uint32_t)((wm * 48 + mi * 16 + arow) * PAD + k0 + acol) * 2;
                ldsm_x4(ah[mi], sAh + ra);
                ldsm_x4(al[mi], sAl + ra);
            }
            {
                uint32_t rb = (uint32_t)((wn * 16 + brow) * PAD + k0 + bcol) * 2;
                ldsm_x4(bh, sBh + rb);
                ldsm_x4(bl, sBl + rb);
            }
#pragma unroll
            for (int mi = 0; mi < 3; ++mi)
#pragma unroll
                for (int ni = 0; ni < 2; ++ni) {
                    mma_bf16(acc[mi][ni], ah[mi], &bh[ni * 2]);
                    mma_bf16(acc[mi][ni], ah[mi], &bl[ni * 2]);
                    mma_bf16(acc[mi][ni], al[mi], &bh[ni * 2]);
                }
        }
        __syncthreads();
    }

    const int r = lid >> 2, c2 = (lid & 3) * 2;
    size_t obase = (size_t)n * 5184;
#pragma unroll
    for (int mi = 0; mi < 3; ++mi)
#pragma unroll
        for (int ni = 0; ni < 2; ++ni) {
            int oc = wn * 16 + ni * 8 + c2;
            float b0 = sbias[oc], b1 = sbias[oc + 1];
            int p0 = wm * 48 + mi * 16 + r;
#pragma unroll
            for (int hh = 0; hh < 2; ++hh) {
                int p = p0 + hh * 8;
                if (p < 81) {
                    float v0 = fmaxf(acc[mi][ni][hh * 2 + 0] + b0, 0.0f);
                    float v1 = fmaxf(acc[mi][ni][hh * 2 + 1] + b1, 0.0f);
                    __nv_bfloat16 h0, l0, h1, l1;
                    hl_split(v0, h0, l0);
                    hl_split(v1, h1, l1);
                    outh[obase + (size_t)oc * 81 + p]       = h0;
                    outl[obase + (size_t)oc * 81 + p]       = l0;
                    outh[obase + (size_t)(oc + 1) * 81 + p] = h1;
                    outl[obase + (size_t)(oc + 1) * 81 + p] = l1;
                }
            }
        }
}

// ============================================================
// conv3: bf16 hi/lo input; writes FC A-operand (a1h/a1l) directly.
// ============================================================
#define C3_SBIAS 0
#define C3_IMGH  256
#define C3_IMGL  (C3_IMGH + 10368)
#define C3_AH    (C3_IMGL + 10368)
#define C3_AL    (C3_AH + 9216)
#define C3_BH    (C3_AL + 9216)
#define C3_BL    (C3_BH + 9216)
#define C3_SMEM  (C3_BL + 9216)

__global__ void __launch_bounds__(256, 3)
conv3_mma_kernel(const __nv_bfloat16* __restrict__ inh, const __nv_bfloat16* __restrict__ inl,
                 const __nv_bfloat16* __restrict__ wh,  const __nv_bfloat16* __restrict__ wl,
                 const float* __restrict__ b,
                 __nv_bfloat16* __restrict__ outh, __nv_bfloat16* __restrict__ outl)
{
    extern __shared__ char smc[];
    float* sbias = (float*)(smc + C3_SBIAS);
    unsigned short* imgh = (unsigned short*)(smc + C3_IMGH);
    unsigned short* imgl = (unsigned short*)(smc + C3_IMGL);
    unsigned short* Ahs  = (unsigned short*)(smc + C3_AH);
    unsigned short* Als  = (unsigned short*)(smc + C3_AL);
    const uint32_t sb = smem_u32(smc);
    const uint32_t sAh = sb + C3_AH, sAl = sb + C3_AL;
    const uint32_t sBh = sb + C3_BH, sBl = sb + C3_BL;

    const int tid = threadIdx.x, wid = tid >> 5, lid = tid & 31;
    const int n = blockIdx.x;
    const int wm = wid >> 2, wn = wid & 3;

    if (tid < 64) sbias[tid] = b[tid];

    const uint4* ih4 = (const uint4*)(inh + (size_t)n * 5184);
    const uint4* il4 = (const uint4*)(inl + (size_t)n * 5184);
    for (int i = tid; i < 648; i += 256) {
        ((uint4*)imgh)[i] = ih4[i];
        ((uint4*)imgl)[i] = il4[i];
    }
    __syncthreads();

    const int arow = lid & 15;
    const int acol = (lid & 16) ? 8 : 0;
    const int brow = (lid & 7) | ((lid & 16) >> 1);
    const int bcol = (lid & 8) ? 8 : 0;

    float acc[2][2][4];
#pragma unroll
    for (int mi = 0; mi < 2; ++mi)
#pragma unroll
        for (int ni = 0; ni < 2; ++ni)
#pragma unroll
            for (int q = 0; q < 4; ++q) acc[mi][ni][q] = 0.0f;

    for (int kc = 0; kc < 9; ++kc) {
#pragma unroll
        for (int h = 0; h < 16; ++h) {
            int idx = tid + h * 256;
            int p = idx >> 6, kk = idx & 63;
            int k = kc * 64 + kk;
            int ic = k / 9, r = k - ic * 9;
            int ky = r / 3, kx = r - ky * 3;
            unsigned short vh = 0, vl = 0;
            if (p < 49) {
                int oy = p / 7, ox = p - oy * 7;
                int s = ic * 81 + (oy + ky) * 9 + ox + kx;
                vh = imgh[s]; vl = imgl[s];
            }
            Ahs[p * PAD + kk] = vh;
            Als[p * PAD + kk] = vl;
        }
#pragma unroll
        for (int h = 0; h < 2; ++h) {
            int i = tid + h * 256;
            int row = i >> 3, c = i & 7;
            *(float4*)(smc + C3_BH + (row * PAD + c * 8) * 2) =
                *(const float4*)(wh + (size_t)row * 576 + kc * 64 + c * 8);
            *(float4*)(smc + C3_BL + (row * PAD + c * 8) * 2) =
                *(const float4*)(wl + (size_t)row * 576 + kc * 64 + c * 8);
        }
        __syncthreads();

#pragma unroll
        for (int ks = 0; ks < 4; ++ks) {
            const int k0 = ks * 16;
            uint32_t ah[2][4], al[2][4], bh[4], bl[4];
#pragma unroll
            for (int mi = 0; mi < 2; ++mi) {
                uint32_t ra = (uint32_t)((wm * 32 + mi * 16 + arow) * PAD + k0 + acol) * 2;
                ldsm_x4(ah[mi], sAh + ra);
                ldsm_x4(al[mi], sAl + ra);
            }
            {
                uint32_t rb = (uint32_t)((wn * 16 + brow) * PAD + k0 + bcol) * 2;
                ldsm_x4(bh, sBh + rb);
                ldsm_x4(bl, sBl + rb);
            }
#pragma unroll
            for (int mi = 0; mi < 2; ++mi)
#pragma unroll
                for (int ni = 0; ni < 2; ++ni) {
                    mma_bf16(acc[mi][ni], ah[mi], &bh[ni * 2]);
                    mma_bf16(acc[mi][ni], ah[mi], &bl[ni * 2]);
                    mma_bf16(acc[mi][ni], al[mi], &bh[ni * 2]);
                }
        }
        __syncthreads();
    }

    // epilogue: write FC A operand rows (n, k = oc*49 + p), hi/lo split
    const int r = lid >> 2, c2 = (lid & 3) * 2;
    size_t obase = (size_t)n * 3136;
#pragma unroll
    for (int mi = 0; mi < 2; ++mi)
#pragma unroll
        for (int ni = 0; ni < 2; ++ni) {
            int oc = wn * 16 + ni * 8 + c2;
            float b0 = sbias[oc], b1 = sbias[oc + 1];
            int p0 = wm * 32 + mi * 16 + r;
#pragma unroll
            for (int hh = 0; hh < 2; ++hh) {
                int p = p0 + hh * 8;
                if (p < 49) {
                    float v0 = fmaxf(acc[mi][ni][hh * 2 + 0] + b0, 0.0f);
                    float v1 = fmaxf(acc[mi][ni][hh * 2 + 1] + b1, 0.0f);
                    __nv_bfloat16 h0, l0, h1, l1;
                    hl_split(v0, h0, l0);
                    hl_split(v1, h1, l1);
                    outh[obase + (size_t)oc * 49 + p]       = h0;
                    outl[obase + (size_t)oc * 49 + p]       = l0;
                    outh[obase + (size_t)(oc + 1) * 49 + p] = h1;
                    outl[obase + (size_t)(oc + 1) * 49 + p] = l1;
                }
            }
        }
}

// ============================================================
// LSTM recurrence [verified] + gx prefetch (hides the 577cyc LDG)
// ============================================================
#define LSTM_SMEM_BYTES (16 * 512 * 16 + 128 * 4 + 512 * 4)

__global__ void __launch_bounds__(512, 1)
lstm_kernel(const float* __restrict__ gx, const float* __restrict__ whh,
            const int* __restrict__ done, const float* __restrict__ h0,
            const float* __restrict__ c0, float* __restrict__ hid)
{
    extern __shared__ float sm[];
    float4* wp4  = (float4*)sm;
    float*  h_sh = sm + 16 * 512 * 4;
    float*  act  = h_sh + 128;

    const int env = blockIdx.x;
    const int j = threadIdx.x;

    const float* wrow = whh + (size_t)j * 128;
    float wreg[64];
#pragma unroll
    for (int k = 0; k < 64; k += 4) {
        float4 v = *(const float4*)(wrow + k);
        wreg[k] = v.x; wreg[k + 1] = v.y; wreg[k + 2] = v.z; wreg[k + 3] = v.w;
    }
#pragma unroll
    for (int kk = 0; kk < 16; ++kk)
        wp4[kk * 512 + j] = *(const float4*)(wrow + 64 + kk * 4);

    float c = 0.0f, hprev = 0.0f;
    if (j < 128) {
        hprev = h0[env * 128 + j];
        c     = c0[env * 128 + j];
    }
    float gnext = gx[(size_t)env * 512 + j];      // t = 0
    __syncthreads();

    for (int t = 0; t < TT; ++t) {
        if (j < 128) {
            float m = 1.0f - (float)done[t * BB + env];
            h_sh[j] = hprev * m;
            c *= m;
        }
        __syncthreads();

        float accv = gnext;
        if (t + 1 < TT)                            // prefetch next step's gx
            gnext = gx[((size_t)(t + 1) * BB + env) * 512 + j];

#pragma unroll
        for (int k = 0; k < 64; k += 4) {
            float4 hv = *(const float4*)&h_sh[k];
            accv += hv.x * wreg[k] + hv.y * wreg[k + 1]
                  + hv.z * wreg[k + 2] + hv.w * wreg[k + 3];
        }
#pragma unroll
        for (int kk = 0; kk < 16; ++kk) {
            float4 wv = wp4[kk * 512 + j];
            float4 hv = *(const float4*)&h_sh[64 + kk * 4];
            accv += wv.x * hv.x + wv.y * hv.y + wv.z * hv.z + wv.w * hv.w;
        }

        float a;
        if (j < 256 || j >= 384) a = 1.0f / (1.0f + expf(-accv));
        else                     a = tanhf(accv);
        act[j] = a;
        __syncthreads();

        if (j < 128) {
            float ig = act[j],       fg = act[128 + j];
            float gg = act[256 + j], og = act[384 + j];
            c = fg * c + ig * gg;
            hprev = og * tanhf(c);
            hid[((size_t)t * BB + env) * 128 + j] = hprev;
        }
    }
}

// ============================================================
// heads [verified]
// ============================================================
__global__ void __launch_bounds__(304, 4)
heads_kernel(const float* __restrict__ hid, const float* __restrict__ wa,
             const float* __restrict__ ba, const float* __restrict__ wc,
             const float* __restrict__ bc, float* __restrict__ out)
{
    __shared__ float wsh[19 * 128];
    __shared__ float hsh[16 * 128];
    __shared__ float bsh[19];

    const int t = threadIdx.x;
    const int rb = blockIdx.x * 16;

    for (int i = t; i < 18 * 128; i += 304) wsh[i] = wa[i];
    for (int i = t; i < 128; i += 304)      wsh[18 * 128 + i] = wc[i];
    for (int i = t; i < 2048; i += 304)     hsh[i] = hid[(size_t)rb * 128 + i];
    if (t < 18) bsh[t] = ba[t];
    if (t == 18) bsh[18] = bc[0];
    __syncthreads();

    const int r = t / 19, cidx = t % 19;
    float accv = bsh[cidx];
    const float* hr = &hsh[r * 128];
    const float* wr = &wsh[cidx * 128];
#pragma unroll
    for (int k = 0; k < 128; k += 4) {
        float4 hv = *(const float4*)(hr + k);
        float4 wv = *(const float4*)(wr + k);
        accv += hv.x * wv.x + hv.y * wv.y + hv.z * wv.z + hv.w * wv.w;
    }
    out[(size_t)(rb + r) * OUTC + cidx] = accv;
}

// ============================================================
// host launcher
// ============================================================
extern "C" void kernel_launch(void* const* d_in, const int* in_sizes, int n_in,
                              void* d_out, int out_size)
{
    const float* x    = (const float*)d_in[0];
    const int*   done = (const int*)  d_in[1];
    const float* h0   = (const float*)d_in[2];
    const float* c0   = (const float*)d_in[3];
    const float* w1   = (const float*)d_in[4];
    const float* b1   = (const float*)d_in[5];
    const float* w2   = (const float*)d_in[6];
    const float* b2   = (const float*)d_in[7];
    const float* w3   = (const float*)d_in[8];
    const float* b3   = (const float*)d_in[9];
    const float* wf   = (const float*)d_in[10];
    const float* bf   = (const float*)d_in[11];
    const float* w_ih = (const float*)d_in[12];
    const float* w_hh = (const float*)d_in[13];
    const float* b_ih = (const float*)d_in[14];
    const float* b_hh = (const float*)d_in[15];
    const float* wa   = (const float*)d_in[16];
    const float* ba   = (const float*)d_in[17];
    const float* wc   = (const float*)d_in[18];
    const float* bc   = (const float*)d_in[19];
    float* out = (float*)d_out;

    float *feat, *gx, *hidp;
    cudaGetSymbolAddress((void**)&feat, g_feat);
    cudaGetSymbolAddress((void**)&gx,   g_gx);
    cudaGetSymbolAddress((void**)&hidp, g_hid);
    __nv_bfloat16 *c1h, *c1l, *c2h, *c2l;
    __nv_bfloat16 *w1h, *w1l, *w2h, *w2l, *w3h, *w3l;
    __nv_bfloat16 *a1h, *a1l, *b1h, *b1l, *a2h, *a2l, *b2h, *b2l;
    cudaGetSymbolAddress((void**)&c1h, g_c1h);
    cudaGetSymbolAddress((void**)&c1l, g_c1l);
    cudaGetSymbolAddress((void**)&c2h, g_c2h);
    cudaGetSymbolAddress((void**)&c2l, g_c2l);
    cudaGetSymbolAddress((void**)&w1h, g_w1h);
    cudaGetSymbolAddress((void**)&w1l, g_w1l);
    cudaGetSymbolAddress((void**)&w2h, g_w2h);
    cudaGetSymbolAddress((void**)&w2l, g_w2l);
    cudaGetSymbolAddress((void**)&w3h, g_w3h);
    cudaGetSymbolAddress((void**)&w3l, g_w3l);
    cudaGetSymbolAddress((void**)&a1h, g_a1h);
    cudaGetSymbolAddress((void**)&a1l, g_a1l);
    cudaGetSymbolAddress((void**)&b1h, g_b1h);
    cudaGetSymbolAddress((void**)&b1l, g_b1l);
    cudaGetSymbolAddress((void**)&a2h, g_a2h);
    cudaGetSymbolAddress((void**)&a2l, g_a2l);
    cudaGetSymbolAddress((void**)&b2h, g_b2h);
    cudaGetSymbolAddress((void**)&b2l, g_b2l);

    cudaFuncSetAttribute(conv1_mma_kernel, cudaFuncAttributeMaxDynamicSharedMemorySize, C1_SMEM);
    cudaFuncSetAttribute(conv2_mma_kernel, cudaFuncAttributeMaxDynamicSharedMemorySize, C2_SMEM);
    cudaFuncSetAttribute(conv3_mma_kernel, cudaFuncAttributeMaxDynamicSharedMemorySize, C3_SMEM);
    cudaFuncSetAttribute(lstm_kernel,  cudaFuncAttributeMaxDynamicSharedMemorySize, LSTM_SMEM_BYTES);
    cudaFuncSetAttribute(mma_gemm_kernel<true,  false>, cudaFuncAttributeMaxDynamicSharedMemorySize, MM_SMEM);
    cudaFuncSetAttribute(mma_gemm_kernel<false, true>,  cudaFuncAttributeMaxDynamicSharedMemorySize, MM_SMEM);

    convert_hl_kernel<<<32,   256>>>(w1,   w1h, w1l, 32 * 256,  1.0f / 255.0f);
    convert_hl_kernel<<<128,  256>>>(w2,   w2h, w2l, 64 * 512,  1.0f);
    convert_hl_kernel<<<144,  256>>>(w3,   w3h, w3l, 64 * 576,  1.0f);
    convert_hl_kernel<<<2048, 256>>>(wf,   b1h, b1l, FEAT * 3136, 1.0f);
    convert_hl_kernel<<<512,  256>>>(w_ih, b2h, b2l, FEAT * FEAT, 1.0f);

    conv1_mma_kernel<<<TB * 2, 256, C1_SMEM>>>(x, w1h, w1l, b1, c1h, c1l);
    conv2_mma_kernel<<<TB, 256, C2_SMEM>>>(c1h, c1l, w2h, w2l, b2, c2h, c2l);
    conv3_mma_kernel<<<TB, 256, C3_SMEM>>>(c2h, c2l, w3h, w3l, b3, a1h, a1l);

    // feat = relu(c3 @ wf^T + bf)  via HMMA bf16-split (K=3136)
    mma_gemm_kernel<true, false><<<dim3(FEAT / 64, TB / 128), 256, MM_SMEM>>>(
        a1h, a1l, b1h, b1l, bf, nullptr, feat, 3136, FEAT);

    // gx = feat @ w_ih^T + b_ih + b_hh  via HMMA bf16-split (K=512)
    convert_hl_kernel<<<2048, 256>>>(feat, a2h, a2l, TB * FEAT, 1.0f);
    mma_gemm_kernel<false, true><<<dim3(FEAT / 64, TB / 128), 256, MM_SMEM>>>(
        a2h, a2l, b2h, b2l, b_ih, b_hh, gx, FEAT, FEAT);

    lstm_kernel<<<BB, 512, LSTM_SMEM_BYTES>>>(gx, w_hh, done, h0, c0, hidp);

    heads_kernel<<<TB / 16, 304>>>(hidp, wa, ba, wc, bc, out);
}

// round 16
// speedup vs baseline: 1.7147x; 1.0067x over previous
#include <cuda_runtime.h>
#include <cuda_bf16.h>
#include <math.h>
#include <stdint.h>

// ---------------- problem constants ----------------
#define TT   128
#define BB   32
#define TB   (TT*BB)          // 4096
#define HID  128
#define FEAT 512
#define AA   18
#define OUTC (AA+1)           // 19

typedef unsigned long long u64;

// ---------------- HMMA helpers (base ISA: mma.sync + ldmatrix) ----------------
__device__ __forceinline__ uint32_t smem_u32(const void* p) {
    uint32_t a;
    asm("{ .reg .u64 t; cvta.to.shared.u64 t, %1; cvt.u32.u64 %0, t; }" : "=r"(a) : "l"(p));
    return a;
}
__device__ __forceinline__ void ldsm_x4(uint32_t* r, uint32_t addr) {
    asm volatile("ldmatrix.sync.aligned.m8n8.x4.shared.b16 {%0,%1,%2,%3}, [%4];"
        : "=r"(r[0]), "=r"(r[1]), "=r"(r[2]), "=r"(r[3]) : "r"(addr));
}
__device__ __forceinline__ void mma_bf16(float* d, const uint32_t* a, const uint32_t* b) {
    asm volatile("mma.sync.aligned.m16n8k16.row.col.f32.bf16.bf16.f32 "
        "{%0,%1,%2,%3}, {%4,%5,%6,%7}, {%8,%9}, {%0,%1,%2,%3};"
        : "+f"(d[0]), "+f"(d[1]), "+f"(d[2]), "+f"(d[3])
        : "r"(a[0]), "r"(a[1]), "r"(a[2]), "r"(a[3]), "r"(b[0]), "r"(b[1]));
}
__device__ __forceinline__ uint32_t bf2(float a, float b) {
    __nv_bfloat162 t = __floats2bfloat162_rn(a, b);
    return *(uint32_t*)&t;
}
__device__ __forceinline__ void hl_split(float v, __nv_bfloat16& h, __nv_bfloat16& l) {
    h = __float2bfloat16(v);
    l = __float2bfloat16(v - __bfloat162float(h));
}

// ---------------- scratch (static device allocations) ----------------
__device__ float g_feat[TB * FEAT];
__device__ float g_gx[TB * 4 * HID];
__device__ float g_hid[TB * HID];
// activations as bf16 hi/lo planes (numerically identical to fp32->split)
__device__ __nv_bfloat16 g_c1h[TB * 12800], g_c1l[TB * 12800];
__device__ __nv_bfloat16 g_c2h[TB * 5184],  g_c2l[TB * 5184];
// bf16 hi/lo split operands (plain row-major)
__device__ __nv_bfloat16 g_w1h[32 * 256],  g_w1l[32 * 256];       // conv1 w (x 1/255)
__device__ __nv_bfloat16 g_w2h[64 * 512],  g_w2l[64 * 512];
__device__ __nv_bfloat16 g_w3h[64 * 576],  g_w3l[64 * 576];
__device__ __nv_bfloat16 g_a1h[TB * 3136], g_a1l[TB * 3136];      // c3 (written by conv3)
__device__ __nv_bfloat16 g_b1h[FEAT * 3136], g_b1l[FEAT * 3136];  // wf
__device__ __nv_bfloat16 g_a2h[TB * FEAT], g_a2l[TB * FEAT];      // feat
__device__ __nv_bfloat16 g_b2h[FEAT * FEAT], g_b2l[FEAT * FEAT];  // w_ih

// ============================================================
// hi/lo bf16 convert, plain row-major, optional scale
// ============================================================
__global__ void convert_hl_kernel(const float* __restrict__ src,
                                  __nv_bfloat16* __restrict__ hi,
                                  __nv_bfloat16* __restrict__ lo,
                                  int total, float scale)
{
    for (int i = blockIdx.x * 256 + threadIdx.x; i < total; i += gridDim.x * 256) {
        float v = src[i] * scale;
        __nv_bfloat16 h, l;
        hl_split(v, h, l);
        hi[i] = h; lo[i] = l;
    }
}

// ============================================================
// HMMA bf16-split GEMM [R10, verified]: C = A@B^T + bias (+bias2)
// ============================================================
#define PAD 72
#define SM_GA   256
#define SM_GAL  (SM_GA  + 128 * PAD * 2)
#define SM_GBH  (SM_GAL + 128 * PAD * 2)
#define SM_GBL  (SM_GBH + 64 * PAD * 2)
#define MM_SMEM (SM_GBL + 64 * PAD * 2)

template <bool RELU, bool BIAS2>
__global__ void __launch_bounds__(256, 2)
mma_gemm_kernel(const __nv_bfloat16* __restrict__ Ah, const __nv_bfloat16* __restrict__ Al,
                const __nv_bfloat16* __restrict__ Bh, const __nv_bfloat16* __restrict__ Bl,
                const float* __restrict__ bias1, const float* __restrict__ bias2,
                float* __restrict__ C, int K, int Ntot)
{
    extern __shared__ char smc[];
    float* sbias = (float*)smc;
    const uint32_t sb = smem_u32(smc);
    const uint32_t sAh = sb + SM_GA,  sAl = sb + SM_GAL;
    const uint32_t sBh = sb + SM_GBH, sBl = sb + SM_GBL;

    const int tid = threadIdx.x, wid = tid >> 5, lid = tid & 31;
    const int bm = blockIdx.y * 128, bn = blockIdx.x * 64;
    const int wm = wid >> 2, wn = wid & 3;

    if (tid < 64) {
        float bv = bias1[bn + tid];
        if (BIAS2) bv += bias2[bn + tid];
        sbias[tid] = bv;
    }

    const int arow = lid & 15;
    const int acol = (lid & 16) ? 8 : 0;
    const int brow = (lid & 7) | ((lid & 16) >> 1);
    const int bcol = (lid & 8) ? 8 : 0;

    float acc[4][2][4];
#pragma unroll
    for (int mi = 0; mi < 4; ++mi)
#pragma unroll
        for (int ni = 0; ni < 2; ++ni)
#pragma unroll
            for (int q = 0; q < 4; ++q) acc[mi][ni][q] = 0.0f;

    for (int kb = 0; kb < K; kb += 64) {
        {
            char* base = smc;
#pragma unroll
            for (int h = 0; h < 4; ++h) {
                int i = tid + h * 256;
                int row = i >> 3, c = i & 7;
                *(float4*)(base + SM_GA + row * (PAD * 2) + c * 16) =
                    *(const float4*)(Ah + (size_t)(bm + row) * K + kb + c * 8);
            }
#pragma unroll
            for (int h = 0; h < 4; ++h) {
                int i = tid + h * 256;
                int row = i >> 3, c = i & 7;
                *(float4*)(base + SM_GAL + row * (PAD * 2) + c * 16) =
                    *(const float4*)(Al + (size_t)(bm + row) * K + kb + c * 8);
            }
#pragma unroll
            for (int h = 0; h < 2; ++h) {
                int i = tid + h * 256;
                int row = i >> 3, c = i & 7;
                *(float4*)(base + SM_GBH + row * (PAD * 2) + c * 16) =
                    *(const float4*)(Bh + (size_t)(bn + row) * K + kb + c * 8);
            }
#pragma unroll
            for (int h = 0; h < 2; ++h) {
                int i = tid + h * 256;
                int row = i >> 3, c = i & 7;
                *(float4*)(base + SM_GBL + row * (PAD * 2) + c * 16) =
                    *(const float4*)(Bl + (size_t)(bn + row) * K + kb + c * 8);
            }
        }
        __syncthreads();

#pragma unroll
        for (int ks = 0; ks < 4; ++ks) {
            const int k0 = ks * 16;
            uint32_t ah[4][4], al[4][4], bh[4], bl[4];
#pragma unroll
            for (int mi = 0; mi < 4; ++mi) {
                uint32_t ra = (uint32_t)((wm * 64 + mi * 16 + arow) * PAD + k0 + acol) * 2;
                ldsm_x4(ah[mi], sAh + ra);
                ldsm_x4(al[mi], sAl + ra);
            }
            {
                uint32_t rb = (uint32_t)((wn * 16 + brow) * PAD + k0 + bcol) * 2;
                ldsm_x4(bh, sBh + rb);
                ldsm_x4(bl, sBl + rb);
            }
#pragma unroll
            for (int mi = 0; mi < 4; ++mi)
#pragma unroll
                for (int ni = 0; ni < 2; ++ni) {
                    mma_bf16(acc[mi][ni], ah[mi], &bh[ni * 2]);
                    mma_bf16(acc[mi][ni], ah[mi], &bl[ni * 2]);
                    mma_bf16(acc[mi][ni], al[mi], &bh[ni * 2]);
                }
        }
        __syncthreads();
    }

    const int r = lid >> 2, c2 = (lid & 3) * 2;
#pragma unroll
    for (int mi = 0; mi < 4; ++mi)
#pragma unroll
        for (int ni = 0; ni < 2; ++ni) {
            int nloc = wn * 16 + ni * 8 + c2;
            float b0 = sbias[nloc], b1 = sbias[nloc + 1];
            int m0 = bm + wm * 64 + mi * 16 + r;
            float v0 = acc[mi][ni][0] + b0, v1 = acc[mi][ni][1] + b1;
            float v2 = acc[mi][ni][2] + b0, v3 = acc[mi][ni][3] + b1;
            if (RELU) {
                v0 = fmaxf(v0, 0.0f); v1 = fmaxf(v1, 0.0f);
                v2 = fmaxf(v2, 0.0f); v3 = fmaxf(v3, 0.0f);
            }
            *(float2*)(C + (size_t)m0 * Ntot + bn + nloc)       = make_float2(v0, v1);
            *(float2*)(C + (size_t)(m0 + 8) * Ntot + bn + nloc) = make_float2(v2, v3);
        }
}

// ============================================================
// conv1 via HMMA implicit GEMM (vectorized im2col, dead-warp trimmed).
// One CTA per HALF image. M=200(pad224 live) x N=32 x K=256.
// Outputs bf16 hi/lo planes (identical numerics to fp32 + later split).
// ============================================================
#define PAD1 40
#define C1_SBIAS 0
#define C1_IMGH  128
#define C1_IMGL  (C1_IMGH + 29568)
#define C1_AH    (C1_IMGL + 29568)          // 256*40 shorts
#define C1_AL    (C1_AH + 20480)
#define C1_BH    (C1_AL + 20480)
#define C1_BL    (C1_BH + 2560)
#define C1_SMEM  (C1_BL + 2560)             // 105344

__global__ void __launch_bounds__(256, 2)
conv1_mma_kernel(const float* __restrict__ x, const __nv_bfloat16* __restrict__ wh,
                 const __nv_bfloat16* __restrict__ wl, const float* __restrict__ b,
                 __nv_bfloat16* __restrict__ outh, __nv_bfloat16* __restrict__ outl)
{
    extern __shared__ char smc[];
    float* sbias = (float*)(smc + C1_SBIAS);
    unsigned short* imgh = (unsigned short*)(smc + C1_IMGH);
    unsigned short* imgl = (unsigned short*)(smc + C1_IMGL);
    unsigned short* Ahs  = (unsigned short*)(smc + C1_AH);
    unsigned short* Als  = (unsigned short*)(smc + C1_AL);
    const uint32_t sb = smem_u32(smc);
    const uint32_t sAh = sb + C1_AH, sAl = sb + C1_AL;
    const uint32_t sBh = sb + C1_BH, sBl = sb + C1_BL;

    const int tid = threadIdx.x, wid = tid >> 5, lid = tid & 31;
    const int n = blockIdx.x >> 1, half = blockIdx.x & 1;
    const int r0 = half * 40;
    const int wm = wid;

    if (tid < 32) sbias[tid] = b[tid];

    const float4* xg4 = (const float4*)(x + (size_t)n * 28224);
    for (int i = tid; i < 3696; i += 256) {
        int ch = i / 924, rr = i - ch * 924;
        float4 v = xg4[ch * 1764 + r0 * 21 + rr];
        float hx = __bfloat162float(__float2bfloat16(v.x));
        float hy = __bfloat162float(__float2bfloat16(v.y));
        float hz = __bfloat162float(__float2bfloat16(v.z));
        float hw = __bfloat162float(__float2bfloat16(v.w));
        ((uint2*)imgh)[i] = make_uint2(bf2(v.x, v.y), bf2(v.z, v.w));
        ((uint2*)imgl)[i] = make_uint2(bf2(v.x - hx, v.y - hy), bf2(v.z - hz, v.w - hw));
    }
    __syncthreads();

    const int arow = lid & 15;
    const int acol = (lid & 16) ? 8 : 0;
    const int brow = (lid & 7) | ((lid & 16) >> 1);
    const int bcol = (lid & 8) ? 8 : 0;

    float acc[2][4][4];
#pragma unroll
    for (int mi = 0; mi < 2; ++mi)
#pragma unroll
        for (int ni = 0; ni < 4; ++ni)
#pragma unroll
            for (int q = 0; q < 4; ++q) acc[mi][ni][q] = 0.0f;

    for (int kc = 0; kc < 8; ++kc) {
        const int icc = kc >> 1;
        const int kyb = (kc & 1) * 4;
        // im2col: rows [0,224) only (rows 224-255 belong to dead warp 7)
#pragma unroll
        for (int h = 0; h < 7; ++h) {
            int idx = tid + h * 256;
            int p = idx >> 3, g = idx & 7;
            int ky = kyb + (g >> 1), kx0 = (g & 1) * 4;
            uint2 vh = make_uint2(0u, 0u), vl = make_uint2(0u, 0u);
            if (p < 200) {
                int oy = p / 20, ox = p - oy * 20;
                int s = icc * 3696 + (oy * 4 + ky) * 84 + ox * 4 + kx0;
                vh = *(const uint2*)(imgh + s);
                vl = *(const uint2*)(imgl + s);
            }
            *(uint2*)(Ahs + p * PAD1 + g * 4) = vh;
            *(uint2*)(Als + p * PAD1 + g * 4) = vl;
        }
        {
            int i = tid & 127;
            int row = i >> 2, c = i & 3;
            const __nv_bfloat16* wsrc = (tid < 128) ? wh : wl;
            char* wdst = smc + ((tid < 128) ? C1_BH : C1_BL);
            *(float4*)(wdst + (row * PAD1 + c * 8) * 2) =
                *(const float4*)(wsrc + (size_t)row * 256 + kc * 32 + c * 8);
        }
        __syncthreads();

        if (wm < 7) {     // warp 7 covers rows 224-255: all dead
#pragma unroll
            for (int ks = 0; ks < 2; ++ks) {
                const int k0 = ks * 16;
                uint32_t ah[2][4], al[2][4], bh[2][4], bl[2][4];
#pragma unroll
                for (int mi = 0; mi < 2; ++mi) {
                    uint32_t ra = (uint32_t)((wm * 32 + mi * 16 + arow) * PAD1 + k0 + acol) * 2;
                    ldsm_x4(ah[mi], sAh + ra);
                    ldsm_x4(al[mi], sAl + ra);
                }
#pragma unroll
                for (int g = 0; g < 2; ++g) {
                    uint32_t rb = (uint32_t)((g * 16 + brow) * PAD1 + k0 + bcol) * 2;
                    ldsm_x4(bh[g], sBh + rb);
                    ldsm_x4(bl[g], sBl + rb);
                }
#pragma unroll
                for (int mi = 0; mi < 2; ++mi)
#pragma unroll
                    for (int ni = 0; ni < 4; ++ni) {
                        int g = ni >> 1, j = (ni & 1) * 2;
                        mma_bf16(acc[mi][ni], ah[mi], &bh[g][j]);
                        mma_bf16(acc[mi][ni], ah[mi], &bl[g][j]);
                        mma_bf16(acc[mi][ni], al[mi], &bh[g][j]);
                    }
            }
        }
        __syncthreads();
    }

    if (wm < 7) {
        const int r = lid >> 2, c2 = (lid & 3) * 2;
        size_t obase = (size_t)n * 12800 + half * 200;
#pragma unroll
        for (int mi = 0; mi < 2; ++mi)
#pragma unroll
            for (int ni = 0; ni < 4; ++ni) {
                int oc = ni * 8 + c2;
                float b0 = sbias[oc], b1 = sbias[oc + 1];
                int p0 = wm * 32 + mi * 16 + r;
#pragma unroll
                for (int hh = 0; hh < 2; ++hh) {
                    int p = p0 + hh * 8;
                    if (p < 200) {
                        float v0 = fmaxf(acc[mi][ni][hh * 2 + 0] + b0, 0.0f);
                        float v1 = fmaxf(acc[mi][ni][hh * 2 + 1] + b1, 0.0f);
                        __nv_bfloat16 h0, l0, h1, l1;
                        hl_split(v0, h0, l0);
                        hl_split(v1, h1, l1);
                        outh[obase + (size_t)oc * 400 + p]       = h0;
                        outl[obase + (size_t)oc * 400 + p]       = l0;
                        outh[obase + (size_t)(oc + 1) * 400 + p] = h1;
                        outl[obase + (size_t)(oc + 1) * 400 + p] = l1;
                    }
                }
            }
    }
}

// ============================================================
// conv2: input already bf16 hi/lo planes -> pure uint4 copies.
// Outputs bf16 hi/lo planes.
// ============================================================
#define C2_SBIAS 0
#define C2_IMGH  256
#define C2_IMGL  (C2_IMGH + 25600)
#define C2_AH    (C2_IMGL + 25600)
#define C2_AL    (C2_AH + 13824)
#define C2_BH    (C2_AL + 13824)
#define C2_BL    (C2_BH + 9216)
#define C2_SMEM  (C2_BL + 9216)

__global__ void __launch_bounds__(256, 2)
conv2_mma_kernel(const __nv_bfloat16* __restrict__ inh, const __nv_bfloat16* __restrict__ inl,
                 const __nv_bfloat16* __restrict__ wh,  const __nv_bfloat16* __restrict__ wl,
                 const float* __restrict__ b,
                 __nv_bfloat16* __restrict__ outh, __nv_bfloat16* __restrict__ outl)
{
    extern __shared__ char smc[];
    float* sbias = (float*)(smc + C2_SBIAS);
    unsigned short* imgh = (unsigned short*)(smc + C2_IMGH);
    unsigned short* imgl = (unsigned short*)(smc + C2_IMGL);
    unsigned short* Ahs  = (unsigned short*)(smc + C2_AH);
    unsigned short* Als  = (unsigned short*)(smc + C2_AL);
    const uint32_t sb = smem_u32(smc);
    const uint32_t sAh = sb + C2_AH, sAl = sb + C2_AL;
    const uint32_t sBh = sb + C2_BH, sBl = sb + C2_BL;

    const int tid = threadIdx.x, wid = tid >> 5, lid = tid & 31;
    const int n = blockIdx.x;
    const int wm = wid >> 2, wn = wid & 3;

    if (tid < 64) sbias[tid] = b[tid];

    const uint4* ih4 = (const uint4*)(inh + (size_t)n * 12800);
    const uint4* il4 = (const uint4*)(inl + (size_t)n * 12800);
    for (int i = tid; i < 1600; i += 256) {
        ((uint4*)imgh)[i] = ih4[i];
        ((uint4*)imgl)[i] = il4[i];
    }
    __syncthreads();

    const int arow = lid & 15;
    const int acol = (lid & 16) ? 8 : 0;
    const int brow = (lid & 7) | ((lid & 16) >> 1);
    const int bcol = (lid & 8) ? 8 : 0;

    float acc[3][2][4];
#pragma unroll
    for (int mi = 0; mi < 3; ++mi)
#pragma unroll
        for (int ni = 0; ni < 2; ++ni)
#pragma unroll
            for (int q = 0; q < 4; ++q) acc[mi][ni][q] = 0.0f;

    for (int kc = 0; kc < 8; ++kc) {
#pragma unroll
        for (int h = 0; h < 12; ++h) {
            int idx = tid + h * 256;
            int p = idx >> 5, g = idx & 31;
            int k0 = kc * 64 + g * 2;
            int ic = k0 >> 4, rr = k0 & 15, ky = rr >> 2, kx0 = rr & 3;
            unsigned int vh = 0u, vl = 0u;
            if (p < 81) {
                int oy = p / 9, ox = p - oy * 9;
                int s = ic * 400 + (oy * 2 + ky) * 20 + ox * 2 + kx0;
                vh = *(const unsigned int*)(imgh + s);
                vl = *(const unsigned int*)(imgl + s);
            }
            *(unsigned int*)(Ahs + p * PAD + g * 2) = vh;
            *(unsigned int*)(Als + p * PAD + g * 2) = vl;
        }
#pragma unroll
        for (int h = 0; h < 2; ++h) {
            int i = tid + h * 256;
            int row = i >> 3, c = i & 7;
            *(float4*)(smc + C2_BH + (row * PAD + c * 8) * 2) =
                *(const float4*)(wh + (size_t)row * 512 + kc * 64 + c * 8);
            *(float4*)(smc + C2_BL + (row * PAD + c * 8) * 2) =
                *(const float4*)(wl + (size_t)row * 512 + kc * 64 + c * 8);
        }
        __syncthreads();

#pragma unroll
        for (int ks = 0; ks < 4; ++ks) {
            const int k0 = ks * 16;
            uint32_t ah[3][4], al[3][4], bh[4], bl[4];
#pragma unroll
            for (int mi = 0; mi < 3; ++mi) {
                uint32_t ra = (uint32_t)((wm * 48 + mi * 16 + arow) * PAD + k0 + acol) * 2;
                ldsm_x4(ah[mi], sAh + ra);
                ldsm_x4(al[mi], sAl + ra);
            }
            {
                uint32_t rb = (uint32_t)((wn * 16 + brow) * PAD + k0 + bcol) * 2;
                ldsm_x4(bh, sBh + rb);
                ldsm_x4(bl, sBl + rb);
            }
#pragma unroll
            for (int mi = 0; mi < 3; ++mi)
#pragma unroll
                for (int ni = 0; ni < 2; ++ni) {
                    mma_bf16(acc[mi][ni], ah[mi], &bh[ni * 2]);
                    mma_bf16(acc[mi][ni], ah[mi], &bl[ni * 2]);
                    mma_bf16(acc[mi][ni], al[mi], &bh[ni * 2]);
                }
        }
        __syncthreads();
    }

    const int r = lid >> 2, c2 = (lid & 3) * 2;
    size_t obase = (size_t)n * 5184;
#pragma unroll
    for (int mi = 0; mi < 3; ++mi)
#pragma unroll
        for (int ni = 0; ni < 2; ++ni) {
            int oc = wn * 16 + ni * 8 + c2;
            float b0 = sbias[oc], b1 = sbias[oc + 1];
            int p0 = wm * 48 + mi * 16 + r;
#pragma unroll
            for (int hh = 0; hh < 2; ++hh) {
                int p = p0 + hh * 8;
                if (p < 81) {
                    float v0 = fmaxf(acc[mi][ni][hh * 2 + 0] + b0, 0.0f);
                    float v1 = fmaxf(acc[mi][ni][hh * 2 + 1] + b1, 0.0f);
                    __nv_bfloat16 h0, l0, h1, l1;
                    hl_split(v0, h0, l0);
                    hl_split(v1, h1, l1);
                    outh[obase + (size_t)oc * 81 + p]       = h0;
                    outl[obase + (size_t)oc * 81 + p]       = l0;
                    outh[obase + (size_t)(oc + 1) * 81 + p] = h1;
                    outl[obase + (size_t)(oc + 1) * 81 + p] = l1;
                }
            }
        }
}

// ============================================================
// conv3: bf16 hi/lo input; writes FC A-operand (a1h/a1l) directly.
// ============================================================
#define C3_SBIAS 0
#define C3_IMGH  256
#define C3_IMGL  (C3_IMGH + 10368)
#define C3_AH    (C3_IMGL + 10368)
#define C3_AL    (C3_AH + 9216)
#define C3_BH    (C3_AL + 9216)
#define C3_BL    (C3_BH + 9216)
#define C3_SMEM  (C3_BL + 9216)

__global__ void __launch_bounds__(256, 3)
conv3_mma_kernel(const __nv_bfloat16* __restrict__ inh, const __nv_bfloat16* __restrict__ inl,
                 const __nv_bfloat16* __restrict__ wh,  const __nv_bfloat16* __restrict__ wl,
                 const float* __restrict__ b,
                 __nv_bfloat16* __restrict__ outh, __nv_bfloat16* __restrict__ outl)
{
    extern __shared__ char smc[];
    float* sbias = (float*)(smc + C3_SBIAS);
    unsigned short* imgh = (unsigned short*)(smc + C3_IMGH);
    unsigned short* imgl = (unsigned short*)(smc + C3_IMGL);
    unsigned short* Ahs  = (unsigned short*)(smc + C3_AH);
    unsigned short* Als  = (unsigned short*)(smc + C3_AL);
    const uint32_t sb = smem_u32(smc);
    const uint32_t sAh = sb + C3_AH, sAl = sb + C3_AL;
    const uint32_t sBh = sb + C3_BH, sBl = sb + C3_BL;

    const int tid = threadIdx.x, wid = tid >> 5, lid = tid & 31;
    const int n = blockIdx.x;
    const int wm = wid >> 2, wn = wid & 3;

    if (tid < 64) sbias[tid] = b[tid];

    const uint4* ih4 = (const uint4*)(inh + (size_t)n * 5184);
    const uint4* il4 = (const uint4*)(inl + (size_t)n * 5184);
    for (int i = tid; i < 648; i += 256) {
        ((uint4*)imgh)[i] = ih4[i];
        ((uint4*)imgl)[i] = il4[i];
    }
    __syncthreads();

    const int arow = lid & 15;
    const int acol = (lid & 16) ? 8 : 0;
    const int brow = (lid & 7) | ((lid & 16) >> 1);
    const int bcol = (lid & 8) ? 8 : 0;

    float acc[2][2][4];
#pragma unroll
    for (int mi = 0; mi < 2; ++mi)
#pragma unroll
        for (int ni = 0; ni < 2; ++ni)
#pragma unroll
            for (int q = 0; q < 4; ++q) acc[mi][ni][q] = 0.0f;

    for (int kc = 0; kc < 9; ++kc) {
#pragma unroll
        for (int h = 0; h < 16; ++h) {
            int idx = tid + h * 256;
            int p = idx >> 6, kk = idx & 63;
            int k = kc * 64 + kk;
            int ic = k / 9, r = k - ic * 9;
            int ky = r / 3, kx = r - ky * 3;
            unsigned short vh = 0, vl = 0;
            if (p < 49) {
                int oy = p / 7, ox = p - oy * 7;
                int s = ic * 81 + (oy + ky) * 9 + ox + kx;
                vh = imgh[s]; vl = imgl[s];
            }
            Ahs[p * PAD + kk] = vh;
            Als[p * PAD + kk] = vl;
        }
#pragma unroll
        for (int h = 0; h < 2; ++h) {
            int i = tid + h * 256;
            int row = i >> 3, c = i & 7;
            *(float4*)(smc + C3_BH + (row * PAD + c * 8) * 2) =
                *(const float4*)(wh + (size_t)row * 576 + kc * 64 + c * 8);
            *(float4*)(smc + C3_BL + (row * PAD + c * 8) * 2) =
                *(const float4*)(wl + (size_t)row * 576 + kc * 64 + c * 8);
        }
        __syncthreads();

#pragma unroll
        for (int ks = 0; ks < 4; ++ks) {
            const int k0 = ks * 16;
            uint32_t ah[2][4], al[2][4], bh[4], bl[4];
#pragma unroll
            for (int mi = 0; mi < 2; ++mi) {
                uint32_t ra = (uint32_t)((wm * 32 + mi * 16 + arow) * PAD + k0 + acol) * 2;
                ldsm_x4(ah[mi], sAh + ra);
                ldsm_x4(al[mi], sAl + ra);
            }
            {
                uint32_t rb = (uint32_t)((wn * 16 + brow) * PAD + k0 + bcol) * 2;
                ldsm_x4(bh, sBh + rb);
                ldsm_x4(bl, sBl + rb);
            }
#pragma unroll
            for (int mi = 0; mi < 2; ++mi)
#pragma unroll
                for (int ni = 0; ni < 2; ++ni) {
                    mma_bf16(acc[mi][ni], ah[mi], &bh[ni * 2]);
                    mma_bf16(acc[mi][ni], ah[mi], &bl[ni * 2]);
                    mma_bf16(acc[mi][ni], al[mi], &bh[ni * 2]);
                }
        }
        __syncthreads();
    }

    // epilogue: write FC A operand rows (n, k = oc*49 + p), hi/lo split
    const int r = lid >> 2, c2 = (lid & 3) * 2;
    size_t obase = (size_t)n * 3136;
#pragma unroll
    for (int mi = 0; mi < 2; ++mi)
#pragma unroll
        for (int ni = 0; ni < 2; ++ni) {
            int oc = wn * 16 + ni * 8 + c2;
            float b0 = sbias[oc], b1 = sbias[oc + 1];
            int p0 = wm * 32 + mi * 16 + r;
#pragma unroll
            for (int hh = 0; hh < 2; ++hh) {
                int p = p0 + hh * 8;
                if (p < 49) {
                    float v0 = fmaxf(acc[mi][ni][hh * 2 + 0] + b0, 0.0f);
                    float v1 = fmaxf(acc[mi][ni][hh * 2 + 1] + b1, 0.0f);
                    __nv_bfloat16 h0, l0, h1, l1;
                    hl_split(v0, h0, l0);
                    hl_split(v1, h1, l1);
                    outh[obase + (size_t)oc * 49 + p]       = h0;
                    outl[obase + (size_t)oc * 49 + p]       = l0;
                    outh[obase + (size_t)(oc + 1) * 49 + p] = h1;
                    outl[obase + (size_t)(oc + 1) * 49 + p] = l1;
                }
            }
        }
}

// ============================================================
// LSTM recurrence [verified] + gx prefetch (hides the 577cyc LDG)
// ============================================================
#define LSTM_SMEM_BYTES (16 * 512 * 16 + 128 * 4 + 512 * 4)

__global__ void __launch_bounds__(512, 1)
lstm_kernel(const float* __restrict__ gx, const float* __restrict__ whh,
            const int* __restrict__ done, const float* __restrict__ h0,
            const float* __restrict__ c0, float* __restrict__ hid)
{
    extern __shared__ float sm[];
    float4* wp4  = (float4*)sm;
    float*  h_sh = sm + 16 * 512 * 4;
    float*  act  = h_sh + 128;

    const int env = blockIdx.x;
    const int j = threadIdx.x;

    const float* wrow = whh + (size_t)j * 128;
    float wreg[64];
#pragma unroll
    for (int k = 0; k < 64; k += 4) {
        float4 v = *(const float4*)(wrow + k);
        wreg[k] = v.x; wreg[k + 1] = v.y; wreg[k + 2] = v.z; wreg[k + 3] = v.w;
    }
#pragma unroll
    for (int kk = 0; kk < 16; ++kk)
        wp4[kk * 512 + j] = *(const float4*)(wrow + 64 + kk * 4);

    float c = 0.0f, hprev = 0.0f;
    if (j < 128) {
        hprev = h0[env * 128 + j];
        c     = c0[env * 128 + j];
    }
    float gnext = gx[(size_t)env * 512 + j];      // t = 0
    __syncthreads();

    for (int t = 0; t < TT; ++t) {
        if (j < 128) {
            float m = 1.0f - (float)done[t * BB + env];
            h_sh[j] = hprev * m;
            c *= m;
        }
        __syncthreads();

        float accv = gnext;
        if (t + 1 < TT)                            // prefetch next step's gx
            gnext = gx[((size_t)(t + 1) * BB + env) * 512 + j];

#pragma unroll
        for (int k = 0; k < 64; k += 4) {
            float4 hv = *(const float4*)&h_sh[k];
            accv += hv.x * wreg[k] + hv.y * wreg[k + 1]
                  + hv.z * wreg[k + 2] + hv.w * wreg[k + 3];
        }
#pragma unroll
        for (int kk = 0; kk < 16; ++kk) {
            float4 wv = wp4[kk * 512 + j];
            float4 hv = *(const float4*)&h_sh[64 + kk * 4];
            accv += wv.x * hv.x + wv.y * hv.y + wv.z * hv.z + wv.w * hv.w;
        }

        float a;
        if (j < 256 || j >= 384) a = 1.0f / (1.0f + expf(-accv));
        else                     a = tanhf(accv);
        act[j] = a;
        __syncthreads();

        if (j < 128) {
            float ig = act[j],       fg = act[128 + j];
            float gg = act[256 + j], og = act[384 + j];
            c = fg * c + ig * gg;
            hprev = og * tanhf(c);
            hid[((size_t)t * BB + env) * 128 + j] = hprev;
        }
    }
}

// ============================================================
// heads [verified]
// ============================================================
__global__ void __launch_bounds__(304, 4)
heads_kernel(const float* __restrict__ hid, const float* __restrict__ wa,
             const float* __restrict__ ba, const float* __restrict__ wc,
             const float* __restrict__ bc, float* __restrict__ out)
{
    __shared__ float wsh[19 * 128];
    __shared__ float hsh[16 * 128];
    __shared__ float bsh[19];

    const int t = threadIdx.x;
    const int rb = blockIdx.x * 16;

    for (int i = t; i < 18 * 128; i += 304) wsh[i] = wa[i];
    for (int i = t; i < 128; i += 304)      wsh[18 * 128 + i] = wc[i];
    for (int i = t; i < 2048; i += 304)     hsh[i] = hid[(size_t)rb * 128 + i];
    if (t < 18) bsh[t] = ba[t];
    if (t == 18) bsh[18] = bc[0];
    __syncthreads();

    const int r = t / 19, cidx = t % 19;
    float accv = bsh[cidx];
    const float* hr = &hsh[r * 128];
    const float* wr = &wsh[cidx * 128];
#pragma unroll
    for (int k = 0; k < 128; k += 4) {
        float4 hv = *(const float4*)(hr + k);
        float4 wv = *(const float4*)(wr + k);
        accv += hv.x * wv.x + hv.y * wv.y + hv.z * wv.z + hv.w * wv.w;
    }
    out[(size_t)(rb + r) * OUTC + cidx] = accv;
}

// ============================================================
// host launcher
// ============================================================
extern "C" void kernel_launch(void* const* d_in, const int* in_sizes, int n_in,
                              void* d_out, int out_size)
{
    const float* x    = (const float*)d_in[0];
    const int*   done = (const int*)  d_in[1];
    const float* h0   = (const float*)d_in[2];
    const float* c0   = (const float*)d_in[3];
    const float* w1   = (const float*)d_in[4];
    const float* b1   = (const float*)d_in[5];
    const float* w2   = (const float*)d_in[6];
    const float* b2   = (const float*)d_in[7];
    const float* w3   = (const float*)d_in[8];
    const float* b3   = (const float*)d_in[9];
    const float* wf   = (const float*)d_in[10];
    const float* bf   = (const float*)d_in[11];
    const float* w_ih = (const float*)d_in[12];
    const float* w_hh = (const float*)d_in[13];
    const float* b_ih = (const float*)d_in[14];
    const float* b_hh = (const float*)d_in[15];
    const float* wa   = (const float*)d_in[16];
    const float* ba   = (const float*)d_in[17];
    const float* wc   = (const float*)d_in[18];
    const float* bc   = (const float*)d_in[19];
    float* out = (float*)d_out;

    float *feat, *gx, *hidp;
    cudaGetSymbolAddress((void**)&feat, g_feat);
    cudaGetSymbolAddress((void**)&gx,   g_gx);
    cudaGetSymbolAddress((void**)&hidp, g_hid);
    __nv_bfloat16 *c1h, *c1l, *c2h, *c2l;
    __nv_bfloat16 *w1h, *w1l, *w2h, *w2l, *w3h, *w3l;
    __nv_bfloat16 *a1h, *a1l, *b1h, *b1l, *a2h, *a2l, *b2h, *b2l;
    cudaGetSymbolAddress((void**)&c1h, g_c1h);
    cudaGetSymbolAddress((void**)&c1l, g_c1l);
    cudaGetSymbolAddress((void**)&c2h, g_c2h);
    cudaGetSymbolAddress((void**)&c2l, g_c2l);
    cudaGetSymbolAddress((void**)&w1h, g_w1h);
    cudaGetSymbolAddress((void**)&w1l, g_w1l);
    cudaGetSymbolAddress((void**)&w2h, g_w2h);
    cudaGetSymbolAddress((void**)&w2l, g_w2l);
    cudaGetSymbolAddress((void**)&w3h, g_w3h);
    cudaGetSymbolAddress((void**)&w3l, g_w3l);
    cudaGetSymbolAddress((void**)&a1h, g_a1h);
    cudaGetSymbolAddress((void**)&a1l, g_a1l);
    cudaGetSymbolAddress((void**)&b1h, g_b1h);
    cudaGetSymbolAddress((void**)&b1l, g_b1l);
    cudaGetSymbolAddress((void**)&a2h, g_a2h);
    cudaGetSymbolAddress((void**)&a2l, g_a2l);
    cudaGetSymbolAddress((void**)&b2h, g_b2h);
    cudaGetSymbolAddress((void**)&b2l, g_b2l);

    cudaFuncSetAttribute(conv1_mma_kernel, cudaFuncAttributeMaxDynamicSharedMemorySize, C1_SMEM);
    cudaFuncSetAttribute(conv2_mma_kernel, cudaFuncAttributeMaxDynamicSharedMemorySize, C2_SMEM);
    cudaFuncSetAttribute(conv3_mma_kernel, cudaFuncAttributeMaxDynamicSharedMemorySize, C3_SMEM);
    cudaFuncSetAttribute(lstm_kernel,  cudaFuncAttributeMaxDynamicSharedMemorySize, LSTM_SMEM_BYTES);
    cudaFuncSetAttribute(mma_gemm_kernel<true,  false>, cudaFuncAttributeMaxDynamicSharedMemorySize, MM_SMEM);
    cudaFuncSetAttribute(mma_gemm_kernel<false, true>,  cudaFuncAttributeMaxDynamicSharedMemorySize, MM_SMEM);

    convert_hl_kernel<<<32,   256>>>(w1,   w1h, w1l, 32 * 256,  1.0f / 255.0f);
    convert_hl_kernel<<<128,  256>>>(w2,   w2h, w2l, 64 * 512,  1.0f);
    convert_hl_kernel<<<144,  256>>>(w3,   w3h, w3l, 64 * 576,  1.0f);
    convert_hl_kernel<<<2048, 256>>>(wf,   b1h, b1l, FEAT * 3136, 1.0f);
    convert_hl_kernel<<<512,  256>>>(w_ih, b2h, b2l, FEAT * FEAT, 1.0f);

    conv1_mma_kernel<<<TB * 2, 256, C1_SMEM>>>(x, w1h, w1l, b1, c1h, c1l);
    conv2_mma_kernel<<<TB, 256, C2_SMEM>>>(c1h, c1l, w2h, w2l, b2, c2h, c2l);
    conv3_mma_kernel<<<TB, 256, C3_SMEM>>>(c2h, c2l, w3h, w3l, b3, a1h, a1l);

    // feat = relu(c3 @ wf^T + bf)  via HMMA bf16-split (K=3136)
    mma_gemm_kernel<true, false><<<dim3(FEAT / 64, TB / 128), 256, MM_SMEM>>>(
        a1h, a1l, b1h, b1l, bf, nullptr, feat, 3136, FEAT);

    // gx = feat @ w_ih^T + b_ih + b_hh  via HMMA bf16-split (K=512)
    convert_hl_kernel<<<2048, 256>>>(feat, a2h, a2l, TB * FEAT, 1.0f);
    mma_gemm_kernel<false, true><<<dim3(FEAT / 64, TB / 128), 256, MM_SMEM>>>(
        a2h, a2l, b2h, b2l, b_ih, b_hh, gx, FEAT, FEAT);

    lstm_kernel<<<BB, 512, LSTM_SMEM_BYTES>>>(gx, w_hh, done, h0, c0, hidp);

    heads_kernel<<<TB / 16, 304>>>(hidp, wa, ba, wc, bc, out);
}